// round 10
// baseline (speedup 1.0000x reference)
#include <cuda_runtime.h>
#include <cuda_bf16.h>
#include <cstdint>

// Problem constants
#define L_   12
#define NH_  16
#define H_   1024
#define FF_  4096
#define V_   32000
#define S_   1024
#define E_   128
#define B_   4
#define HEAD_ 64
#define M4   (B_ * S_)   // 4096 rows total
#define QKVS 3072        // fused qkv row stride (floats)

// Arch-feature dispatch: tcgen05 only legal in the sm_103a pass.
#if defined(__CUDA_ARCH__) && defined(__CUDA_ARCH_FEAT_SM103_ALL)
#define TC_PATH 1
#else
#define TC_PATH 0
#endif

// ---------------------------------------------------------------------------
// Scratch (device globals — allocation-free per harness rules)
// ---------------------------------------------------------------------------
__device__ float g_xemb   [M4 * H_];
__device__ float g_layerin[M4 * H_];
__device__ float g_qkv    [M4 * QKVS];
__device__ float g_xmulti [M4 * H_];
__device__ float g_xself  [M4 * H_];
__device__ float g_ffw2   [M4 * H_];
__device__ float g_xffw   [M4 * H_];
__device__ float g_decout [M4 * H_];   // RNA-tf32-rounded fp32 (feeds logits GEMM)

// bf16 split-K3 operand buffers.  A' = [hi | lo | hi] (row-major, 3K cols),
// B' = [hi | hi | lo] as [N, 3K] (k-contiguous, i.e. transposed weight).
__device__ __align__(128) __nv_bfloat16 g_a3_emb [M4 * 3 * E_];
__device__ __align__(128) __nv_bfloat16 g_a3_li  [M4 * 3 * H_];
__device__ __align__(128) __nv_bfloat16 g_a3_conc[M4 * 3 * H_];
__device__ __align__(128) __nv_bfloat16 g_a3_self[M4 * 3 * H_];
__device__ __align__(128) __nv_bfloat16 g_a3_ffw1[(size_t)M4 * 3 * FF_];

__device__ __align__(128) __nv_bfloat16 g_w3_dec [H_ * 3 * E_];
__device__ __align__(128) __nv_bfloat16 g_w3_qkv [(size_t)QKVS * 3 * H_];
__device__ __align__(128) __nv_bfloat16 g_w3_c   [H_ * 3 * H_];
__device__ __align__(128) __nv_bfloat16 g_w3_ff1 [(size_t)FF_ * 3 * H_];
__device__ __align__(128) __nv_bfloat16 g_w3_ff2 [(size_t)H_ * 3 * FF_];
// p_decoder transposed, RNA-tf32-rounded fp32  [V, H]
__device__ __align__(128) float g_wtp [(size_t)V_ * H_];

// ---------------------------------------------------------------------------
// PTX helpers — baseline-legal
// ---------------------------------------------------------------------------
__device__ __forceinline__ uint32_t smem_u32(const void* p) {
    uint32_t a;
    asm("{ .reg .u64 t; cvta.to.shared.u64 t, %1; cvt.u32.u64 %0, t; }"
        : "=r"(a) : "l"(p));
    return a;
}
__device__ __forceinline__ void cp16(uint32_t dst, const void* src) {
    asm volatile("cp.async.cg.shared.global [%0], [%1], 16;"
                 :: "r"(dst), "l"(src) : "memory");
}
__device__ __forceinline__ void cp_commit() {
    asm volatile("cp.async.commit_group;" ::: "memory");
}
template <int N>
__device__ __forceinline__ void cp_wait() {
    asm volatile("cp.async.wait_group %0;" :: "n"(N) : "memory");
}
__device__ __forceinline__ uint32_t elect_one_pred() {
    uint32_t pred;
    asm volatile(
        "{\n\t.reg .pred p;\n\telect.sync _|p, 0xFFFFFFFF;\n\t"
        "selp.b32 %0, 1, 0, p;\n\t}" : "=r"(pred));
    return pred;
}
// legacy m16n8k16 bf16 MMA, fp32 accumulate (sm_80+)
__device__ __forceinline__ void mma16(float* d, const uint32_t* a, const uint32_t* b) {
    asm volatile(
        "mma.sync.aligned.m16n8k16.row.col.f32.bf16.bf16.f32 "
        "{%0,%1,%2,%3}, {%4,%5,%6,%7}, {%8,%9}, {%0,%1,%2,%3};"
        : "+f"(d[0]), "+f"(d[1]), "+f"(d[2]), "+f"(d[3])
        : "r"(a[0]), "r"(a[1]), "r"(a[2]), "r"(a[3]),
          "r"(b[0]), "r"(b[1]));
}
__device__ __forceinline__ uint32_t pack_bf16x2(float lo_elem, float hi_elem) {
    uint32_t r;
    asm("cvt.rn.bf16x2.f32 %0, %1, %2;" : "=r"(r) : "f"(hi_elem), "f"(lo_elem));
    return r;
}
__device__ __forceinline__ uint32_t pack_raw(__nv_bfloat16 lo, __nv_bfloat16 hi) {
    return (uint32_t)__bfloat16_as_ushort(lo) | ((uint32_t)__bfloat16_as_ushort(hi) << 16);
}
// RNA round fp32 -> tf32 (bit pattern stays a valid fp32)
__device__ __forceinline__ float rna_tf32(float v) {
    uint32_t r;
    asm("cvt.rna.tf32.f32 %0, %1;" : "=r"(r) : "f"(v));
    return __uint_as_float(r);
}

#define SMEM_SWIZZLE_128B(o) ((o) ^ (((o) >> 3) & 0x70))

#if TC_PATH
// ---- tcgen05 helpers (only compiled in the sm_103a pass) ----
#define TCGEN05_ALLOC(smem_addr, nCols) \
    asm volatile("tcgen05.alloc.cta_group::1.sync.aligned.shared::cta.b32 [%0], %1;" \
                 :: "r"((uint32_t)(smem_addr)), "r"((uint32_t)(nCols)) : "memory")
#define TCGEN05_DEALLOC(tmem_addr, nCols) \
    asm volatile("tcgen05.dealloc.cta_group::1.sync.aligned.b32 %0, %1;" \
                 :: "r"(tmem_addr), "r"((uint32_t)(nCols)))
#define TCGEN05_RELINQUISH() \
    asm volatile("tcgen05.relinquish_alloc_permit.cta_group::1.sync.aligned;")
#define TCGEN05_COMMIT(mbar) \
    asm volatile("tcgen05.commit.cta_group::1.mbarrier::arrive::one.shared::cluster.b64 [%0];" \
                 :: "r"((uint32_t)(mbar)) : "memory")
#define TCGEN05_FENCE_AFTER() \
    asm volatile("tcgen05.fence::after_thread_sync;" ::: "memory")
#define TCGEN05_FENCE_BEFORE() \
    asm volatile("tcgen05.fence::before_thread_sync;" ::: "memory")
#define TCGEN05_WAIT_LD() \
    asm volatile("tcgen05.wait::ld.sync.aligned;" ::: "memory")
#define MBARRIER_INIT(mbar, cnt) \
    asm volatile("mbarrier.init.shared.b64 [%0], %1;" \
                 :: "r"((uint32_t)(mbar)), "r"((uint32_t)(cnt)) : "memory")
#define MBARRIER_INVAL(mbar) \
    asm volatile("mbarrier.inval.shared.b64 [%0];" :: "r"((uint32_t)(mbar)) : "memory")
#define FENCE_PROXY_ASYNC() \
    asm volatile("fence.proxy.async.shared::cta;" ::: "memory")

#define MBARRIER_WAIT_PARITY(mbar_smem_addr, phase_parity) do { \
    uint32_t _mbar = (uint32_t)(mbar_smem_addr); \
    uint32_t _parity = (uint32_t)(phase_parity); \
    uint32_t _done; \
    asm volatile("{\n\t.reg .pred p;\n\t" \
        "mbarrier.try_wait.parity.acquire.cta.shared::cta.b64 p, [%1], %2;\n\t" \
        "selp.b32 %0, 1, 0, p;\n\t}" \
        : "=r"(_done) : "r"(_mbar), "r"(_parity) : "memory"); \
    if (!_done) { \
        asm volatile("{\n\t.reg .pred P1;\n\t" \
            "WAIT_LOOP_%=:\n\t" \
            "mbarrier.try_wait.parity.acquire.cta.shared::cta.b64 P1, [%0], %1, 0x989680;\n\t" \
            "@P1 bra.uni WAIT_DONE_%=;\n\t" \
            "bra.uni WAIT_LOOP_%=;\n\t" \
            "WAIT_DONE_%=:\n\t}" \
            :: "r"(_mbar), "r"(_parity) : "memory"); \
    } \
} while(0)

#define TCGEN05_LD_32X32B_X32(r, tmem_addr) \
    asm volatile( \
        "tcgen05.ld.sync.aligned.32x32b.x32.b32 " \
        "{%0, %1, %2, %3, %4, %5, %6, %7, " \
        " %8, %9, %10, %11, %12, %13, %14, %15, " \
        " %16, %17, %18, %19, %20, %21, %22, %23, " \
        " %24, %25, %26, %27, %28, %29, %30, %31}, [%32];" \
        : "=r"((r)[0]),  "=r"((r)[1]),  "=r"((r)[2]),  "=r"((r)[3]), \
          "=r"((r)[4]),  "=r"((r)[5]),  "=r"((r)[6]),  "=r"((r)[7]), \
          "=r"((r)[8]),  "=r"((r)[9]),  "=r"((r)[10]), "=r"((r)[11]), \
          "=r"((r)[12]), "=r"((r)[13]), "=r"((r)[14]), "=r"((r)[15]), \
          "=r"((r)[16]), "=r"((r)[17]), "=r"((r)[18]), "=r"((r)[19]), \
          "=r"((r)[20]), "=r"((r)[21]), "=r"((r)[22]), "=r"((r)[23]), \
          "=r"((r)[24]), "=r"((r)[25]), "=r"((r)[26]), "=r"((r)[27]), \
          "=r"((r)[28]), "=r"((r)[29]), "=r"((r)[30]), "=r"((r)[31]) \
        : "r"(tmem_addr))

static constexpr uint64_t SMEM_DESC_BASE_SW128 =
    (uint64_t(2) << 61) | (uint64_t(1) << 46) | (uint64_t(64) << 32) | (uint64_t(1) << 16);
#define MAKE_SMEM_DESC(addr) (SMEM_DESC_BASE_SW128 | ((uint64_t)((addr) >> 4) & 0x3FFF))

__device__ __forceinline__ void mma_bf16_ss(uint32_t d_tmem, uint64_t a_desc,
                                            uint64_t b_desc, uint32_t idesc,
                                            uint32_t enable_d) {
    uint32_t z = 0;
    asm volatile(
        "{\n\t.reg .pred p;\n\tsetp.ne.u32 p, %5, 0;\n\t"
        "tcgen05.mma.cta_group::1.kind::f16 [%0], %1, %2, %3, {%4, %4, %4, %4}, p;\n\t}"
        :: "r"(d_tmem), "l"(a_desc), "l"(b_desc), "r"(idesc), "r"(z), "r"(enable_d)
        : "memory");
}
__device__ __forceinline__ void mma_tf32_ss(uint32_t d_tmem, uint64_t a_desc,
                                            uint64_t b_desc, uint32_t idesc,
                                            uint32_t enable_d) {
    uint32_t z = 0;
    asm volatile(
        "{\n\t.reg .pred p;\n\tsetp.ne.u32 p, %5, 0;\n\t"
        "tcgen05.mma.cta_group::1.kind::tf32 [%0], %1, %2, %3, {%4, %4, %4, %4}, p;\n\t}"
        :: "r"(d_tmem), "l"(a_desc), "l"(b_desc), "r"(idesc), "r"(z), "r"(enable_d)
        : "memory");
}
#endif // TC_PATH

// ---------------------------------------------------------------------------
// Shared epilogue value transform
// ---------------------------------------------------------------------------
__device__ __forceinline__ void store_split3(__nv_bfloat16* op, int N,
                                             float v0, float v1) {
    __nv_bfloat16 h0 = __float2bfloat16_rn(v0);
    __nv_bfloat16 h1 = __float2bfloat16_rn(v1);
    uint32_t hp = pack_raw(h0, h1);
    uint32_t lp = pack_bf16x2(v0 - __bfloat162float(h0), v1 - __bfloat162float(h1));
    *reinterpret_cast<uint32_t*>(op) = hp;
    *reinterpret_cast<uint32_t*>(op + N) = lp;
    *reinterpret_cast<uint32_t*>(op + 2 * N) = hp;
}

#if !TC_PATH
// ---------------------------------------------------------------------------
// Legacy HMMA 128x128 tile (compute_103 fallback only)
// ---------------------------------------------------------------------------
#define RSTRIDE 36
#define ABUF (128 * RSTRIDE)
#define BBUF (128 * RSTRIDE)

__device__ void legacy_tile128(
    const __nv_bfloat16* __restrict__ A3, const __nv_bfloat16* __restrict__ B3,
    const float* __restrict__ bias, float* __restrict__ C,
    __nv_bfloat16* __restrict__ out3,
    int N, int K3, float alpha, int do_relu,
    int m0, int n0, uint32_t* sm, uint32_t smb)
{
    const int tid = threadIdx.x;
    const int wid = tid >> 5, lane = tid & 31;
    const int g = lane >> 2, c4 = lane & 3;
    const int warp_m = wid >> 2;
    const int warp_n = wid & 3;

    const int srow = tid >> 1, spart = tid & 1;
    const __nv_bfloat16* aptr = A3 + (size_t)(m0 + srow) * K3 + spart * 32;
    const __nv_bfloat16* bptr = B3 + (size_t)(n0 + srow) * K3 + spart * 32;
    const uint32_t as_base = smb + (srow * RSTRIDE + spart * 16) * 4;
    const uint32_t bs_base = smb + (2 * ABUF + srow * RSTRIDE + spart * 16) * 4;

    const int NC = K3 / 64;

    float acc[4][4][4];
    #pragma unroll
    for (int i = 0; i < 4; i++)
        #pragma unroll
        for (int j = 0; j < 4; j++)
            #pragma unroll
            for (int q = 0; q < 4; q++) acc[i][j][q] = 0.f;

    #pragma unroll
    for (int q = 0; q < 4; q++) cp16(as_base + q * 16, aptr + q * 8);
    #pragma unroll
    for (int q = 0; q < 4; q++) cp16(bs_base + q * 16, bptr + q * 8);
    cp_commit();

    for (int c = 0; c < NC; c++) {
        if (c + 1 < NC) {
            const int nb = (c + 1) & 1;
            const __nv_bfloat16* ap = aptr + (c + 1) * 64;
            const __nv_bfloat16* bp = bptr + (c + 1) * 64;
            #pragma unroll
            for (int q = 0; q < 4; q++)
                cp16(as_base + nb * ABUF * 4 + q * 16, ap + q * 8);
            #pragma unroll
            for (int q = 0; q < 4; q++)
                cp16(bs_base + nb * BBUF * 4 + q * 16, bp + q * 8);
            cp_commit();
            cp_wait<1>();
        } else {
            cp_wait<0>();
        }
        __syncthreads();

        const uint32_t* ab = sm + (c & 1) * ABUF;
        const uint32_t* bb = sm + 2 * ABUF + (c & 1) * BBUF;

        #pragma unroll
        for (int ks = 0; ks < 4; ks++) {
            const int kb = ks * 8;
            uint32_t af[4][4], bf[4][2];
            #pragma unroll
            for (int i = 0; i < 4; i++) {
                const uint32_t* p = ab + (warp_m * 64 + i * 16 + g) * RSTRIDE + kb + c4;
                af[i][0] = p[0];
                af[i][1] = p[8 * RSTRIDE];
                af[i][2] = p[4];
                af[i][3] = p[8 * RSTRIDE + 4];
            }
            #pragma unroll
            for (int j = 0; j < 4; j++) {
                const uint32_t* p = bb + (warp_n * 32 + j * 8 + g) * RSTRIDE + kb + c4;
                bf[j][0] = p[0];
                bf[j][1] = p[4];
            }
            #pragma unroll
            for (int i = 0; i < 4; i++)
                #pragma unroll
                for (int j = 0; j < 4; j++)
                    mma16(acc[i][j], af[i], bf[j]);
        }
        __syncthreads();
    }

    #pragma unroll
    for (int i = 0; i < 4; i++) {
        #pragma unroll
        for (int j = 0; j < 4; j++) {
            const int col = n0 + warp_n * 32 + j * 8 + c4 * 2;
            float b0v = 0.f, b1v = 0.f;
            if (bias) { b0v = bias[col]; b1v = bias[col + 1]; }
            float v0 = acc[i][j][0] * alpha + b0v;
            float v1 = acc[i][j][1] * alpha + b1v;
            float v2 = acc[i][j][2] * alpha + b0v;
            float v3 = acc[i][j][3] * alpha + b1v;
            if (do_relu) {
                v0 = fmaxf(v0, 0.f); v1 = fmaxf(v1, 0.f);
                v2 = fmaxf(v2, 0.f); v3 = fmaxf(v3, 0.f);
            }
            const int ra = m0 + warp_m * 64 + i * 16 + g;
            if (out3) {
                store_split3(out3 + (size_t)ra * 3 * N + col, N, v0, v1);
                store_split3(out3 + (size_t)(ra + 8) * 3 * N + col, N, v2, v3);
            } else {
                float2 lo = {v0, v1}, hi = {v2, v3};
                *reinterpret_cast<float2*>(C + (size_t)ra * N + col) = lo;
                *reinterpret_cast<float2*>(C + (size_t)(ra + 8) * N + col) = hi;
            }
        }
    }
}
#endif // !TC_PATH

// ---------------------------------------------------------------------------
// 256x256 bf16-split GEMM (all bf16-split GEMMs).  3-stage, 1 CTA/SM.
// C = alpha*(A3[M,K3] @ B3[N,K3]^T) + bias (+relu), or split-bf16 out3.
// Requires K3 % 64 == 0, K3/64 >= 2, M%256==0, N%256==0.
// ---------------------------------------------------------------------------
#define G2_SMEM (1024 + 3 * 65536)   // 197632 B

__global__ __launch_bounds__(256, 1) void gemm256_kernel(
    const __nv_bfloat16* __restrict__ A3, const __nv_bfloat16* __restrict__ B3,
    const float* __restrict__ bias, float* __restrict__ C,
    __nv_bfloat16* __restrict__ out3,
    int M, int N, int K3, float alpha, int do_relu)
{
#if TC_PATH
    extern __shared__ char smc[];
    const uint32_t smb = smem_u32(smc);
    const int tid = threadIdx.x;
    const int wid = tid >> 5, lane = tid & 31;
    const int m0 = blockIdx.x * 256;
    const int n0 = blockIdx.y * 256;

    const uint32_t mb[3] = {smb + 8u, smb + 16u, smb + 24u};

    if (wid == 0) TCGEN05_ALLOC(smb, 512);
    if (tid == 0) { MBARRIER_INIT(mb[0], 1); MBARRIER_INIT(mb[1], 1); MBARRIER_INIT(mb[2], 1); }
    __syncthreads();
    uint32_t tmem;
    asm volatile("ld.shared.b32 %0, [%1];" : "=r"(tmem) : "r"(smb));
    if (wid == 0) TCGEN05_RELINQUISH();

    const uint32_t IDESC2 =
        (1u << 4) | (1u << 7) | (1u << 10) | ((256 / 8) << 17) | ((128 / 16) << 24);

    const int NC = K3 / 64;
    const int r0s = tid >> 3;
    const int c8 = tid & 7;
    const __nv_bfloat16* abase = A3 + (size_t)(m0 + r0s) * K3 + c8 * 8;
    const __nv_bfloat16* bbase = B3 + (size_t)(n0 + r0s) * K3 + c8 * 8;
    uint32_t swoff[8];
    #pragma unroll
    for (int it = 0; it < 8; it++)
        swoff[it] = SMEM_SWIZZLE_128B((uint32_t)((r0s + it * 32) * 128 + c8 * 16));

    auto stage_chunk = [&](int chunk, int buf) {
        const uint32_t sa = smb + 1024u + (uint32_t)buf * 65536u;
        const uint32_t sbo = sa + 32768u;
        #pragma unroll
        for (int it = 0; it < 8; it++) {
            cp16(sa + swoff[it], abase + (size_t)it * 32 * K3 + chunk * 64);
            cp16(sbo + swoff[it], bbase + (size_t)it * 32 * K3 + chunk * 64);
        }
        cp_commit();
    };

    int ph[3] = {0, 0, 0};
    stage_chunk(0, 0);
    stage_chunk(1, 1);

    for (int c = 0; c < NC; c++) {
        const int b = c % 3;
        if (c + 2 < NC) {
            const int nb = (c + 2) % 3;
            if (c >= 1) { MBARRIER_WAIT_PARITY(mb[nb], ph[nb]); ph[nb] ^= 1; }
            stage_chunk(c + 2, nb);
            cp_wait<2>();
        } else if (c + 1 < NC) {
            cp_wait<1>();
        } else {
            cp_wait<0>();
        }
        __syncthreads();
        if (wid == 0 && elect_one_pred()) {
            FENCE_PROXY_ASYNC();
            const uint32_t sa = smb + 1024u + (uint32_t)b * 65536u;
            const uint64_t ad = MAKE_SMEM_DESC(sa);
            const uint64_t bd = MAKE_SMEM_DESC(sa + 32768u);
            #pragma unroll
            for (int ks = 0; ks < 4; ks++) {
                const uint32_t en = (c > 0 || ks > 0) ? 1u : 0u;
                mma_bf16_ss(tmem,       ad + ks * 2,        bd + ks * 2, IDESC2, en);
                mma_bf16_ss(tmem + 256, ad + 1024 + ks * 2, bd + ks * 2, IDESC2, en);
            }
            TCGEN05_COMMIT(mb[b]);
        }
    }
    MBARRIER_WAIT_PARITY(mb[(NC - 1) % 3], ph[(NC - 1) % 3]);
    TCGEN05_FENCE_AFTER();

    {
        const int mh = wid >> 2;
        const int w4 = wid & 3;
        const uint32_t lofs = (uint32_t)w4 << 21;
        const int row = m0 + mh * 128 + w4 * 32 + lane;
        #pragma unroll
        for (int j = 0; j < 8; j++) {
            uint32_t r[32];
            TCGEN05_LD_32X32B_X32(r, tmem + mh * 256 + j * 32 + lofs);
            TCGEN05_WAIT_LD();
            const float* bp = bias ? (bias + n0 + j * 32) : nullptr;
            if (out3) {
                __nv_bfloat16* op = out3 + (size_t)row * 3 * N + n0 + j * 32;
                #pragma unroll
                for (int q = 0; q < 32; q += 2) {
                    float v0 = __uint_as_float(r[q + 0]) * alpha;
                    float v1 = __uint_as_float(r[q + 1]) * alpha;
                    if (bp) { v0 += bp[q]; v1 += bp[q + 1]; }
                    if (do_relu) { v0 = fmaxf(v0, 0.f); v1 = fmaxf(v1, 0.f); }
                    store_split3(op + q, N, v0, v1);
                }
            } else {
                float* cp = C + (size_t)row * N + n0 + j * 32;
                #pragma unroll
                for (int q = 0; q < 32; q += 4) {
                    float v0 = __uint_as_float(r[q + 0]) * alpha;
                    float v1 = __uint_as_float(r[q + 1]) * alpha;
                    float v2 = __uint_as_float(r[q + 2]) * alpha;
                    float v3 = __uint_as_float(r[q + 3]) * alpha;
                    if (bp) { v0 += bp[q]; v1 += bp[q + 1]; v2 += bp[q + 2]; v3 += bp[q + 3]; }
                    if (do_relu) {
                        v0 = fmaxf(v0, 0.f); v1 = fmaxf(v1, 0.f);
                        v2 = fmaxf(v2, 0.f); v3 = fmaxf(v3, 0.f);
                    }
                    float4 o = {v0, v1, v2, v3};
                    *reinterpret_cast<float4*>(cp + q) = o;
                }
            }
        }
        TCGEN05_FENCE_BEFORE();
    }
    __syncthreads();
    if (tid == 0) { MBARRIER_INVAL(mb[0]); MBARRIER_INVAL(mb[1]); MBARRIER_INVAL(mb[2]); }
    __syncthreads();
    if (wid == 0) TCGEN05_DEALLOC(tmem, 512);
#else
    extern __shared__ uint32_t sm[];
    const uint32_t smb = smem_u32(sm);
    #pragma unroll
    for (int qm = 0; qm < 2; qm++)
        for (int qn = 0; qn < 2; qn++) {
            legacy_tile128(A3, B3, bias, C, out3, N, K3, alpha, do_relu,
                           blockIdx.x * 256 + qm * 128,
                           blockIdx.y * 256 + qn * 128, sm, smb);
            __syncthreads();
        }
#endif
}

// ---------------------------------------------------------------------------
// 256x256 tf32 GEMM (logits only). A, B are RNA-tf32-rounded fp32.
// ---------------------------------------------------------------------------
__global__ __launch_bounds__(256, 1) void gemm256tf_kernel(
    const float* __restrict__ A, const float* __restrict__ Bm,
    float* __restrict__ C, int M, int N, int K)
{
#if TC_PATH
    extern __shared__ char smc[];
    const uint32_t smb = smem_u32(smc);
    const int tid = threadIdx.x;
    const int wid = tid >> 5, lane = tid & 31;
    const int m0 = blockIdx.x * 256;
    const int n0 = blockIdx.y * 256;

    const uint32_t mb[3] = {smb + 8u, smb + 16u, smb + 24u};

    if (wid == 0) TCGEN05_ALLOC(smb, 512);
    if (tid == 0) { MBARRIER_INIT(mb[0], 1); MBARRIER_INIT(mb[1], 1); MBARRIER_INIT(mb[2], 1); }
    __syncthreads();
    uint32_t tmem;
    asm volatile("ld.shared.b32 %0, [%1];" : "=r"(tmem) : "r"(smb));
    if (wid == 0) TCGEN05_RELINQUISH();

    const uint32_t IDESCT =
        (1u << 4) | (2u << 7) | (2u << 10) | ((256 / 8) << 17) | ((128 / 16) << 24);

    const int NC = K / 32;
    const int r0s = tid >> 3;
    const int c8 = tid & 7;
    const float* abase = A + (size_t)(m0 + r0s) * K + c8 * 4;
    const float* bbase = Bm + (size_t)(n0 + r0s) * K + c8 * 4;
    uint32_t swoff[8];
    #pragma unroll
    for (int it = 0; it < 8; it++)
        swoff[it] = SMEM_SWIZZLE_128B((uint32_t)((r0s + it * 32) * 128 + c8 * 16));

    auto stage_chunk = [&](int chunk, int buf) {
        const uint32_t sa = smb + 1024u + (uint32_t)buf * 65536u;
        const uint32_t sbo = sa + 32768u;
        #pragma unroll
        for (int it = 0; it < 8; it++) {
            cp16(sa + swoff[it], abase + (size_t)it * 32 * K + chunk * 32);
            cp16(sbo + swoff[it], bbase + (size_t)it * 32 * K + chunk * 32);
        }
        cp_commit();
    };

    int ph[3] = {0, 0, 0};
    stage_chunk(0, 0);
    stage_chunk(1, 1);

    for (int c = 0; c < NC; c++) {
        const int b = c % 3;
        if (c + 2 < NC) {
            const int nb = (c + 2) % 3;
            if (c >= 1) { MBARRIER_WAIT_PARITY(mb[nb], ph[nb]); ph[nb] ^= 1; }
            stage_chunk(c + 2, nb);
            cp_wait<2>();
        } else if (c + 1 < NC) {
            cp_wait<1>();
        } else {
            cp_wait<0>();
        }
        __syncthreads();
        if (wid == 0 && elect_one_pred()) {
            FENCE_PROXY_ASYNC();
            const uint32_t sa = smb + 1024u + (uint32_t)b * 65536u;
            const uint64_t ad = MAKE_SMEM_DESC(sa);
            const uint64_t bd = MAKE_SMEM_DESC(sa + 32768u);
            #pragma unroll
            for (int ks = 0; ks < 4; ks++) {
                const uint32_t en = (c > 0 || ks > 0) ? 1u : 0u;
                mma_tf32_ss(tmem,       ad + ks * 2,        bd + ks * 2, IDESCT, en);
                mma_tf32_ss(tmem + 256, ad + 1024 + ks * 2, bd + ks * 2, IDESCT, en);
            }
            TCGEN05_COMMIT(mb[b]);
        }
    }
    MBARRIER_WAIT_PARITY(mb[(NC - 1) % 3], ph[(NC - 1) % 3]);
    TCGEN05_FENCE_AFTER();

    {
        const int mh = wid >> 2;
        const int w4 = wid & 3;
        const uint32_t lofs = (uint32_t)w4 << 21;
        const int row = m0 + mh * 128 + w4 * 32 + lane;
        #pragma unroll
        for (int j = 0; j < 8; j++) {
            uint32_t r[32];
            TCGEN05_LD_32X32B_X32(r, tmem + mh * 256 + j * 32 + lofs);
            TCGEN05_WAIT_LD();
            float* cp = C + (size_t)row * N + n0 + j * 32;
            #pragma unroll
            for (int q = 0; q < 32; q += 4) {
                float4 o;
                o.x = __uint_as_float(r[q + 0]);
                o.y = __uint_as_float(r[q + 1]);
                o.z = __uint_as_float(r[q + 2]);
                o.w = __uint_as_float(r[q + 3]);
                *reinterpret_cast<float4*>(cp + q) = o;
            }
        }
        TCGEN05_FENCE_BEFORE();
    }
    __syncthreads();
    if (tid == 0) { MBARRIER_INVAL(mb[0]); MBARRIER_INVAL(mb[1]); MBARRIER_INVAL(mb[2]); }
    __syncthreads();
    if (wid == 0) TCGEN05_DEALLOC(tmem, 512);
#else
    // correctness-only fallback (never executes on sm_103a; operands pre-rounded)
    const int m0 = blockIdx.x * 256;
    const int n0 = blockIdx.y * 256;
    for (int idx = threadIdx.x; idx < 256 * 256; idx += 256) {
        const int i = idx >> 8, j = idx & 255;
        const float* a = A + (size_t)(m0 + i) * K;
        const float* b = Bm + (size_t)(n0 + j) * K;
        float s = 0.f;
        for (int k = 0; k < K; k++) s += a[k] * b[k];
        C[(size_t)(m0 + i) * N + n0 + j] = s;
    }
#endif
}

// ---------------------------------------------------------------------------
// Tensor-core split-bf16 causal flash attention (fused-QKV input, stride QKVS)
// ---------------------------------------------------------------------------
#define AT_STRIDE 136
#define ATT_SMEM  (3 * 64 * AT_STRIDE * 2)   // 52224 B

__global__ __launch_bounds__(128, 3) void attn_mma_kernel(
    const float* __restrict__ Q, const float* __restrict__ Kg,
    const float* __restrict__ Vg, __nv_bfloat16* __restrict__ conc3)
{
    extern __shared__ __nv_bfloat16 sh[];
    __nv_bfloat16* Qs = sh;
    __nv_bfloat16* Ks = sh + 64 * AT_STRIDE;
    __nv_bfloat16* Vs = sh + 128 * AT_STRIDE;

    const int qt = blockIdx.x;
    const int bh = blockIdx.y;
    const int b = bh >> 4, n = bh & 15;
    const int tid = threadIdx.x;
    const int wid = tid >> 5, lane = tid & 31;
    const int g = lane >> 2, c4 = lane & 3;

    {
        const int r = tid >> 1;
        const int dbase = (tid & 1) * 32;
        const float* qp = Q + ((size_t)(b * S_ + qt * 64 + r)) * QKVS + n * 64 + dbase;
        #pragma unroll
        for (int i = 0; i < 32; i += 4) {
            float4 f = *reinterpret_cast<const float4*>(qp + i);
            float vals[4] = {f.x, f.y, f.z, f.w};
            #pragma unroll
            for (int e = 0; e < 4; e++) {
                __nv_bfloat16 hi = __float2bfloat16_rn(vals[e]);
                Qs[r * AT_STRIDE + dbase + i + e] = hi;
                Qs[r * AT_STRIDE + 64 + dbase + i + e] =
                    __float2bfloat16_rn(vals[e] - __bfloat162float(hi));
            }
        }
    }

    const int row0 = wid * 16 + g;
    float m0 = -1e30f, m1 = -1e30f, l0 = 0.f, l1 = 0.f;
    float o[8][4];
    #pragma unroll
    for (int j = 0; j < 8; j++)
        #pragma unroll
        for (int q = 0; q < 4; q++) o[j][q] = 0.f;

    for (int kt = 0; kt <= qt; kt++) {
        __syncthreads();
        {
            const int r = tid >> 1;
            const int dbase = (tid & 1) * 32;
            const float* kp = Kg + ((size_t)(b * S_ + kt * 64 + r)) * QKVS + n * 64 + dbase;
            const float* vp = Vg + ((size_t)(b * S_ + kt * 64 + r)) * QKVS + n * 64 + dbase;
            #pragma unroll
            for (int i = 0; i < 32; i += 4) {
                float4 fk = *reinterpret_cast<const float4*>(kp + i);
                float4 fv = *reinterpret_cast<const float4*>(vp + i);
                float kv[4] = {fk.x, fk.y, fk.z, fk.w};
                float vv[4] = {fv.x, fv.y, fv.z, fv.w};
                #pragma unroll
                for (int e = 0; e < 4; e++) {
                    const int d = dbase + i + e;
                    __nv_bfloat16 kh = __float2bfloat16_rn(kv[e]);
                    Ks[r * AT_STRIDE + d] = kh;
                    Ks[r * AT_STRIDE + 64 + d] =
                        __float2bfloat16_rn(kv[e] - __bfloat162float(kh));
                    __nv_bfloat16 vh = __float2bfloat16_rn(vv[e]);
                    Vs[d * AT_STRIDE + r] = vh;
                    Vs[d * AT_STRIDE + 64 + r] =
                        __float2bfloat16_rn(vv[e] - __bfloat162float(vh));
                }
            }
        }
        __syncthreads();

        float s[8][4];
        #pragma unroll
        for (int j = 0; j < 8; j++)
            #pragma unroll
            for (int q = 0; q < 4; q++) s[j][q] = 0.f;

        #pragma unroll
        for (int phs = 0; phs < 3; phs++) {
            const int aoff = (phs == 1) ? 64 : 0;
            const int boff = (phs == 2) ? 64 : 0;
            #pragma unroll
            for (int ks = 0; ks < 4; ks++) {
                uint32_t a[4];
                const __nv_bfloat16* ap = Qs + row0 * AT_STRIDE + aoff + ks * 16 + c4 * 2;
                a[0] = *reinterpret_cast<const uint32_t*>(ap);
                a[1] = *reinterpret_cast<const uint32_t*>(ap + 8 * AT_STRIDE);
                a[2] = *reinterpret_cast<const uint32_t*>(ap + 8);
                a[3] = *reinterpret_cast<const uint32_t*>(ap + 8 * AT_STRIDE + 8);
                #pragma unroll
                for (int j = 0; j < 8; j++) {
                    uint32_t bf[2];
                    const __nv_bfloat16* bp =
                        Ks + (8 * j + g) * AT_STRIDE + boff + ks * 16 + c4 * 2;
                    bf[0] = *reinterpret_cast<const uint32_t*>(bp);
                    bf[1] = *reinterpret_cast<const uint32_t*>(bp + 8);
                    mma16(s[j], a, bf);
                }
            }
        }

        if (kt == qt) {
            #pragma unroll
            for (int j = 0; j < 8; j++) {
                const int colb = 8 * j + 2 * c4;
                if (colb     > row0)     s[j][0] = -1e30f;
                if (colb + 1 > row0)     s[j][1] = -1e30f;
                if (colb     > row0 + 8) s[j][2] = -1e30f;
                if (colb + 1 > row0 + 8) s[j][3] = -1e30f;
            }
        }

        float rm0 = -1e30f, rm1 = -1e30f;
        #pragma unroll
        for (int j = 0; j < 8; j++) {
            rm0 = fmaxf(rm0, fmaxf(s[j][0], s[j][1]));
            rm1 = fmaxf(rm1, fmaxf(s[j][2], s[j][3]));
        }
        rm0 = fmaxf(rm0, __shfl_xor_sync(0xFFFFFFFFu, rm0, 1));
        rm0 = fmaxf(rm0, __shfl_xor_sync(0xFFFFFFFFu, rm0, 2));
        rm1 = fmaxf(rm1, __shfl_xor_sync(0xFFFFFFFFu, rm1, 1));
        rm1 = fmaxf(rm1, __shfl_xor_sync(0xFFFFFFFFu, rm1, 2));
        const float mn0 = fmaxf(m0, rm0), mn1 = fmaxf(m1, rm1);
        const float cr0 = __expf(m0 - mn0), cr1 = __expf(m1 - mn1);
        m0 = mn0; m1 = mn1;

        float ps0 = 0.f, ps1 = 0.f;
        uint32_t phi[8][2], plo[8][2];
        #pragma unroll
        for (int j = 0; j < 8; j++) {
            float p0 = __expf(s[j][0] - mn0);
            float p1 = __expf(s[j][1] - mn0);
            float p2 = __expf(s[j][2] - mn1);
            float p3 = __expf(s[j][3] - mn1);
            ps0 += p0 + p1; ps1 += p2 + p3;
            __nv_bfloat16 h0 = __float2bfloat16_rn(p0), h1 = __float2bfloat16_rn(p1);
            __nv_bfloat16 h2 = __float2bfloat16_rn(p2), h3 = __float2bfloat16_rn(p3);
            phi[j][0] = pack_raw(h0, h1);
            phi[j][1] = pack_raw(h2, h3);
            plo[j][0] = pack_bf16x2(p0 - __bfloat162float(h0), p1 - __bfloat162float(h1));
            plo[j][1] = pack_bf16x2(p2 - __bfloat162float(h2), p3 - __bfloat162float(h3));
        }
        ps0 += __shfl_xor_sync(0xFFFFFFFFu, ps0, 1);
        ps0 += __shfl_xor_sync(0xFFFFFFFFu, ps0, 2);
        ps1 += __shfl_xor_sync(0xFFFFFFFFu, ps1, 1);
        ps1 += __shfl_xor_sync(0xFFFFFFFFu, ps1, 2);
        l0 = l0 * cr0 + ps0;
        l1 = l1 * cr1 + ps1;
        #pragma unroll
        for (int j = 0; j < 8; j++) {
            o[j][0] *= cr0; o[j][1] *= cr0;
            o[j][2] *= cr1; o[j][3] *= cr1;
        }

        #pragma unroll
        for (int phs = 0; phs < 3; phs++) {
            const int voff = (phs == 2) ? 64 : 0;
            #pragma unroll
            for (int ks = 0; ks < 4; ks++) {
                uint32_t a[4];
                if (phs == 1) {
                    a[0] = plo[2 * ks][0]; a[1] = plo[2 * ks][1];
                    a[2] = plo[2 * ks + 1][0]; a[3] = plo[2 * ks + 1][1];
                } else {
                    a[0] = phi[2 * ks][0]; a[1] = phi[2 * ks][1];
                    a[2] = phi[2 * ks + 1][0]; a[3] = phi[2 * ks + 1][1];
                }
                #pragma unroll
                for (int j = 0; j < 8; j++) {
                    uint32_t bf[2];
                    const __nv_bfloat16* bp =
                        Vs + (8 * j + g) * AT_STRIDE + voff + ks * 16 + c4 * 2;
                    bf[0] = *reinterpret_cast<const uint32_t*>(bp);
                    bf[1] = *reinterpret_cast<const uint32_t*>(bp + 8);
                    mma16(o[j], a, bf);
                }
            }
        }
    }

    const float inv0 = 1.f / l0, inv1 = 1.f / l1;
    const size_t r0 = (size_t)(b * S_ + qt * 64 + row0);
    __nv_bfloat16* o0 = conc3 + r0 * 3 * H_;
    __nv_bfloat16* o1 = conc3 + (r0 + 8) * 3 * H_;
    #pragma unroll
    for (int j = 0; j < 8; j++) {
        const int col = n * 64 + 8 * j + 2 * c4;
        store_split3(o0 + col, H_, o[j][0] * inv0, o[j][1] * inv0);
        store_split3(o1 + col, H_, o[j][2] * inv1, o[j][3] * inv1);
    }
}

// ---------------------------------------------------------------------------
// Conversion / elementwise kernels
// ---------------------------------------------------------------------------
// fused gather + split: A3_emb[i, :] from emb_decode[x[i], :]
__global__ void gather_split_kernel(const int* __restrict__ x,
                                    const float* __restrict__ emb,
                                    __nv_bfloat16* __restrict__ out3)
{
    int idx = blockIdx.x * blockDim.x + threadIdx.x;
    if (idx >= M4 * E_) return;
    int i = idx / E_;
    int e = idx - i * E_;
    float v = emb[(size_t)x[i] * E_ + e];
    __nv_bfloat16 hi = __float2bfloat16_rn(v);
    __nv_bfloat16 lo = __float2bfloat16_rn(v - __bfloat162float(hi));
    size_t base = (size_t)i * 3 * E_;
    out3[base + e] = hi;
    out3[base + E_ + e] = lo;
    out3[base + 2 * E_ + e] = hi;
}

__global__ __launch_bounds__(256) void conv_wT_kernel(
    const float* __restrict__ W, __nv_bfloat16* __restrict__ out,
    int K, int N, float wscale)
{
    __shared__ float tile[32][33];
    const int tx = threadIdx.x & 31;
    const int ty = threadIdx.x >> 5;
    const int n0 = blockIdx.x * 32;
    const int k0 = blockIdx.y * 32;
    #pragma unroll
    for (int i = 0; i < 4; i++)
        tile[ty + i * 8][tx] = W[(size_t)(k0 + ty + i * 8) * N + n0 + tx];
    __syncthreads();
    #pragma unroll
    for (int i = 0; i < 4; i++) {
        const int nn = n0 + ty + i * 8;
        const int k = k0 + tx;
        float x = tile[tx][ty + i * 8] * wscale;
        __nv_bfloat16 hi = __float2bfloat16_rn(x);
        __nv_bfloat16 lo = __float2bfloat16_rn(x - __bfloat162float(hi));
        size_t base = (size_t)nn * 3 * K;
        out[base + k] = hi;
        out[base + K + k] = hi;
        out[base + 2 * K + k] = lo;
    }
}

// transpose + RNA-tf32-round to fp32 (for p_decoder)
__global__ __launch_bounds__(256) void conv_wTf32_kernel(
    const float* __restrict__ W, float* __restrict__ out, int K, int N)
{
    __shared__ float tile[32][33];
    const int tx = threadIdx.x & 31;
    const int ty = threadIdx.x >> 5;
    const int n0 = blockIdx.x * 32;
    const int k0 = blockIdx.y * 32;
    #pragma unroll
    for (int i = 0; i < 4; i++)
        tile[ty + i * 8][tx] = W[(size_t)(k0 + ty + i * 8) * N + n0 + tx];
    __syncthreads();
    #pragma unroll
    for (int i = 0; i < 4; i++) {
        const int nn = n0 + ty + i * 8;
        out[(size_t)nn * K + k0 + tx] = rna_tf32(tile[tx][ty + i * 8]);
    }
}

__global__ void addpos_kernel(const float* __restrict__ xemb,
                              const float* __restrict__ pos11,
                              float* __restrict__ out,
                              __nv_bfloat16* __restrict__ out3)
{
    int idx = blockIdx.x * blockDim.x + threadIdx.x;
    if (idx >= M4 * H_) return;
    int i = idx / H_;
    int h = idx - i * H_;
    int s = i & (S_ - 1);
    float y = xemb[idx] + pos11[(size_t)s * H_ + h];
    out[idx] = y;
    __nv_bfloat16 hi = __float2bfloat16_rn(y);
    __nv_bfloat16 lo = __float2bfloat16_rn(y - __bfloat162float(hi));
    size_t base = (size_t)i * 3 * H_;
    out3[base + h] = hi;
    out3[base + H_ + h] = lo;
    out3[base + 2 * H_ + h] = hi;
}

__global__ __launch_bounds__(256) void ln_res_kernel(
    const float* __restrict__ res, const float* __restrict__ x,
    const float* __restrict__ bias, const float* __restrict__ scale,
    float* __restrict__ out, __nv_bfloat16* __restrict__ out3,
    int round_out)
{
    __shared__ float red[256];
    const int row = blockIdx.x;
    const int t = threadIdx.x;
    const float* xr = x + (size_t)row * H_;

    float lsum = 0.f;
    for (int i = t; i < H_; i += 256) lsum += xr[i];
    red[t] = lsum; __syncthreads();
    for (int s = 128; s > 0; s >>= 1) { if (t < s) red[t] += red[t + s]; __syncthreads(); }
    const float mean = red[0] * (1.0f / H_);
    __syncthreads();

    float lvar = 0.f;
    for (int i = t; i < H_; i += 256) { float d = xr[i] - mean; lvar += d * d; }
    red[t] = lvar; __syncthreads();
    for (int s = 128; s > 0; s >>= 1) { if (t < s) red[t] += red[t + s]; __syncthreads(); }
    const float rstd = rsqrtf(red[0] * (1.0f / H_) + 1e-6f);

    for (int i = t; i < H_; i += 256) {
        float y = res[(size_t)row * H_ + i] + (xr[i] - mean) * rstd * scale[i] + bias[i];
        out[(size_t)row * H_ + i] = round_out ? rna_tf32(y) : y;
        if (out3) {
            __nv_bfloat16 hi = __float2bfloat16_rn(y);
            __nv_bfloat16 lo = __float2bfloat16_rn(y - __bfloat162float(hi));
            size_t base = (size_t)row * 3 * H_;
            out3[base + i] = hi;
            out3[base + H_ + i] = lo;
            out3[base + 2 * H_ + i] = hi;
        }
    }
}

// ---------------------------------------------------------------------------
// Launch helpers
// ---------------------------------------------------------------------------
static inline void run_gemm256(const __nv_bfloat16* A3, const __nv_bfloat16* B3,
                               const float* bias, float* C, __nv_bfloat16* out3,
                               int M, int N, int K3, float alpha, int relu)
{
    dim3 grid(M / 256, N / 256);
    gemm256_kernel<<<grid, 256, G2_SMEM>>>(A3, B3, bias, C, out3,
                                           M, N, K3, alpha, relu);
}
static inline void run_gemm256tf(const float* A, const float* Bm, float* C,
                                 int M, int N, int K)
{
    dim3 grid(M / 256, N / 256);
    gemm256tf_kernel<<<grid, 256, G2_SMEM>>>(A, Bm, C, M, N, K);
}
static inline void run_conv_wT(const float* W, __nv_bfloat16* out,
                               int K, int N, float wscale)
{
    dim3 grid(N / 32, K / 32);
    conv_wT_kernel<<<grid, 256>>>(W, out, K, N, wscale);
}

extern "C" void kernel_launch(void* const* d_in, const int* in_sizes, int n_in,
                              void* d_out, int out_size)
{
    const int*   x            = (const int*)  d_in[0];
    const float* emb_decode   = (const float*)d_in[1];
    const float* W_dec_lin    = (const float*)d_in[2];
    const float* p_decoder    = (const float*)d_in[3];
    const float* x_emb_pos    = (const float*)d_in[4];
    const float* p_d_q        = (const float*)d_in[5];
    const float* p_d_k        = (const float*)d_in[6];
    const float* p_d_v        = (const float*)d_in[7];
    const float* p_d_c        = (const float*)d_in[8];
    const float* p_d_ff1      = (const float*)d_in[9];
    const float* p_d_ff2      = (const float*)d_in[10];
    const float* b_d_ff1      = (const float*)d_in[11];
    const float* b_d_ff2      = (const float*)d_in[12];
    const float* d_o_bias     = (const float*)d_in[13];
    const float* d_o_scale    = (const float*)d_in[14];
    const float* b_d_bias_1   = (const float*)d_in[15];
    const float* b_d_bias_2   = (const float*)d_in[16];
    const float* b_d_scale_1  = (const float*)d_in[17];
    const float* b_d_scale_2  = (const float*)d_in[18];
    float* out = (float*)d_out;

    const int m = L_ - 1;   // only the last layer's result is observable

    cudaFuncSetAttribute(gemm256_kernel,
                         cudaFuncAttributeMaxDynamicSharedMemorySize, G2_SMEM);
    cudaFuncSetAttribute(gemm256tf_kernel,
                         cudaFuncAttributeMaxDynamicSharedMemorySize, G2_SMEM);
    cudaFuncSetAttribute(attn_mma_kernel,
                         cudaFuncAttributeMaxDynamicSharedMemorySize, ATT_SMEM);

    float *xemb, *layerin, *qkv, *xmulti, *xself, *ffw2, *xffw, *decout, *wtp;
    __nv_bfloat16 *a3_emb, *a3_li, *a3_conc, *a3_self, *a3_ffw1;
    __nv_bfloat16 *w3_dec, *w3_qkv, *w3_c, *w3_ff1, *w3_ff2;
    cudaGetSymbolAddress((void**)&xemb,    g_xemb);
    cudaGetSymbolAddress((void**)&layerin, g_layerin);
    cudaGetSymbolAddress((void**)&qkv,     g_qkv);
    cudaGetSymbolAddress((void**)&xmulti,  g_xmulti);
    cudaGetSymbolAddress((void**)&xself,   g_xself);
    cudaGetSymbolAddress((void**)&ffw2,    g_ffw2);
    cudaGetSymbolAddress((void**)&xffw,    g_xffw);
    cudaGetSymbolAddress((void**)&decout,  g_decout);
    cudaGetSymbolAddress((void**)&wtp,     g_wtp);
    cudaGetSymbolAddress((void**)&a3_emb,  g_a3_emb);
    cudaGetSymbolAddress((void**)&a3_li,   g_a3_li);
    cudaGetSymbolAddress((void**)&a3_conc, g_a3_conc);
    cudaGetSymbolAddress((void**)&a3_self, g_a3_self);
    cudaGetSymbolAddress((void**)&a3_ffw1, g_a3_ffw1);
    cudaGetSymbolAddress((void**)&w3_dec,  g_w3_dec);
    cudaGetSymbolAddress((void**)&w3_qkv,  g_w3_qkv);
    cudaGetSymbolAddress((void**)&w3_c,    g_w3_c);
    cudaGetSymbolAddress((void**)&w3_ff1,  g_w3_ff1);
    cudaGetSymbolAddress((void**)&w3_ff2,  g_w3_ff2);

    // weight conversions; Q weights pre-scaled by 1/sqrt(head)
    run_conv_wT(W_dec_lin, w3_dec, E_, H_, 1.f);
    run_conv_wT(p_d_q + (size_t)m * H_ * H_, w3_qkv, H_, H_, 0.125f);
    run_conv_wT(p_d_k + (size_t)m * H_ * H_, w3_qkv + (size_t)1024 * 3 * H_, H_, H_, 1.f);
    run_conv_wT(p_d_v + (size_t)m * H_ * H_, w3_qkv + (size_t)2048 * 3 * H_, H_, H_, 1.f);
    run_conv_wT(p_d_c + (size_t)m * H_ * H_, w3_c, H_, H_, 1.f);
    run_conv_wT(p_d_ff1 + (size_t)m * H_ * FF_, w3_ff1, H_, FF_, 1.f);
    run_conv_wT(p_d_ff2 + (size_t)m * FF_ * H_, w3_ff2, FF_, H_, 1.f);
    {   // p_decoder -> transposed RNA-rounded fp32
        dim3 grid(V_ / 32, H_ / 32);
        conv_wTf32_kernel<<<grid, 256>>>(p_decoder, wtp, H_, V_);
    }

    // 1. gather embeddings + split (fused)
    gather_split_kernel<<<(M4 * E_ + 255) / 256, 256>>>(x, emb_decode, a3_emb);

    // 2. x_dec_embed = A_emb @ W_dec_lin   (K3 = 384, NC = 6)
    run_gemm256(a3_emb, w3_dec, nullptr, xemb, nullptr, M4, H_, 3 * E_, 1.f, 0);

    // 3. layer_in = pos[11] + x_dec_embed  (+ fused split)
    addpos_kernel<<<(M4 * H_ + 255) / 256, 256>>>(
        xemb, x_emb_pos + (size_t)m * S_ * H_, layerin, a3_li);

    // 4. fused Q/K/V projection
    run_gemm256(a3_li, w3_qkv, nullptr, qkv, nullptr, M4, QKVS, 3 * H_, 1.f, 0);

    // 5. tensor-core causal attention -> a3_conc
    attn_mma_kernel<<<dim3(S_ / 64, B_ * NH_), 128, ATT_SMEM>>>(
        qkv, qkv + 1024, qkv + 2048, a3_conc);

    // 6. x_multi = conc @ p_d_c
    run_gemm256(a3_conc, w3_c, nullptr, xmulti, nullptr, M4, H_, 3 * H_, 1.f, 0);

    // 7. x_self = layer_in + LN(x_multi)  (+ fused split)
    ln_res_kernel<<<M4, 256>>>(layerin, xmulti,
                               b_d_bias_1 + (size_t)m * H_,
                               b_d_scale_1 + (size_t)m * H_, xself, a3_self, 0);

    // 8. FFN (both legs on 256-tiles)
    run_gemm256(a3_self, w3_ff1, b_d_ff1 + (size_t)m * FF_, nullptr, a3_ffw1,
                M4, FF_, 3 * H_, 1.f, 1);
    run_gemm256(a3_ffw1, w3_ff2, b_d_ff2 + (size_t)m * H_, ffw2, nullptr,
                M4, H_, 3 * FF_, 1.f, 0);

    // 9. x_ffw = x_self + LN(ffw2)
    ln_res_kernel<<<M4, 256>>>(xself, ffw2,
                               b_d_bias_2 + (size_t)m * H_,
                               b_d_scale_2 + (size_t)m * H_, xffw, nullptr, 0);

    // 10. dec_outputs = x_dec_embed + LN(x_ffw), RNA-tf32-rounded fp32
    ln_res_kernel<<<M4, 256>>>(xemb, xffw, d_o_bias, d_o_scale, decout, nullptr, 1);

    // 11. logits = dec_outputs @ p_decoder  (tf32 tcgen05)
    run_gemm256tf(decout, wtp, out, M4, V_, H_);
}

// round 11
// speedup vs baseline: 1.0510x; 1.0510x over previous
#include <cuda_runtime.h>
#include <cuda_bf16.h>
#include <cstdint>

// Problem constants
#define L_   12
#define NH_  16
#define H_   1024
#define FF_  4096
#define V_   32000
#define S_   1024
#define E_   128
#define B_   4
#define HEAD_ 64
#define M4   (B_ * S_)   // 4096 rows total
#define QKVS 3072        // fused qkv row stride (floats)

// Arch-feature dispatch: tcgen05 only legal in the sm_103a pass.
#if defined(__CUDA_ARCH__) && defined(__CUDA_ARCH_FEAT_SM103_ALL)
#define TC_PATH 1
#else
#define TC_PATH 0
#endif

// ---------------------------------------------------------------------------
// Scratch (device globals — allocation-free per harness rules)
// ---------------------------------------------------------------------------
__device__ float g_xemb   [M4 * H_];
__device__ float g_layerin[M4 * H_];
__device__ float g_qkv    [M4 * QKVS];
__device__ float g_xmulti [M4 * H_];
__device__ float g_xself  [M4 * H_];
__device__ float g_ffw1   [M4 * FF_];
__device__ float g_ffw2   [M4 * H_];
__device__ float g_xffw   [M4 * H_];
__device__ float g_decout [M4 * H_];   // RNA-tf32-rounded fp32 (feeds logits GEMM)

// bf16 split-K3 operand buffers.  A' = [hi | lo | hi] (row-major, 3K cols),
// B' = [hi | hi | lo] as [N, 3K] (k-contiguous, i.e. transposed weight).
__device__ __align__(128) __nv_bfloat16 g_a3_emb [M4 * 3 * E_];
__device__ __align__(128) __nv_bfloat16 g_a3_li  [M4 * 3 * H_];
__device__ __align__(128) __nv_bfloat16 g_a3_conc[M4 * 3 * H_];
__device__ __align__(128) __nv_bfloat16 g_a3_self[M4 * 3 * H_];
__device__ __align__(128) __nv_bfloat16 g_a3_ffw1[(size_t)M4 * 3 * FF_];

__device__ __align__(128) __nv_bfloat16 g_w3_dec [H_ * 3 * E_];
__device__ __align__(128) __nv_bfloat16 g_w3_qkv [(size_t)QKVS * 3 * H_];
__device__ __align__(128) __nv_bfloat16 g_w3_c   [H_ * 3 * H_];
__device__ __align__(128) __nv_bfloat16 g_w3_ff1 [(size_t)FF_ * 3 * H_];
__device__ __align__(128) __nv_bfloat16 g_w3_ff2 [(size_t)H_ * 3 * FF_];
// p_decoder transposed, RNA-tf32-rounded fp32  [V, H]
__device__ __align__(128) float g_wtp [(size_t)V_ * H_];

// ---------------------------------------------------------------------------
// PTX helpers — baseline-legal
// ---------------------------------------------------------------------------
__device__ __forceinline__ uint32_t smem_u32(const void* p) {
    uint32_t a;
    asm("{ .reg .u64 t; cvta.to.shared.u64 t, %1; cvt.u32.u64 %0, t; }"
        : "=r"(a) : "l"(p));
    return a;
}
__device__ __forceinline__ void cp16(uint32_t dst, const void* src) {
    asm volatile("cp.async.cg.shared.global [%0], [%1], 16;"
                 :: "r"(dst), "l"(src) : "memory");
}
__device__ __forceinline__ void cp_commit() {
    asm volatile("cp.async.commit_group;" ::: "memory");
}
template <int N>
__device__ __forceinline__ void cp_wait() {
    asm volatile("cp.async.wait_group %0;" :: "n"(N) : "memory");
}
__device__ __forceinline__ uint32_t elect_one_pred() {
    uint32_t pred;
    asm volatile(
        "{\n\t.reg .pred p;\n\telect.sync _|p, 0xFFFFFFFF;\n\t"
        "selp.b32 %0, 1, 0, p;\n\t}" : "=r"(pred));
    return pred;
}
// legacy m16n8k16 bf16 MMA, fp32 accumulate (sm_80+)
__device__ __forceinline__ void mma16(float* d, const uint32_t* a, const uint32_t* b) {
    asm volatile(
        "mma.sync.aligned.m16n8k16.row.col.f32.bf16.bf16.f32 "
        "{%0,%1,%2,%3}, {%4,%5,%6,%7}, {%8,%9}, {%0,%1,%2,%3};"
        : "+f"(d[0]), "+f"(d[1]), "+f"(d[2]), "+f"(d[3])
        : "r"(a[0]), "r"(a[1]), "r"(a[2]), "r"(a[3]),
          "r"(b[0]), "r"(b[1]));
}
__device__ __forceinline__ uint32_t pack_bf16x2(float lo_elem, float hi_elem) {
    uint32_t r;
    asm("cvt.rn.bf16x2.f32 %0, %1, %2;" : "=r"(r) : "f"(hi_elem), "f"(lo_elem));
    return r;
}
__device__ __forceinline__ uint32_t pack_raw(__nv_bfloat16 lo, __nv_bfloat16 hi) {
    return (uint32_t)__bfloat16_as_ushort(lo) | ((uint32_t)__bfloat16_as_ushort(hi) << 16);
}
// RNA round fp32 -> tf32 (bit pattern stays a valid fp32)
__device__ __forceinline__ float rna_tf32(float v) {
    uint32_t r;
    asm("cvt.rna.tf32.f32 %0, %1;" : "=r"(r) : "f"(v));
    return __uint_as_float(r);
}

#define SMEM_SWIZZLE_128B(o) ((o) ^ (((o) >> 3) & 0x70))

#if TC_PATH
// ---- tcgen05 helpers (only compiled in the sm_103a pass) ----
#define TCGEN05_ALLOC(smem_addr, nCols) \
    asm volatile("tcgen05.alloc.cta_group::1.sync.aligned.shared::cta.b32 [%0], %1;" \
                 :: "r"((uint32_t)(smem_addr)), "r"((uint32_t)(nCols)) : "memory")
#define TCGEN05_DEALLOC(tmem_addr, nCols) \
    asm volatile("tcgen05.dealloc.cta_group::1.sync.aligned.b32 %0, %1;" \
                 :: "r"(tmem_addr), "r"((uint32_t)(nCols)))
#define TCGEN05_RELINQUISH() \
    asm volatile("tcgen05.relinquish_alloc_permit.cta_group::1.sync.aligned;")
#define TCGEN05_COMMIT(mbar) \
    asm volatile("tcgen05.commit.cta_group::1.mbarrier::arrive::one.shared::cluster.b64 [%0];" \
                 :: "r"((uint32_t)(mbar)) : "memory")
#define TCGEN05_FENCE_AFTER() \
    asm volatile("tcgen05.fence::after_thread_sync;" ::: "memory")
#define TCGEN05_FENCE_BEFORE() \
    asm volatile("tcgen05.fence::before_thread_sync;" ::: "memory")
#define TCGEN05_WAIT_LD() \
    asm volatile("tcgen05.wait::ld.sync.aligned;" ::: "memory")
#define MBARRIER_INIT(mbar, cnt) \
    asm volatile("mbarrier.init.shared.b64 [%0], %1;" \
                 :: "r"((uint32_t)(mbar)), "r"((uint32_t)(cnt)) : "memory")
#define MBARRIER_INVAL(mbar) \
    asm volatile("mbarrier.inval.shared.b64 [%0];" :: "r"((uint32_t)(mbar)) : "memory")
#define FENCE_PROXY_ASYNC() \
    asm volatile("fence.proxy.async.shared::cta;" ::: "memory")

#define MBARRIER_WAIT_PARITY(mbar_smem_addr, phase_parity) do { \
    uint32_t _mbar = (uint32_t)(mbar_smem_addr); \
    uint32_t _parity = (uint32_t)(phase_parity); \
    uint32_t _done; \
    asm volatile("{\n\t.reg .pred p;\n\t" \
        "mbarrier.try_wait.parity.acquire.cta.shared::cta.b64 p, [%1], %2;\n\t" \
        "selp.b32 %0, 1, 0, p;\n\t}" \
        : "=r"(_done) : "r"(_mbar), "r"(_parity) : "memory"); \
    if (!_done) { \
        asm volatile("{\n\t.reg .pred P1;\n\t" \
            "WAIT_LOOP_%=:\n\t" \
            "mbarrier.try_wait.parity.acquire.cta.shared::cta.b64 P1, [%0], %1, 0x989680;\n\t" \
            "@P1 bra.uni WAIT_DONE_%=;\n\t" \
            "bra.uni WAIT_LOOP_%=;\n\t" \
            "WAIT_DONE_%=:\n\t}" \
            :: "r"(_mbar), "r"(_parity) : "memory"); \
    } \
} while(0)

#define TCGEN05_LD_32X32B_X32(r, tmem_addr) \
    asm volatile( \
        "tcgen05.ld.sync.aligned.32x32b.x32.b32 " \
        "{%0, %1, %2, %3, %4, %5, %6, %7, " \
        " %8, %9, %10, %11, %12, %13, %14, %15, " \
        " %16, %17, %18, %19, %20, %21, %22, %23, " \
        " %24, %25, %26, %27, %28, %29, %30, %31}, [%32];" \
        : "=r"((r)[0]),  "=r"((r)[1]),  "=r"((r)[2]),  "=r"((r)[3]), \
          "=r"((r)[4]),  "=r"((r)[5]),  "=r"((r)[6]),  "=r"((r)[7]), \
          "=r"((r)[8]),  "=r"((r)[9]),  "=r"((r)[10]), "=r"((r)[11]), \
          "=r"((r)[12]), "=r"((r)[13]), "=r"((r)[14]), "=r"((r)[15]), \
          "=r"((r)[16]), "=r"((r)[17]), "=r"((r)[18]), "=r"((r)[19]), \
          "=r"((r)[20]), "=r"((r)[21]), "=r"((r)[22]), "=r"((r)[23]), \
          "=r"((r)[24]), "=r"((r)[25]), "=r"((r)[26]), "=r"((r)[27]), \
          "=r"((r)[28]), "=r"((r)[29]), "=r"((r)[30]), "=r"((r)[31]) \
        : "r"(tmem_addr))

static constexpr uint64_t SMEM_DESC_BASE_SW128 =
    (uint64_t(2) << 61) | (uint64_t(1) << 46) | (uint64_t(64) << 32) | (uint64_t(1) << 16);
#define MAKE_SMEM_DESC(addr) (SMEM_DESC_BASE_SW128 | ((uint64_t)((addr) >> 4) & 0x3FFF))

__device__ __forceinline__ void mma_bf16_ss(uint32_t d_tmem, uint64_t a_desc,
                                            uint64_t b_desc, uint32_t idesc,
                                            uint32_t enable_d) {
    uint32_t z = 0;
    asm volatile(
        "{\n\t.reg .pred p;\n\tsetp.ne.u32 p, %5, 0;\n\t"
        "tcgen05.mma.cta_group::1.kind::f16 [%0], %1, %2, %3, {%4, %4, %4, %4}, p;\n\t}"
        :: "r"(d_tmem), "l"(a_desc), "l"(b_desc), "r"(idesc), "r"(z), "r"(enable_d)
        : "memory");
}
__device__ __forceinline__ void mma_tf32_ss(uint32_t d_tmem, uint64_t a_desc,
                                            uint64_t b_desc, uint32_t idesc,
                                            uint32_t enable_d) {
    uint32_t z = 0;
    asm volatile(
        "{\n\t.reg .pred p;\n\tsetp.ne.u32 p, %5, 0;\n\t"
        "tcgen05.mma.cta_group::1.kind::tf32 [%0], %1, %2, %3, {%4, %4, %4, %4}, p;\n\t}"
        :: "r"(d_tmem), "l"(a_desc), "l"(b_desc), "r"(idesc), "r"(z), "r"(enable_d)
        : "memory");
}
#endif // TC_PATH

// ---------------------------------------------------------------------------
// Shared epilogue value transform
// ---------------------------------------------------------------------------
__device__ __forceinline__ void store_split3(__nv_bfloat16* op, int N,
                                             float v0, float v1) {
    __nv_bfloat16 h0 = __float2bfloat16_rn(v0);
    __nv_bfloat16 h1 = __float2bfloat16_rn(v1);
    uint32_t hp = pack_raw(h0, h1);
    uint32_t lp = pack_bf16x2(v0 - __bfloat162float(h0), v1 - __bfloat162float(h1));
    *reinterpret_cast<uint32_t*>(op) = hp;
    *reinterpret_cast<uint32_t*>(op + N) = lp;
    *reinterpret_cast<uint32_t*>(op + 2 * N) = hp;
}

// ---------------------------------------------------------------------------
// Legacy HMMA 128x128 tile (compute_103 fallback only)
// ---------------------------------------------------------------------------
#define GBM 128
#define GBN 128
#define GBK 64
#define RSTRIDE 36
#define ABUF (128 * RSTRIDE)
#define BBUF (128 * RSTRIDE)
#define GEMM_SMEM_BYTES 99328

#if !TC_PATH
__device__ void legacy_tile128(
    const __nv_bfloat16* __restrict__ A3, const __nv_bfloat16* __restrict__ B3,
    const float* __restrict__ bias, float* __restrict__ C,
    __nv_bfloat16* __restrict__ out3,
    int N, int K3, float alpha, int do_relu,
    int m0, int n0, uint32_t* sm, uint32_t smb)
{
    const int tid = threadIdx.x;
    const int wid = tid >> 5, lane = tid & 31;
    const int g = lane >> 2, c4 = lane & 3;
    const int warp_m = wid >> 2;
    const int warp_n = wid & 3;

    const int srow = tid >> 1, spart = tid & 1;
    const __nv_bfloat16* aptr = A3 + (size_t)(m0 + srow) * K3 + spart * 32;
    const __nv_bfloat16* bptr = B3 + (size_t)(n0 + srow) * K3 + spart * 32;
    const uint32_t as_base = smb + (srow * RSTRIDE + spart * 16) * 4;
    const uint32_t bs_base = smb + (2 * ABUF + srow * RSTRIDE + spart * 16) * 4;

    const int NC = K3 / GBK;

    float acc[4][4][4];
    #pragma unroll
    for (int i = 0; i < 4; i++)
        #pragma unroll
        for (int j = 0; j < 4; j++)
            #pragma unroll
            for (int q = 0; q < 4; q++) acc[i][j][q] = 0.f;

    #pragma unroll
    for (int q = 0; q < 4; q++) cp16(as_base + q * 16, aptr + q * 8);
    #pragma unroll
    for (int q = 0; q < 4; q++) cp16(bs_base + q * 16, bptr + q * 8);
    cp_commit();

    for (int c = 0; c < NC; c++) {
        if (c + 1 < NC) {
            const int nb = (c + 1) & 1;
            const __nv_bfloat16* ap = aptr + (c + 1) * GBK;
            const __nv_bfloat16* bp = bptr + (c + 1) * GBK;
            #pragma unroll
            for (int q = 0; q < 4; q++)
                cp16(as_base + nb * ABUF * 4 + q * 16, ap + q * 8);
            #pragma unroll
            for (int q = 0; q < 4; q++)
                cp16(bs_base + nb * BBUF * 4 + q * 16, bp + q * 8);
            cp_commit();
            cp_wait<1>();
        } else {
            cp_wait<0>();
        }
        __syncthreads();

        const uint32_t* ab = sm + (c & 1) * ABUF;
        const uint32_t* bb = sm + 2 * ABUF + (c & 1) * BBUF;

        #pragma unroll
        for (int ks = 0; ks < 4; ks++) {
            const int kb = ks * 8;
            uint32_t af[4][4], bf[4][2];
            #pragma unroll
            for (int i = 0; i < 4; i++) {
                const uint32_t* p = ab + (warp_m * 64 + i * 16 + g) * RSTRIDE + kb + c4;
                af[i][0] = p[0];
                af[i][1] = p[8 * RSTRIDE];
                af[i][2] = p[4];
                af[i][3] = p[8 * RSTRIDE + 4];
            }
            #pragma unroll
            for (int j = 0; j < 4; j++) {
                const uint32_t* p = bb + (warp_n * 32 + j * 8 + g) * RSTRIDE + kb + c4;
                bf[j][0] = p[0];
                bf[j][1] = p[4];
            }
            #pragma unroll
            for (int i = 0; i < 4; i++)
                #pragma unroll
                for (int j = 0; j < 4; j++)
                    mma16(acc[i][j], af[i], bf[j]);
        }
        __syncthreads();
    }

    #pragma unroll
    for (int i = 0; i < 4; i++) {
        #pragma unroll
        for (int j = 0; j < 4; j++) {
            const int col = n0 + warp_n * 32 + j * 8 + c4 * 2;
            float b0v = 0.f, b1v = 0.f;
            if (bias) { b0v = bias[col]; b1v = bias[col + 1]; }
            float v0 = acc[i][j][0] * alpha + b0v;
            float v1 = acc[i][j][1] * alpha + b1v;
            float v2 = acc[i][j][2] * alpha + b0v;
            float v3 = acc[i][j][3] * alpha + b1v;
            if (do_relu) {
                v0 = fmaxf(v0, 0.f); v1 = fmaxf(v1, 0.f);
                v2 = fmaxf(v2, 0.f); v3 = fmaxf(v3, 0.f);
            }
            const int ra = m0 + warp_m * 64 + i * 16 + g;
            if (out3) {
                store_split3(out3 + (size_t)ra * 3 * N + col, N, v0, v1);
                store_split3(out3 + (size_t)(ra + 8) * 3 * N + col, N, v2, v3);
            } else {
                float2 lo = {v0, v1}, hi = {v2, v3};
                *reinterpret_cast<float2*>(C + (size_t)ra * N + col) = lo;
                *reinterpret_cast<float2*>(C + (size_t)(ra + 8) * N + col) = hi;
            }
        }
    }
}
#endif // !TC_PATH

// ---------------------------------------------------------------------------
// 128x128 bf16-split GEMM (N=1024 cases; 2 CTAs/SM)
// ---------------------------------------------------------------------------
__global__ __launch_bounds__(256, 2) void gemm_bf16_kernel(
    const __nv_bfloat16* __restrict__ A3, const __nv_bfloat16* __restrict__ B3,
    const float* __restrict__ bias, float* __restrict__ C,
    __nv_bfloat16* __restrict__ out3,
    int M, int N, int K3, float alpha, int do_relu)
{
#if TC_PATH
    extern __shared__ char smc[];
    const uint32_t smb = smem_u32(smc);
    const int tid = threadIdx.x;
    const int wid = tid >> 5, lane = tid & 31;
    const int m0 = blockIdx.x * GBM;
    const int n0 = blockIdx.y * GBN;

    const uint32_t sa[3] = {1024u, 1024u + 16384u, 1024u + 32768u};
    const uint32_t sb[3] = {1024u + 49152u, 1024u + 65536u, 1024u + 81920u};
    const uint32_t mb[3] = {smb + 8u, smb + 16u, smb + 24u};

    if (wid == 0) TCGEN05_ALLOC(smb, 128);
    if (tid == 0) { MBARRIER_INIT(mb[0], 1); MBARRIER_INIT(mb[1], 1); MBARRIER_INIT(mb[2], 1); }
    __syncthreads();
    uint32_t tmem;
    asm volatile("ld.shared.b32 %0, [%1];" : "=r"(tmem) : "r"(smb));
    if (wid == 0) TCGEN05_RELINQUISH();

    const uint32_t IDESC =
        (1u << 4) | (1u << 7) | (1u << 10) | ((GBN / 8) << 17) | ((GBM / 16) << 24);

    const int NC = K3 / GBK;
    const int r0s = tid >> 3;
    const int c8 = tid & 7;
    const __nv_bfloat16* abase = A3 + (size_t)(m0 + r0s) * K3 + c8 * 8;
    const __nv_bfloat16* bbase = B3 + (size_t)(n0 + r0s) * K3 + c8 * 8;
    const uint32_t swoff[4] = {
        SMEM_SWIZZLE_128B((uint32_t)((r0s +  0) * 128 + c8 * 16)),
        SMEM_SWIZZLE_128B((uint32_t)((r0s + 32) * 128 + c8 * 16)),
        SMEM_SWIZZLE_128B((uint32_t)((r0s + 64) * 128 + c8 * 16)),
        SMEM_SWIZZLE_128B((uint32_t)((r0s + 96) * 128 + c8 * 16))};

    auto stage_chunk = [&](int chunk, int buf) {
        #pragma unroll
        for (int it = 0; it < 4; it++) {
            cp16(smb + sa[buf] + swoff[it], abase + (size_t)it * 32 * K3 + chunk * GBK);
            cp16(smb + sb[buf] + swoff[it], bbase + (size_t)it * 32 * K3 + chunk * GBK);
        }
        cp_commit();
    };

    int ph[3] = {0, 0, 0};
    stage_chunk(0, 0);
    stage_chunk(1, 1);

    for (int c = 0; c < NC; c++) {
        const int b = c % 3;
        if (c + 2 < NC) {
            const int nb = (c + 2) % 3;
            if (c >= 1) { MBARRIER_WAIT_PARITY(mb[nb], ph[nb]); ph[nb] ^= 1; }
            stage_chunk(c + 2, nb);
            cp_wait<2>();
        } else if (c + 1 < NC) {
            cp_wait<1>();
        } else {
            cp_wait<0>();
        }
        __syncthreads();
        if (wid == 0 && elect_one_pred()) {
            FENCE_PROXY_ASYNC();
            const uint64_t ad = MAKE_SMEM_DESC(smb + sa[b]);
            const uint64_t bd = MAKE_SMEM_DESC(smb + sb[b]);
            #pragma unroll
            for (int ks = 0; ks < 4; ks++)
                mma_bf16_ss(tmem, ad + ks * 2, bd + ks * 2, IDESC,
                            (c > 0 || ks > 0) ? 1u : 0u);
            TCGEN05_COMMIT(mb[b]);
        }
    }
    MBARRIER_WAIT_PARITY(mb[(NC - 1) % 3], ph[(NC - 1) % 3]);
    TCGEN05_FENCE_AFTER();

    if (wid < 4) {
        const uint32_t lofs = (uint32_t)wid << 21;
        const int row = m0 + wid * 32 + lane;
        #pragma unroll
        for (int j = 0; j < 4; j++) {
            uint32_t r[32];
            TCGEN05_LD_32X32B_X32(r, tmem + j * 32 + lofs);
            TCGEN05_WAIT_LD();
            const float* bp = bias ? (bias + n0 + j * 32) : nullptr;
            if (out3) {
                __nv_bfloat16* op = out3 + (size_t)row * 3 * N + n0 + j * 32;
                #pragma unroll
                for (int q = 0; q < 32; q += 2) {
                    float v0 = __uint_as_float(r[q + 0]) * alpha;
                    float v1 = __uint_as_float(r[q + 1]) * alpha;
                    if (bp) { v0 += bp[q]; v1 += bp[q + 1]; }
                    if (do_relu) { v0 = fmaxf(v0, 0.f); v1 = fmaxf(v1, 0.f); }
                    store_split3(op + q, N, v0, v1);
                }
            } else {
                float* cp = C + (size_t)row * N + n0 + j * 32;
                #pragma unroll
                for (int q = 0; q < 32; q += 4) {
                    float v0 = __uint_as_float(r[q + 0]) * alpha;
                    float v1 = __uint_as_float(r[q + 1]) * alpha;
                    float v2 = __uint_as_float(r[q + 2]) * alpha;
                    float v3 = __uint_as_float(r[q + 3]) * alpha;
                    if (bp) { v0 += bp[q]; v1 += bp[q + 1]; v2 += bp[q + 2]; v3 += bp[q + 3]; }
                    if (do_relu) {
                        v0 = fmaxf(v0, 0.f); v1 = fmaxf(v1, 0.f);
                        v2 = fmaxf(v2, 0.f); v3 = fmaxf(v3, 0.f);
                    }
                    float4 o = {v0, v1, v2, v3};
                    *reinterpret_cast<float4*>(cp + q) = o;
                }
            }
        }
        TCGEN05_FENCE_BEFORE();
    }
    __syncthreads();
    if (tid == 0) { MBARRIER_INVAL(mb[0]); MBARRIER_INVAL(mb[1]); MBARRIER_INVAL(mb[2]); }
    __syncthreads();
    if (wid == 0) TCGEN05_DEALLOC(tmem, 128);
#else
    extern __shared__ uint32_t sm[];
    const uint32_t smb = smem_u32(sm);
    legacy_tile128(A3, B3, bias, C, out3, N, K3, alpha, do_relu,
                   blockIdx.x * GBM, blockIdx.y * GBN, sm, smb);
#endif
}

// ---------------------------------------------------------------------------
// 256x256 bf16-split GEMM (big-N cases: QKV, ff1)
// ---------------------------------------------------------------------------
#define G2K 64
#define G2_SMEM (1024 + 3 * 65536)   // 197632 B

__global__ __launch_bounds__(256, 1) void gemm256_kernel(
    const __nv_bfloat16* __restrict__ A3, const __nv_bfloat16* __restrict__ B3,
    const float* __restrict__ bias, float* __restrict__ C,
    __nv_bfloat16* __restrict__ out3,
    int M, int N, int K3, float alpha, int do_relu)
{
#if TC_PATH
    extern __shared__ char smc[];
    const uint32_t smb = smem_u32(smc);
    const int tid = threadIdx.x;
    const int wid = tid >> 5, lane = tid & 31;
    const int m0 = blockIdx.x * 256;
    const int n0 = blockIdx.y * 256;

    const uint32_t mb[3] = {smb + 8u, smb + 16u, smb + 24u};

    if (wid == 0) TCGEN05_ALLOC(smb, 512);
    if (tid == 0) { MBARRIER_INIT(mb[0], 1); MBARRIER_INIT(mb[1], 1); MBARRIER_INIT(mb[2], 1); }
    __syncthreads();
    uint32_t tmem;
    asm volatile("ld.shared.b32 %0, [%1];" : "=r"(tmem) : "r"(smb));
    if (wid == 0) TCGEN05_RELINQUISH();

    const uint32_t IDESC2 =
        (1u << 4) | (1u << 7) | (1u << 10) | ((256 / 8) << 17) | ((128 / 16) << 24);

    const int NC = K3 / G2K;
    const int r0s = tid >> 3;
    const int c8 = tid & 7;
    const __nv_bfloat16* abase = A3 + (size_t)(m0 + r0s) * K3 + c8 * 8;
    const __nv_bfloat16* bbase = B3 + (size_t)(n0 + r0s) * K3 + c8 * 8;
    uint32_t swoff[8];
    #pragma unroll
    for (int it = 0; it < 8; it++)
        swoff[it] = SMEM_SWIZZLE_128B((uint32_t)((r0s + it * 32) * 128 + c8 * 16));

    auto stage_chunk = [&](int chunk, int buf) {
        const uint32_t sa = smb + 1024u + (uint32_t)buf * 65536u;
        const uint32_t sbo = sa + 32768u;
        #pragma unroll
        for (int it = 0; it < 8; it++) {
            cp16(sa + swoff[it], abase + (size_t)it * 32 * K3 + chunk * G2K);
            cp16(sbo + swoff[it], bbase + (size_t)it * 32 * K3 + chunk * G2K);
        }
        cp_commit();
    };

    int ph[3] = {0, 0, 0};
    stage_chunk(0, 0);
    stage_chunk(1, 1);

    for (int c = 0; c < NC; c++) {
        const int b = c % 3;
        if (c + 2 < NC) {
            const int nb = (c + 2) % 3;
            if (c >= 1) { MBARRIER_WAIT_PARITY(mb[nb], ph[nb]); ph[nb] ^= 1; }
            stage_chunk(c + 2, nb);
            cp_wait<2>();
        } else if (c + 1 < NC) {
            cp_wait<1>();
        } else {
            cp_wait<0>();
        }
        __syncthreads();
        if (wid == 0 && elect_one_pred()) {
            FENCE_PROXY_ASYNC();
            const uint32_t sa = smb + 1024u + (uint32_t)b * 65536u;
            const uint64_t ad = MAKE_SMEM_DESC(sa);
            const uint64_t bd = MAKE_SMEM_DESC(sa + 32768u);
            #pragma unroll
            for (int ks = 0; ks < 4; ks++) {
                const uint32_t en = (c > 0 || ks > 0) ? 1u : 0u;
                mma_bf16_ss(tmem,       ad + ks * 2,        bd + ks * 2, IDESC2, en);
                mma_bf16_ss(tmem + 256, ad + 1024 + ks * 2, bd + ks * 2, IDESC2, en);
            }
            TCGEN05_COMMIT(mb[b]);
        }
    }
    MBARRIER_WAIT_PARITY(mb[(NC - 1) % 3], ph[(NC - 1) % 3]);
    TCGEN05_FENCE_AFTER();

    {
        const int mh = wid >> 2;
        const int w4 = wid & 3;
        const uint32_t lofs = (uint32_t)w4 << 21;
        const int row = m0 + mh * 128 + w4 * 32 + lane;
        #pragma unroll
        for (int j = 0; j < 8; j++) {
            uint32_t r[32];
            TCGEN05_LD_32X32B_X32(r, tmem + mh * 256 + j * 32 + lofs);
            TCGEN05_WAIT_LD();
            const float* bp = bias ? (bias + n0 + j * 32) : nullptr;
            if (out3) {
                __nv_bfloat16* op = out3 + (size_t)row * 3 * N + n0 + j * 32;
                #pragma unroll
                for (int q = 0; q < 32; q += 2) {
                    float v0 = __uint_as_float(r[q + 0]) * alpha;
                    float v1 = __uint_as_float(r[q + 1]) * alpha;
                    if (bp) { v0 += bp[q]; v1 += bp[q + 1]; }
                    if (do_relu) { v0 = fmaxf(v0, 0.f); v1 = fmaxf(v1, 0.f); }
                    store_split3(op + q, N, v0, v1);
                }
            } else {
                float* cp = C + (size_t)row * N + n0 + j * 32;
                #pragma unroll
                for (int q = 0; q < 32; q += 4) {
                    float v0 = __uint_as_float(r[q + 0]) * alpha;
                    float v1 = __uint_as_float(r[q + 1]) * alpha;
                    float v2 = __uint_as_float(r[q + 2]) * alpha;
                    float v3 = __uint_as_float(r[q + 3]) * alpha;
                    if (bp) { v0 += bp[q]; v1 += bp[q + 1]; v2 += bp[q + 2]; v3 += bp[q + 3]; }
                    if (do_relu) {
                        v0 = fmaxf(v0, 0.f); v1 = fmaxf(v1, 0.f);
                        v2 = fmaxf(v2, 0.f); v3 = fmaxf(v3, 0.f);
                    }
                    float4 o = {v0, v1, v2, v3};
                    *reinterpret_cast<float4*>(cp + q) = o;
                }
            }
        }
        TCGEN05_FENCE_BEFORE();
    }
    __syncthreads();
    if (tid == 0) { MBARRIER_INVAL(mb[0]); MBARRIER_INVAL(mb[1]); MBARRIER_INVAL(mb[2]); }
    __syncthreads();
    if (wid == 0) TCGEN05_DEALLOC(tmem, 512);
#else
    extern __shared__ uint32_t sm[];
    const uint32_t smb = smem_u32(sm);
    #pragma unroll
    for (int qm = 0; qm < 2; qm++)
        for (int qn = 0; qn < 2; qn++) {
            legacy_tile128(A3, B3, bias, C, out3, N, K3, alpha, do_relu,
                           blockIdx.x * 256 + qm * 128,
                           blockIdx.y * 256 + qn * 128, sm, smb);
            __syncthreads();
        }
#endif
}

// ---------------------------------------------------------------------------
// 256x256 tf32 GEMM (logits only). A, B are RNA-tf32-rounded fp32.
// ---------------------------------------------------------------------------
__global__ __launch_bounds__(256, 1) void gemm256tf_kernel(
    const float* __restrict__ A, const float* __restrict__ Bm,
    float* __restrict__ C, int M, int N, int K)
{
#if TC_PATH
    extern __shared__ char smc[];
    const uint32_t smb = smem_u32(smc);
    const int tid = threadIdx.x;
    const int wid = tid >> 5, lane = tid & 31;
    const int m0 = blockIdx.x * 256;
    const int n0 = blockIdx.y * 256;

    const uint32_t mb[3] = {smb + 8u, smb + 16u, smb + 24u};

    if (wid == 0) TCGEN05_ALLOC(smb, 512);
    if (tid == 0) { MBARRIER_INIT(mb[0], 1); MBARRIER_INIT(mb[1], 1); MBARRIER_INIT(mb[2], 1); }
    __syncthreads();
    uint32_t tmem;
    asm volatile("ld.shared.b32 %0, [%1];" : "=r"(tmem) : "r"(smb));
    if (wid == 0) TCGEN05_RELINQUISH();

    const uint32_t IDESCT =
        (1u << 4) | (2u << 7) | (2u << 10) | ((256 / 8) << 17) | ((128 / 16) << 24);

    const int NC = K / 32;
    const int r0s = tid >> 3;
    const int c8 = tid & 7;
    const float* abase = A + (size_t)(m0 + r0s) * K + c8 * 4;
    const float* bbase = Bm + (size_t)(n0 + r0s) * K + c8 * 4;
    uint32_t swoff[8];
    #pragma unroll
    for (int it = 0; it < 8; it++)
        swoff[it] = SMEM_SWIZZLE_128B((uint32_t)((r0s + it * 32) * 128 + c8 * 16));

    auto stage_chunk = [&](int chunk, int buf) {
        const uint32_t sa = smb + 1024u + (uint32_t)buf * 65536u;
        const uint32_t sbo = sa + 32768u;
        #pragma unroll
        for (int it = 0; it < 8; it++) {
            cp16(sa + swoff[it], abase + (size_t)it * 32 * K + chunk * 32);
            cp16(sbo + swoff[it], bbase + (size_t)it * 32 * K + chunk * 32);
        }
        cp_commit();
    };

    int ph[3] = {0, 0, 0};
    stage_chunk(0, 0);
    stage_chunk(1, 1);

    for (int c = 0; c < NC; c++) {
        const int b = c % 3;
        if (c + 2 < NC) {
            const int nb = (c + 2) % 3;
            if (c >= 1) { MBARRIER_WAIT_PARITY(mb[nb], ph[nb]); ph[nb] ^= 1; }
            stage_chunk(c + 2, nb);
            cp_wait<2>();
        } else if (c + 1 < NC) {
            cp_wait<1>();
        } else {
            cp_wait<0>();
        }
        __syncthreads();
        if (wid == 0 && elect_one_pred()) {
            FENCE_PROXY_ASYNC();
            const uint32_t sa = smb + 1024u + (uint32_t)b * 65536u;
            const uint64_t ad = MAKE_SMEM_DESC(sa);
            const uint64_t bd = MAKE_SMEM_DESC(sa + 32768u);
            #pragma unroll
            for (int ks = 0; ks < 4; ks++) {
                const uint32_t en = (c > 0 || ks > 0) ? 1u : 0u;
                mma_tf32_ss(tmem,       ad + ks * 2,        bd + ks * 2, IDESCT, en);
                mma_tf32_ss(tmem + 256, ad + 1024 + ks * 2, bd + ks * 2, IDESCT, en);
            }
            TCGEN05_COMMIT(mb[b]);
        }
    }
    MBARRIER_WAIT_PARITY(mb[(NC - 1) % 3], ph[(NC - 1) % 3]);
    TCGEN05_FENCE_AFTER();

    {
        const int mh = wid >> 2;
        const int w4 = wid & 3;
        const uint32_t lofs = (uint32_t)w4 << 21;
        const int row = m0 + mh * 128 + w4 * 32 + lane;
        #pragma unroll
        for (int j = 0; j < 8; j++) {
            uint32_t r[32];
            TCGEN05_LD_32X32B_X32(r, tmem + mh * 256 + j * 32 + lofs);
            TCGEN05_WAIT_LD();
            float* cp = C + (size_t)row * N + n0 + j * 32;
            #pragma unroll
            for (int q = 0; q < 32; q += 4) {
                float4 o;
                o.x = __uint_as_float(r[q + 0]);
                o.y = __uint_as_float(r[q + 1]);
                o.z = __uint_as_float(r[q + 2]);
                o.w = __uint_as_float(r[q + 3]);
                *reinterpret_cast<float4*>(cp + q) = o;
            }
        }
        TCGEN05_FENCE_BEFORE();
    }
    __syncthreads();
    if (tid == 0) { MBARRIER_INVAL(mb[0]); MBARRIER_INVAL(mb[1]); MBARRIER_INVAL(mb[2]); }
    __syncthreads();
    if (wid == 0) TCGEN05_DEALLOC(tmem, 512);
#else
    // correctness-only fallback (never executes on sm_103a; operands pre-rounded)
    const int m0 = blockIdx.x * 256;
    const int n0 = blockIdx.y * 256;
    for (int idx = threadIdx.x; idx < 256 * 256; idx += 256) {
        const int i = idx >> 8, j = idx & 255;
        const float* a = A + (size_t)(m0 + i) * K;
        const float* b = Bm + (size_t)(n0 + j) * K;
        float s = 0.f;
        for (int k = 0; k < K; k++) s += a[k] * b[k];
        C[(size_t)(m0 + i) * N + n0 + j] = s;
    }
#endif
}

// ---------------------------------------------------------------------------
// Tensor-core split-bf16 causal flash attention (fused-QKV input, stride QKVS)
// ---------------------------------------------------------------------------
#define AT_STRIDE 136
#define ATT_SMEM  (3 * 64 * AT_STRIDE * 2)   // 52224 B

__global__ __launch_bounds__(128, 3) void attn_mma_kernel(
    const float* __restrict__ Q, const float* __restrict__ Kg,
    const float* __restrict__ Vg, __nv_bfloat16* __restrict__ conc3)
{
    extern __shared__ __nv_bfloat16 sh[];
    __nv_bfloat16* Qs = sh;
    __nv_bfloat16* Ks = sh + 64 * AT_STRIDE;
    __nv_bfloat16* Vs = sh + 128 * AT_STRIDE;

    const int qt = blockIdx.x;
    const int bh = blockIdx.y;
    const int b = bh >> 4, n = bh & 15;
    const int tid = threadIdx.x;
    const int wid = tid >> 5, lane = tid & 31;
    const int g = lane >> 2, c4 = lane & 3;

    {
        const int r = tid >> 1;
        const int dbase = (tid & 1) * 32;
        const float* qp = Q + ((size_t)(b * S_ + qt * 64 + r)) * QKVS + n * 64 + dbase;
        #pragma unroll
        for (int i = 0; i < 32; i += 4) {
            float4 f = *reinterpret_cast<const float4*>(qp + i);
            float vals[4] = {f.x, f.y, f.z, f.w};
            #pragma unroll
            for (int e = 0; e < 4; e++) {
                __nv_bfloat16 hi = __float2bfloat16_rn(vals[e]);
                Qs[r * AT_STRIDE + dbase + i + e] = hi;
                Qs[r * AT_STRIDE + 64 + dbase + i + e] =
                    __float2bfloat16_rn(vals[e] - __bfloat162float(hi));
            }
        }
    }

    const int row0 = wid * 16 + g;
    float m0 = -1e30f, m1 = -1e30f, l0 = 0.f, l1 = 0.f;
    float o[8][4];
    #pragma unroll
    for (int j = 0; j < 8; j++)
        #pragma unroll
        for (int q = 0; q < 4; q++) o[j][q] = 0.f;

    for (int kt = 0; kt <= qt; kt++) {
        __syncthreads();
        {
            const int r = tid >> 1;
            const int dbase = (tid & 1) * 32;
            const float* kp = Kg + ((size_t)(b * S_ + kt * 64 + r)) * QKVS + n * 64 + dbase;
            const float* vp = Vg + ((size_t)(b * S_ + kt * 64 + r)) * QKVS + n * 64 + dbase;
            #pragma unroll
            for (int i = 0; i < 32; i += 4) {
                float4 fk = *reinterpret_cast<const float4*>(kp + i);
                float4 fv = *reinterpret_cast<const float4*>(vp + i);
                float kv[4] = {fk.x, fk.y, fk.z, fk.w};
                float vv[4] = {fv.x, fv.y, fv.z, fv.w};
                #pragma unroll
                for (int e = 0; e < 4; e++) {
                    const int d = dbase + i + e;
                    __nv_bfloat16 kh = __float2bfloat16_rn(kv[e]);
                    Ks[r * AT_STRIDE + d] = kh;
                    Ks[r * AT_STRIDE + 64 + d] =
                        __float2bfloat16_rn(kv[e] - __bfloat162float(kh));
                    __nv_bfloat16 vh = __float2bfloat16_rn(vv[e]);
                    Vs[d * AT_STRIDE + r] = vh;
                    Vs[d * AT_STRIDE + 64 + r] =
                        __float2bfloat16_rn(vv[e] - __bfloat162float(vh));
                }
            }
        }
        __syncthreads();

        float s[8][4];
        #pragma unroll
        for (int j = 0; j < 8; j++)
            #pragma unroll
            for (int q = 0; q < 4; q++) s[j][q] = 0.f;

        #pragma unroll
        for (int phs = 0; phs < 3; phs++) {
            const int aoff = (phs == 1) ? 64 : 0;
            const int boff = (phs == 2) ? 64 : 0;
            #pragma unroll
            for (int ks = 0; ks < 4; ks++) {
                uint32_t a[4];
                const __nv_bfloat16* ap = Qs + row0 * AT_STRIDE + aoff + ks * 16 + c4 * 2;
                a[0] = *reinterpret_cast<const uint32_t*>(ap);
                a[1] = *reinterpret_cast<const uint32_t*>(ap + 8 * AT_STRIDE);
                a[2] = *reinterpret_cast<const uint32_t*>(ap + 8);
                a[3] = *reinterpret_cast<const uint32_t*>(ap + 8 * AT_STRIDE + 8);
                #pragma unroll
                for (int j = 0; j < 8; j++) {
                    uint32_t bf[2];
                    const __nv_bfloat16* bp =
                        Ks + (8 * j + g) * AT_STRIDE + boff + ks * 16 + c4 * 2;
                    bf[0] = *reinterpret_cast<const uint32_t*>(bp);
                    bf[1] = *reinterpret_cast<const uint32_t*>(bp + 8);
                    mma16(s[j], a, bf);
                }
            }
        }

        if (kt == qt) {
            #pragma unroll
            for (int j = 0; j < 8; j++) {
                const int colb = 8 * j + 2 * c4;
                if (colb     > row0)     s[j][0] = -1e30f;
                if (colb + 1 > row0)     s[j][1] = -1e30f;
                if (colb     > row0 + 8) s[j][2] = -1e30f;
                if (colb + 1 > row0 + 8) s[j][3] = -1e30f;
            }
        }

        float rm0 = -1e30f, rm1 = -1e30f;
        #pragma unroll
        for (int j = 0; j < 8; j++) {
            rm0 = fmaxf(rm0, fmaxf(s[j][0], s[j][1]));
            rm1 = fmaxf(rm1, fmaxf(s[j][2], s[j][3]));
        }
        rm0 = fmaxf(rm0, __shfl_xor_sync(0xFFFFFFFFu, rm0, 1));
        rm0 = fmaxf(rm0, __shfl_xor_sync(0xFFFFFFFFu, rm0, 2));
        rm1 = fmaxf(rm1, __shfl_xor_sync(0xFFFFFFFFu, rm1, 1));
        rm1 = fmaxf(rm1, __shfl_xor_sync(0xFFFFFFFFu, rm1, 2));
        const float mn0 = fmaxf(m0, rm0), mn1 = fmaxf(m1, rm1);
        const float cr0 = __expf(m0 - mn0), cr1 = __expf(m1 - mn1);
        m0 = mn0; m1 = mn1;

        float ps0 = 0.f, ps1 = 0.f;
        uint32_t phi[8][2], plo[8][2];
        #pragma unroll
        for (int j = 0; j < 8; j++) {
            float p0 = __expf(s[j][0] - mn0);
            float p1 = __expf(s[j][1] - mn0);
            float p2 = __expf(s[j][2] - mn1);
            float p3 = __expf(s[j][3] - mn1);
            ps0 += p0 + p1; ps1 += p2 + p3;
            __nv_bfloat16 h0 = __float2bfloat16_rn(p0), h1 = __float2bfloat16_rn(p1);
            __nv_bfloat16 h2 = __float2bfloat16_rn(p2), h3 = __float2bfloat16_rn(p3);
            phi[j][0] = pack_raw(h0, h1);
            phi[j][1] = pack_raw(h2, h3);
            plo[j][0] = pack_bf16x2(p0 - __bfloat162float(h0), p1 - __bfloat162float(h1));
            plo[j][1] = pack_bf16x2(p2 - __bfloat162float(h2), p3 - __bfloat162float(h3));
        }
        ps0 += __shfl_xor_sync(0xFFFFFFFFu, ps0, 1);
        ps0 += __shfl_xor_sync(0xFFFFFFFFu, ps0, 2);
        ps1 += __shfl_xor_sync(0xFFFFFFFFu, ps1, 1);
        ps1 += __shfl_xor_sync(0xFFFFFFFFu, ps1, 2);
        l0 = l0 * cr0 + ps0;
        l1 = l1 * cr1 + ps1;
        #pragma unroll
        for (int j = 0; j < 8; j++) {
            o[j][0] *= cr0; o[j][1] *= cr0;
            o[j][2] *= cr1; o[j][3] *= cr1;
        }

        #pragma unroll
        for (int phs = 0; phs < 3; phs++) {
            const int voff = (phs == 2) ? 64 : 0;
            #pragma unroll
            for (int ks = 0; ks < 4; ks++) {
                uint32_t a[4];
                if (phs == 1) {
                    a[0] = plo[2 * ks][0]; a[1] = plo[2 * ks][1];
                    a[2] = plo[2 * ks + 1][0]; a[3] = plo[2 * ks + 1][1];
                } else {
                    a[0] = phi[2 * ks][0]; a[1] = phi[2 * ks][1];
                    a[2] = phi[2 * ks + 1][0]; a[3] = phi[2 * ks + 1][1];
                }
                #pragma unroll
                for (int j = 0; j < 8; j++) {
                    uint32_t bf[2];
                    const __nv_bfloat16* bp =
                        Vs + (8 * j + g) * AT_STRIDE + voff + ks * 16 + c4 * 2;
                    bf[0] = *reinterpret_cast<const uint32_t*>(bp);
                    bf[1] = *reinterpret_cast<const uint32_t*>(bp + 8);
                    mma16(o[j], a, bf);
                }
            }
        }
    }

    const float inv0 = 1.f / l0, inv1 = 1.f / l1;
    const size_t r0 = (size_t)(b * S_ + qt * 64 + row0);
    __nv_bfloat16* o0 = conc3 + r0 * 3 * H_;
    __nv_bfloat16* o1 = conc3 + (r0 + 8) * 3 * H_;
    #pragma unroll
    for (int j = 0; j < 8; j++) {
        const int col = n * 64 + 8 * j + 2 * c4;
        store_split3(o0 + col, H_, o[j][0] * inv0, o[j][1] * inv0);
        store_split3(o1 + col, H_, o[j][2] * inv1, o[j][3] * inv1);
    }
}

// ---------------------------------------------------------------------------
// Conversion / elementwise kernels
// ---------------------------------------------------------------------------
// fused gather + split: A3_emb[i, :] from emb_decode[x[i], :]
__global__ void gather_split_kernel(const int* __restrict__ x,
                                    const float* __restrict__ emb,
                                    __nv_bfloat16* __restrict__ out3)
{
    int idx = blockIdx.x * blockDim.x + threadIdx.x;
    if (idx >= M4 * E_) return;
    int i = idx / E_;
    int e = idx - i * E_;
    float v = emb[(size_t)x[i] * E_ + e];
    __nv_bfloat16 hi = __float2bfloat16_rn(v);
    __nv_bfloat16 lo = __float2bfloat16_rn(v - __bfloat162float(hi));
    size_t base = (size_t)i * 3 * E_;
    out3[base + e] = hi;
    out3[base + E_ + e] = lo;
    out3[base + 2 * E_ + e] = hi;
}

__global__ __launch_bounds__(256) void conv_wT_kernel(
    const float* __restrict__ W, __nv_bfloat16* __restrict__ out,
    int K, int N, float wscale)
{
    __shared__ float tile[32][33];
    const int tx = threadIdx.x & 31;
    const int ty = threadIdx.x >> 5;
    const int n0 = blockIdx.x * 32;
    const int k0 = blockIdx.y * 32;
    #pragma unroll
    for (int i = 0; i < 4; i++)
        tile[ty + i * 8][tx] = W[(size_t)(k0 + ty + i * 8) * N + n0 + tx];
    __syncthreads();
    #pragma unroll
    for (int i = 0; i < 4; i++) {
        const int nn = n0 + ty + i * 8;
        const int k = k0 + tx;
        float x = tile[tx][ty + i * 8] * wscale;
        __nv_bfloat16 hi = __float2bfloat16_rn(x);
        __nv_bfloat16 lo = __float2bfloat16_rn(x - __bfloat162float(hi));
        size_t base = (size_t)nn * 3 * K;
        out[base + k] = hi;
        out[base + K + k] = hi;
        out[base + 2 * K + k] = lo;
    }
}

// transpose + RNA-tf32-round to fp32 (for p_decoder)
__global__ __launch_bounds__(256) void conv_wTf32_kernel(
    const float* __restrict__ W, float* __restrict__ out, int K, int N)
{
    __shared__ float tile[32][33];
    const int tx = threadIdx.x & 31;
    const int ty = threadIdx.x >> 5;
    const int n0 = blockIdx.x * 32;
    const int k0 = blockIdx.y * 32;
    #pragma unroll
    for (int i = 0; i < 4; i++)
        tile[ty + i * 8][tx] = W[(size_t)(k0 + ty + i * 8) * N + n0 + tx];
    __syncthreads();
    #pragma unroll
    for (int i = 0; i < 4; i++) {
        const int nn = n0 + ty + i * 8;
        out[(size_t)nn * K + k0 + tx] = rna_tf32(tile[tx][ty + i * 8]);
    }
}

__global__ void addpos_kernel(const float* __restrict__ xemb,
                              const float* __restrict__ pos11,
                              float* __restrict__ out,
                              __nv_bfloat16* __restrict__ out3)
{
    int idx = blockIdx.x * blockDim.x + threadIdx.x;
    if (idx >= M4 * H_) return;
    int i = idx / H_;
    int h = idx - i * H_;
    int s = i & (S_ - 1);
    float y = xemb[idx] + pos11[(size_t)s * H_ + h];
    out[idx] = y;
    __nv_bfloat16 hi = __float2bfloat16_rn(y);
    __nv_bfloat16 lo = __float2bfloat16_rn(y - __bfloat162float(hi));
    size_t base = (size_t)i * 3 * H_;
    out3[base + h] = hi;
    out3[base + H_ + h] = lo;
    out3[base + 2 * H_ + h] = hi;
}

__global__ __launch_bounds__(256) void ln_res_kernel(
    const float* __restrict__ res, const float* __restrict__ x,
    const float* __restrict__ bias, const float* __restrict__ scale,
    float* __restrict__ out, __nv_bfloat16* __restrict__ out3,
    int round_out)
{
    __shared__ float red[256];
    const int row = blockIdx.x;
    const int t = threadIdx.x;
    const float* xr = x + (size_t)row * H_;

    float lsum = 0.f;
    for (int i = t; i < H_; i += 256) lsum += xr[i];
    red[t] = lsum; __syncthreads();
    for (int s = 128; s > 0; s >>= 1) { if (t < s) red[t] += red[t + s]; __syncthreads(); }
    const float mean = red[0] * (1.0f / H_);
    __syncthreads();

    float lvar = 0.f;
    for (int i = t; i < H_; i += 256) { float d = xr[i] - mean; lvar += d * d; }
    red[t] = lvar; __syncthreads();
    for (int s = 128; s > 0; s >>= 1) { if (t < s) red[t] += red[t + s]; __syncthreads(); }
    const float rstd = rsqrtf(red[0] * (1.0f / H_) + 1e-6f);

    for (int i = t; i < H_; i += 256) {
        float y = res[(size_t)row * H_ + i] + (xr[i] - mean) * rstd * scale[i] + bias[i];
        out[(size_t)row * H_ + i] = round_out ? rna_tf32(y) : y;
        if (out3) {
            __nv_bfloat16 hi = __float2bfloat16_rn(y);
            __nv_bfloat16 lo = __float2bfloat16_rn(y - __bfloat162float(hi));
            size_t base = (size_t)row * 3 * H_;
            out3[base + i] = hi;
            out3[base + H_ + i] = lo;
            out3[base + 2 * H_ + i] = hi;
        }
    }
}

// ---------------------------------------------------------------------------
// Launch helpers
// ---------------------------------------------------------------------------
static inline void run_gemm(const __nv_bfloat16* A3, const __nv_bfloat16* B3,
                            const float* bias, float* C, __nv_bfloat16* out3,
                            int M, int N, int K3, float alpha, int relu)
{
    dim3 grid(M / GBM, N / GBN);
    gemm_bf16_kernel<<<grid, 256, GEMM_SMEM_BYTES>>>(A3, B3, bias, C, out3,
                                                     M, N, K3, alpha, relu);
}
static inline void run_gemm256(const __nv_bfloat16* A3, const __nv_bfloat16* B3,
                               const float* bias, float* C, __nv_bfloat16* out3,
                               int M, int N, int K3, float alpha, int relu)
{
    dim3 grid(M / 256, N / 256);
    gemm256_kernel<<<grid, 256, G2_SMEM>>>(A3, B3, bias, C, out3,
                                           M, N, K3, alpha, relu);
}
static inline void run_gemm256tf(const float* A, const float* Bm, float* C,
                                 int M, int N, int K)
{
    dim3 grid(M / 256, N / 256);
    gemm256tf_kernel<<<grid, 256, G2_SMEM>>>(A, Bm, C, M, N, K);
}
static inline void run_conv_wT(const float* W, __nv_bfloat16* out,
                               int K, int N, float wscale)
{
    dim3 grid(N / 32, K / 32);
    conv_wT_kernel<<<grid, 256>>>(W, out, K, N, wscale);
}

extern "C" void kernel_launch(void* const* d_in, const int* in_sizes, int n_in,
                              void* d_out, int out_size)
{
    const int*   x            = (const int*)  d_in[0];
    const float* emb_decode   = (const float*)d_in[1];
    const float* W_dec_lin    = (const float*)d_in[2];
    const float* p_decoder    = (const float*)d_in[3];
    const float* x_emb_pos    = (const float*)d_in[4];
    const float* p_d_q        = (const float*)d_in[5];
    const float* p_d_k        = (const float*)d_in[6];
    const float* p_d_v        = (const float*)d_in[7];
    const float* p_d_c        = (const float*)d_in[8];
    const float* p_d_ff1      = (const float*)d_in[9];
    const float* p_d_ff2      = (const float*)d_in[10];
    const float* b_d_ff1      = (const float*)d_in[11];
    const float* b_d_ff2      = (const float*)d_in[12];
    const float* d_o_bias     = (const float*)d_in[13];
    const float* d_o_scale    = (const float*)d_in[14];
    const float* b_d_bias_1   = (const float*)d_in[15];
    const float* b_d_bias_2   = (const float*)d_in[16];
    const float* b_d_scale_1  = (const float*)d_in[17];
    const float* b_d_scale_2  = (const float*)d_in[18];
    float* out = (float*)d_out;

    const int m = L_ - 1;   // only the last layer's result is observable

    cudaFuncSetAttribute(gemm_bf16_kernel,
                         cudaFuncAttributeMaxDynamicSharedMemorySize, GEMM_SMEM_BYTES);
    cudaFuncSetAttribute(gemm256_kernel,
                         cudaFuncAttributeMaxDynamicSharedMemorySize, G2_SMEM);
    cudaFuncSetAttribute(gemm256tf_kernel,
                         cudaFuncAttributeMaxDynamicSharedMemorySize, G2_SMEM);
    cudaFuncSetAttribute(attn_mma_kernel,
                         cudaFuncAttributeMaxDynamicSharedMemorySize, ATT_SMEM);

    float *xemb, *layerin, *qkv, *xmulti, *xself, *ffw1, *ffw2, *xffw, *decout, *wtp;
    __nv_bfloat16 *a3_emb, *a3_li, *a3_conc, *a3_self, *a3_ffw1;
    __nv_bfloat16 *w3_dec, *w3_qkv, *w3_c, *w3_ff1, *w3_ff2;
    cudaGetSymbolAddress((void**)&xemb,    g_xemb);
    cudaGetSymbolAddress((void**)&layerin, g_layerin);
    cudaGetSymbolAddress((void**)&qkv,     g_qkv);
    cudaGetSymbolAddress((void**)&xmulti,  g_xmulti);
    cudaGetSymbolAddress((void**)&xself,   g_xself);
    cudaGetSymbolAddress((void**)&ffw1,    g_ffw1);
    cudaGetSymbolAddress((void**)&ffw2,    g_ffw2);
    cudaGetSymbolAddress((void**)&xffw,    g_xffw);
    cudaGetSymbolAddress((void**)&decout,  g_decout);
    cudaGetSymbolAddress((void**)&wtp,     g_wtp);
    cudaGetSymbolAddress((void**)&a3_emb,  g_a3_emb);
    cudaGetSymbolAddress((void**)&a3_li,   g_a3_li);
    cudaGetSymbolAddress((void**)&a3_conc, g_a3_conc);
    cudaGetSymbolAddress((void**)&a3_self, g_a3_self);
    cudaGetSymbolAddress((void**)&a3_ffw1, g_a3_ffw1);
    cudaGetSymbolAddress((void**)&w3_dec,  g_w3_dec);
    cudaGetSymbolAddress((void**)&w3_qkv,  g_w3_qkv);
    cudaGetSymbolAddress((void**)&w3_c,    g_w3_c);
    cudaGetSymbolAddress((void**)&w3_ff1,  g_w3_ff1);
    cudaGetSymbolAddress((void**)&w3_ff2,  g_w3_ff2);

    // weight conversions; Q weights pre-scaled by 1/sqrt(head)
    run_conv_wT(W_dec_lin, w3_dec, E_, H_, 1.f);
    run_conv_wT(p_d_q + (size_t)m * H_ * H_, w3_qkv, H_, H_, 0.125f);
    run_conv_wT(p_d_k + (size_t)m * H_ * H_, w3_qkv + (size_t)1024 * 3 * H_, H_, H_, 1.f);
    run_conv_wT(p_d_v + (size_t)m * H_ * H_, w3_qkv + (size_t)2048 * 3 * H_, H_, H_, 1.f);
    run_conv_wT(p_d_c + (size_t)m * H_ * H_, w3_c, H_, H_, 1.f);
    run_conv_wT(p_d_ff1 + (size_t)m * H_ * FF_, w3_ff1, H_, FF_, 1.f);
    run_conv_wT(p_d_ff2 + (size_t)m * FF_ * H_, w3_ff2, FF_, H_, 1.f);
    {   // p_decoder -> transposed RNA-rounded fp32
        dim3 grid(V_ / 32, H_ / 32);
        conv_wTf32_kernel<<<grid, 256>>>(p_decoder, wtp, H_, V_);
    }

    // 1. gather embeddings + split (fused, no fp32 round-trip)
    gather_split_kernel<<<(M4 * E_ + 255) / 256, 256>>>(x, emb_decode, a3_emb);

    // 2. x_dec_embed = A_emb @ W_dec_lin   (128-tile: 256 CTAs, 2/SM)
    run_gemm(a3_emb, w3_dec, nullptr, xemb, nullptr, M4, H_, 3 * E_, 1.f, 0);

    // 3. layer_in = pos[11] + x_dec_embed  (+ fused split)
    addpos_kernel<<<(M4 * H_ + 255) / 256, 256>>>(
        xemb, x_emb_pos + (size_t)m * S_ * H_, layerin, a3_li);

    // 4. fused Q/K/V projection (256-tile: grid 16x12 = 192 CTAs)
    run_gemm256(a3_li, w3_qkv, nullptr, qkv, nullptr, M4, QKVS, 3 * H_, 1.f, 0);

    // 5. tensor-core causal attention -> a3_conc
    attn_mma_kernel<<<dim3(S_ / 64, B_ * NH_), 128, ATT_SMEM>>>(
        qkv, qkv + 1024, qkv + 2048, a3_conc);

    // 6. x_multi = conc @ p_d_c  (128-tile)
    run_gemm(a3_conc, w3_c, nullptr, xmulti, nullptr, M4, H_, 3 * H_, 1.f, 0);

    // 7. x_self = layer_in + LN(x_multi)  (+ fused split)
    ln_res_kernel<<<M4, 256>>>(layerin, xmulti,
                               b_d_bias_1 + (size_t)m * H_,
                               b_d_scale_1 + (size_t)m * H_, xself, a3_self, 0);

    // 8. FFN (ff1 on 256-tile: grid 16x16 = 256 CTAs; ff2 on 128-tile)
    run_gemm256(a3_self, w3_ff1, b_d_ff1 + (size_t)m * FF_, ffw1, a3_ffw1,
                M4, FF_, 3 * H_, 1.f, 1);
    run_gemm(a3_ffw1, w3_ff2, b_d_ff2 + (size_t)m * H_, ffw2, nullptr,
             M4, H_, 3 * FF_, 1.f, 0);

    // 9. x_ffw = x_self + LN(ffw2)
    ln_res_kernel<<<M4, 256>>>(xself, ffw2,
                               b_d_bias_2 + (size_t)m * H_,
                               b_d_scale_2 + (size_t)m * H_, xffw, nullptr, 0);

    // 10. dec_outputs = x_dec_embed + LN(x_ffw), RNA-tf32-rounded fp32
    ln_res_kernel<<<M4, 256>>>(xemb, xffw, d_o_bias, d_o_scale, decout, nullptr, 1);

    // 11. logits = dec_outputs @ p_decoder  (tf32 tcgen05, grid 16x125)
    run_gemm256tf(decout, wtp, out, M4, V_, H_);
}

// round 12
// speedup vs baseline: 1.0592x; 1.0078x over previous
#include <cuda_runtime.h>
#include <cuda_bf16.h>
#include <cstdint>

// Problem constants
#define L_   12
#define NH_  16
#define H_   1024
#define FF_  4096
#define V_   32000
#define S_   1024
#define E_   128
#define B_   4
#define HEAD_ 64
#define M4   (B_ * S_)   // 4096 rows total
#define QKVS 3072        // fused qkv row stride (floats)

// Arch-feature dispatch: tcgen05 only legal in the sm_103a pass.
#if defined(__CUDA_ARCH__) && defined(__CUDA_ARCH_FEAT_SM103_ALL)
#define TC_PATH 1
#else
#define TC_PATH 0
#endif

// ---------------------------------------------------------------------------
// Scratch (device globals — allocation-free per harness rules)
// ---------------------------------------------------------------------------
__device__ float g_xemb   [M4 * H_];
__device__ float g_layerin[M4 * H_];
__device__ float g_qkv    [M4 * QKVS];
__device__ float g_xmulti [M4 * H_];
__device__ float g_xself  [M4 * H_];
__device__ float g_ffw1   [M4 * FF_];
__device__ float g_ffw2   [M4 * H_];
__device__ float g_decout [M4 * H_];   // RNA-tf32-rounded fp32 (feeds logits GEMM)

// bf16 split-K3 operand buffers.  A' = [hi | lo | hi] (row-major, 3K cols),
// B' = [hi | hi | lo] as [N, 3K] (k-contiguous, i.e. transposed weight).
__device__ __align__(128) __nv_bfloat16 g_a3_emb [M4 * 3 * E_];
__device__ __align__(128) __nv_bfloat16 g_a3_li  [M4 * 3 * H_];
__device__ __align__(128) __nv_bfloat16 g_a3_conc[M4 * 3 * H_];
__device__ __align__(128) __nv_bfloat16 g_a3_self[M4 * 3 * H_];
__device__ __align__(128) __nv_bfloat16 g_a3_ffw1[(size_t)M4 * 3 * FF_];

__device__ __align__(128) __nv_bfloat16 g_w3_dec [H_ * 3 * E_];
__device__ __align__(128) __nv_bfloat16 g_w3_qkv [(size_t)QKVS * 3 * H_];
__device__ __align__(128) __nv_bfloat16 g_w3_c   [H_ * 3 * H_];
__device__ __align__(128) __nv_bfloat16 g_w3_ff1 [(size_t)FF_ * 3 * H_];
__device__ __align__(128) __nv_bfloat16 g_w3_ff2 [(size_t)H_ * 3 * FF_];
// p_decoder transposed, RNA-tf32-rounded fp32  [V, H]
__device__ __align__(128) float g_wtp [(size_t)V_ * H_];

// ---------------------------------------------------------------------------
// PTX helpers — baseline-legal
// ---------------------------------------------------------------------------
__device__ __forceinline__ uint32_t smem_u32(const void* p) {
    uint32_t a;
    asm("{ .reg .u64 t; cvta.to.shared.u64 t, %1; cvt.u32.u64 %0, t; }"
        : "=r"(a) : "l"(p));
    return a;
}
__device__ __forceinline__ void cp16(uint32_t dst, const void* src) {
    asm volatile("cp.async.cg.shared.global [%0], [%1], 16;"
                 :: "r"(dst), "l"(src) : "memory");
}
__device__ __forceinline__ void cp_commit() {
    asm volatile("cp.async.commit_group;" ::: "memory");
}
template <int N>
__device__ __forceinline__ void cp_wait() {
    asm volatile("cp.async.wait_group %0;" :: "n"(N) : "memory");
}
__device__ __forceinline__ uint32_t elect_one_pred() {
    uint32_t pred;
    asm volatile(
        "{\n\t.reg .pred p;\n\telect.sync _|p, 0xFFFFFFFF;\n\t"
        "selp.b32 %0, 1, 0, p;\n\t}" : "=r"(pred));
    return pred;
}
// legacy m16n8k16 bf16 MMA, fp32 accumulate (sm_80+)
__device__ __forceinline__ void mma16(float* d, const uint32_t* a, const uint32_t* b) {
    asm volatile(
        "mma.sync.aligned.m16n8k16.row.col.f32.bf16.bf16.f32 "
        "{%0,%1,%2,%3}, {%4,%5,%6,%7}, {%8,%9}, {%0,%1,%2,%3};"
        : "+f"(d[0]), "+f"(d[1]), "+f"(d[2]), "+f"(d[3])
        : "r"(a[0]), "r"(a[1]), "r"(a[2]), "r"(a[3]),
          "r"(b[0]), "r"(b[1]));
}
__device__ __forceinline__ uint32_t pack_bf16x2(float lo_elem, float hi_elem) {
    uint32_t r;
    asm("cvt.rn.bf16x2.f32 %0, %1, %2;" : "=r"(r) : "f"(hi_elem), "f"(lo_elem));
    return r;
}
__device__ __forceinline__ uint32_t pack_raw(__nv_bfloat16 lo, __nv_bfloat16 hi) {
    return (uint32_t)__bfloat16_as_ushort(lo) | ((uint32_t)__bfloat16_as_ushort(hi) << 16);
}
// RNA round fp32 -> tf32 (bit pattern stays a valid fp32)
__device__ __forceinline__ float rna_tf32(float v) {
    uint32_t r;
    asm("cvt.rna.tf32.f32 %0, %1;" : "=r"(r) : "f"(v));
    return __uint_as_float(r);
}

#define SMEM_SWIZZLE_128B(o) ((o) ^ (((o) >> 3) & 0x70))

#if TC_PATH
// ---- tcgen05 helpers (only compiled in the sm_103a pass) ----
#define TCGEN05_ALLOC(smem_addr, nCols) \
    asm volatile("tcgen05.alloc.cta_group::1.sync.aligned.shared::cta.b32 [%0], %1;" \
                 :: "r"((uint32_t)(smem_addr)), "r"((uint32_t)(nCols)) : "memory")
#define TCGEN05_DEALLOC(tmem_addr, nCols) \
    asm volatile("tcgen05.dealloc.cta_group::1.sync.aligned.b32 %0, %1;" \
                 :: "r"(tmem_addr), "r"((uint32_t)(nCols)))
#define TCGEN05_RELINQUISH() \
    asm volatile("tcgen05.relinquish_alloc_permit.cta_group::1.sync.aligned;")
#define TCGEN05_COMMIT(mbar) \
    asm volatile("tcgen05.commit.cta_group::1.mbarrier::arrive::one.shared::cluster.b64 [%0];" \
                 :: "r"((uint32_t)(mbar)) : "memory")
#define TCGEN05_FENCE_AFTER() \
    asm volatile("tcgen05.fence::after_thread_sync;" ::: "memory")
#define TCGEN05_FENCE_BEFORE() \
    asm volatile("tcgen05.fence::before_thread_sync;" ::: "memory")
#define TCGEN05_WAIT_LD() \
    asm volatile("tcgen05.wait::ld.sync.aligned;" ::: "memory")
#define MBARRIER_INIT(mbar, cnt) \
    asm volatile("mbarrier.init.shared.b64 [%0], %1;" \
                 :: "r"((uint32_t)(mbar)), "r"((uint32_t)(cnt)) : "memory")
#define MBARRIER_INVAL(mbar) \
    asm volatile("mbarrier.inval.shared.b64 [%0];" :: "r"((uint32_t)(mbar)) : "memory")
#define FENCE_PROXY_ASYNC() \
    asm volatile("fence.proxy.async.shared::cta;" ::: "memory")

#define MBARRIER_WAIT_PARITY(mbar_smem_addr, phase_parity) do { \
    uint32_t _mbar = (uint32_t)(mbar_smem_addr); \
    uint32_t _parity = (uint32_t)(phase_parity); \
    uint32_t _done; \
    asm volatile("{\n\t.reg .pred p;\n\t" \
        "mbarrier.try_wait.parity.acquire.cta.shared::cta.b64 p, [%1], %2;\n\t" \
        "selp.b32 %0, 1, 0, p;\n\t}" \
        : "=r"(_done) : "r"(_mbar), "r"(_parity) : "memory"); \
    if (!_done) { \
        asm volatile("{\n\t.reg .pred P1;\n\t" \
            "WAIT_LOOP_%=:\n\t" \
            "mbarrier.try_wait.parity.acquire.cta.shared::cta.b64 P1, [%0], %1, 0x989680;\n\t" \
            "@P1 bra.uni WAIT_DONE_%=;\n\t" \
            "bra.uni WAIT_LOOP_%=;\n\t" \
            "WAIT_DONE_%=:\n\t}" \
            :: "r"(_mbar), "r"(_parity) : "memory"); \
    } \
} while(0)

#define TCGEN05_LD_32X32B_X32(r, tmem_addr) \
    asm volatile( \
        "tcgen05.ld.sync.aligned.32x32b.x32.b32 " \
        "{%0, %1, %2, %3, %4, %5, %6, %7, " \
        " %8, %9, %10, %11, %12, %13, %14, %15, " \
        " %16, %17, %18, %19, %20, %21, %22, %23, " \
        " %24, %25, %26, %27, %28, %29, %30, %31}, [%32];" \
        : "=r"((r)[0]),  "=r"((r)[1]),  "=r"((r)[2]),  "=r"((r)[3]), \
          "=r"((r)[4]),  "=r"((r)[5]),  "=r"((r)[6]),  "=r"((r)[7]), \
          "=r"((r)[8]),  "=r"((r)[9]),  "=r"((r)[10]), "=r"((r)[11]), \
          "=r"((r)[12]), "=r"((r)[13]), "=r"((r)[14]), "=r"((r)[15]), \
          "=r"((r)[16]), "=r"((r)[17]), "=r"((r)[18]), "=r"((r)[19]), \
          "=r"((r)[20]), "=r"((r)[21]), "=r"((r)[22]), "=r"((r)[23]), \
          "=r"((r)[24]), "=r"((r)[25]), "=r"((r)[26]), "=r"((r)[27]), \
          "=r"((r)[28]), "=r"((r)[29]), "=r"((r)[30]), "=r"((r)[31]) \
        : "r"(tmem_addr))

static constexpr uint64_t SMEM_DESC_BASE_SW128 =
    (uint64_t(2) << 61) | (uint64_t(1) << 46) | (uint64_t(64) << 32) | (uint64_t(1) << 16);
#define MAKE_SMEM_DESC(addr) (SMEM_DESC_BASE_SW128 | ((uint64_t)((addr) >> 4) & 0x3FFF))

__device__ __forceinline__ void mma_bf16_ss(uint32_t d_tmem, uint64_t a_desc,
                                            uint64_t b_desc, uint32_t idesc,
                                            uint32_t enable_d) {
    uint32_t z = 0;
    asm volatile(
        "{\n\t.reg .pred p;\n\tsetp.ne.u32 p, %5, 0;\n\t"
        "tcgen05.mma.cta_group::1.kind::f16 [%0], %1, %2, %3, {%4, %4, %4, %4}, p;\n\t}"
        :: "r"(d_tmem), "l"(a_desc), "l"(b_desc), "r"(idesc), "r"(z), "r"(enable_d)
        : "memory");
}
__device__ __forceinline__ void mma_tf32_ss(uint32_t d_tmem, uint64_t a_desc,
                                            uint64_t b_desc, uint32_t idesc,
                                            uint32_t enable_d) {
    uint32_t z = 0;
    asm volatile(
        "{\n\t.reg .pred p;\n\tsetp.ne.u32 p, %5, 0;\n\t"
        "tcgen05.mma.cta_group::1.kind::tf32 [%0], %1, %2, %3, {%4, %4, %4, %4}, p;\n\t}"
        :: "r"(d_tmem), "l"(a_desc), "l"(b_desc), "r"(idesc), "r"(z), "r"(enable_d)
        : "memory");
}
#endif // TC_PATH

// ---------------------------------------------------------------------------
// Shared epilogue value transform
// ---------------------------------------------------------------------------
__device__ __forceinline__ void store_split3(__nv_bfloat16* op, int N,
                                             float v0, float v1) {
    __nv_bfloat16 h0 = __float2bfloat16_rn(v0);
    __nv_bfloat16 h1 = __float2bfloat16_rn(v1);
    uint32_t hp = pack_raw(h0, h1);
    uint32_t lp = pack_bf16x2(v0 - __bfloat162float(h0), v1 - __bfloat162float(h1));
    *reinterpret_cast<uint32_t*>(op) = hp;
    *reinterpret_cast<uint32_t*>(op + N) = lp;
    *reinterpret_cast<uint32_t*>(op + 2 * N) = hp;
}

// ---------------------------------------------------------------------------
// Legacy HMMA 128x128 tile (compute_103 fallback only)
// ---------------------------------------------------------------------------
#define GBM 128
#define GBN 128
#define GBK 64
#define RSTRIDE 36
#define ABUF (128 * RSTRIDE)
#define BBUF (128 * RSTRIDE)
#define GEMM_SMEM_BYTES 99328

#if !TC_PATH
__device__ void legacy_tile128(
    const __nv_bfloat16* __restrict__ A3, const __nv_bfloat16* __restrict__ B3,
    const float* __restrict__ bias, float* __restrict__ C,
    __nv_bfloat16* __restrict__ out3,
    int N, int K3, float alpha, int do_relu,
    int m0, int n0, uint32_t* sm, uint32_t smb)
{
    const int tid = threadIdx.x;
    const int wid = tid >> 5, lane = tid & 31;
    const int g = lane >> 2, c4 = lane & 3;
    const int warp_m = wid >> 2;
    const int warp_n = wid & 3;

    const int srow = tid >> 1, spart = tid & 1;
    const __nv_bfloat16* aptr = A3 + (size_t)(m0 + srow) * K3 + spart * 32;
    const __nv_bfloat16* bptr = B3 + (size_t)(n0 + srow) * K3 + spart * 32;
    const uint32_t as_base = smb + (srow * RSTRIDE + spart * 16) * 4;
    const uint32_t bs_base = smb + (2 * ABUF + srow * RSTRIDE + spart * 16) * 4;

    const int NC = K3 / GBK;

    float acc[4][4][4];
    #pragma unroll
    for (int i = 0; i < 4; i++)
        #pragma unroll
        for (int j = 0; j < 4; j++)
            #pragma unroll
            for (int q = 0; q < 4; q++) acc[i][j][q] = 0.f;

    #pragma unroll
    for (int q = 0; q < 4; q++) cp16(as_base + q * 16, aptr + q * 8);
    #pragma unroll
    for (int q = 0; q < 4; q++) cp16(bs_base + q * 16, bptr + q * 8);
    cp_commit();

    for (int c = 0; c < NC; c++) {
        if (c + 1 < NC) {
            const int nb = (c + 1) & 1;
            const __nv_bfloat16* ap = aptr + (c + 1) * GBK;
            const __nv_bfloat16* bp = bptr + (c + 1) * GBK;
            #pragma unroll
            for (int q = 0; q < 4; q++)
                cp16(as_base + nb * ABUF * 4 + q * 16, ap + q * 8);
            #pragma unroll
            for (int q = 0; q < 4; q++)
                cp16(bs_base + nb * BBUF * 4 + q * 16, bp + q * 8);
            cp_commit();
            cp_wait<1>();
        } else {
            cp_wait<0>();
        }
        __syncthreads();

        const uint32_t* ab = sm + (c & 1) * ABUF;
        const uint32_t* bb = sm + 2 * ABUF + (c & 1) * BBUF;

        #pragma unroll
        for (int ks = 0; ks < 4; ks++) {
            const int kb = ks * 8;
            uint32_t af[4][4], bf[4][2];
            #pragma unroll
            for (int i = 0; i < 4; i++) {
                const uint32_t* p = ab + (warp_m * 64 + i * 16 + g) * RSTRIDE + kb + c4;
                af[i][0] = p[0];
                af[i][1] = p[8 * RSTRIDE];
                af[i][2] = p[4];
                af[i][3] = p[8 * RSTRIDE + 4];
            }
            #pragma unroll
            for (int j = 0; j < 4; j++) {
                const uint32_t* p = bb + (warp_n * 32 + j * 8 + g) * RSTRIDE + kb + c4;
                bf[j][0] = p[0];
                bf[j][1] = p[4];
            }
            #pragma unroll
            for (int i = 0; i < 4; i++)
                #pragma unroll
                for (int j = 0; j < 4; j++)
                    mma16(acc[i][j], af[i], bf[j]);
        }
        __syncthreads();
    }

    #pragma unroll
    for (int i = 0; i < 4; i++) {
        #pragma unroll
        for (int j = 0; j < 4; j++) {
            const int col = n0 + warp_n * 32 + j * 8 + c4 * 2;
            float b0v = 0.f, b1v = 0.f;
            if (bias) { b0v = bias[col]; b1v = bias[col + 1]; }
            float v0 = acc[i][j][0] * alpha + b0v;
            float v1 = acc[i][j][1] * alpha + b1v;
            float v2 = acc[i][j][2] * alpha + b0v;
            float v3 = acc[i][j][3] * alpha + b1v;
            if (do_relu) {
                v0 = fmaxf(v0, 0.f); v1 = fmaxf(v1, 0.f);
                v2 = fmaxf(v2, 0.f); v3 = fmaxf(v3, 0.f);
            }
            const int ra = m0 + warp_m * 64 + i * 16 + g;
            if (out3) {
                store_split3(out3 + (size_t)ra * 3 * N + col, N, v0, v1);
                store_split3(out3 + (size_t)(ra + 8) * 3 * N + col, N, v2, v3);
            } else {
                float2 lo = {v0, v1}, hi = {v2, v3};
                *reinterpret_cast<float2*>(C + (size_t)ra * N + col) = lo;
                *reinterpret_cast<float2*>(C + (size_t)(ra + 8) * N + col) = hi;
            }
        }
    }
}
#endif // !TC_PATH

// ---------------------------------------------------------------------------
// 128x128 bf16-split GEMM (N=1024 cases; 2 CTAs/SM)
// ---------------------------------------------------------------------------
__global__ __launch_bounds__(256, 2) void gemm_bf16_kernel(
    const __nv_bfloat16* __restrict__ A3, const __nv_bfloat16* __restrict__ B3,
    const float* __restrict__ bias, float* __restrict__ C,
    __nv_bfloat16* __restrict__ out3,
    int M, int N, int K3, float alpha, int do_relu)
{
#if TC_PATH
    extern __shared__ char smc[];
    const uint32_t smb = smem_u32(smc);
    const int tid = threadIdx.x;
    const int wid = tid >> 5, lane = tid & 31;
    const int m0 = blockIdx.x * GBM;
    const int n0 = blockIdx.y * GBN;

    const uint32_t sa[3] = {1024u, 1024u + 16384u, 1024u + 32768u};
    const uint32_t sb[3] = {1024u + 49152u, 1024u + 65536u, 1024u + 81920u};
    const uint32_t mb[3] = {smb + 8u, smb + 16u, smb + 24u};

    if (wid == 0) TCGEN05_ALLOC(smb, 128);
    if (tid == 0) { MBARRIER_INIT(mb[0], 1); MBARRIER_INIT(mb[1], 1); MBARRIER_INIT(mb[2], 1); }
    __syncthreads();
    uint32_t tmem;
    asm volatile("ld.shared.b32 %0, [%1];" : "=r"(tmem) : "r"(smb));
    if (wid == 0) TCGEN05_RELINQUISH();

    const uint32_t IDESC =
        (1u << 4) | (1u << 7) | (1u << 10) | ((GBN / 8) << 17) | ((GBM / 16) << 24);

    const int NC = K3 / GBK;
    const int r0s = tid >> 3;
    const int c8 = tid & 7;
    const __nv_bfloat16* abase = A3 + (size_t)(m0 + r0s) * K3 + c8 * 8;
    const __nv_bfloat16* bbase = B3 + (size_t)(n0 + r0s) * K3 + c8 * 8;
    const uint32_t swoff[4] = {
        SMEM_SWIZZLE_128B((uint32_t)((r0s +  0) * 128 + c8 * 16)),
        SMEM_SWIZZLE_128B((uint32_t)((r0s + 32) * 128 + c8 * 16)),
        SMEM_SWIZZLE_128B((uint32_t)((r0s + 64) * 128 + c8 * 16)),
        SMEM_SWIZZLE_128B((uint32_t)((r0s + 96) * 128 + c8 * 16))};

    auto stage_chunk = [&](int chunk, int buf) {
        #pragma unroll
        for (int it = 0; it < 4; it++) {
            cp16(smb + sa[buf] + swoff[it], abase + (size_t)it * 32 * K3 + chunk * GBK);
            cp16(smb + sb[buf] + swoff[it], bbase + (size_t)it * 32 * K3 + chunk * GBK);
        }
        cp_commit();
    };

    int ph[3] = {0, 0, 0};
    stage_chunk(0, 0);
    stage_chunk(1, 1);

    for (int c = 0; c < NC; c++) {
        const int b = c % 3;
        if (c + 2 < NC) {
            const int nb = (c + 2) % 3;
            if (c >= 1) { MBARRIER_WAIT_PARITY(mb[nb], ph[nb]); ph[nb] ^= 1; }
            stage_chunk(c + 2, nb);
            cp_wait<2>();
        } else if (c + 1 < NC) {
            cp_wait<1>();
        } else {
            cp_wait<0>();
        }
        __syncthreads();
        if (wid == 0 && elect_one_pred()) {
            FENCE_PROXY_ASYNC();
            const uint64_t ad = MAKE_SMEM_DESC(smb + sa[b]);
            const uint64_t bd = MAKE_SMEM_DESC(smb + sb[b]);
            #pragma unroll
            for (int ks = 0; ks < 4; ks++)
                mma_bf16_ss(tmem, ad + ks * 2, bd + ks * 2, IDESC,
                            (c > 0 || ks > 0) ? 1u : 0u);
            TCGEN05_COMMIT(mb[b]);
        }
    }
    MBARRIER_WAIT_PARITY(mb[(NC - 1) % 3], ph[(NC - 1) % 3]);
    TCGEN05_FENCE_AFTER();

    if (wid < 4) {
        const uint32_t lofs = (uint32_t)wid << 21;
        const int row = m0 + wid * 32 + lane;
        #pragma unroll
        for (int j = 0; j < 4; j++) {
            uint32_t r[32];
            TCGEN05_LD_32X32B_X32(r, tmem + j * 32 + lofs);
            TCGEN05_WAIT_LD();
            const float* bp = bias ? (bias + n0 + j * 32) : nullptr;
            if (out3) {
                __nv_bfloat16* op = out3 + (size_t)row * 3 * N + n0 + j * 32;
                #pragma unroll
                for (int q = 0; q < 32; q += 2) {
                    float v0 = __uint_as_float(r[q + 0]) * alpha;
                    float v1 = __uint_as_float(r[q + 1]) * alpha;
                    if (bp) { v0 += bp[q]; v1 += bp[q + 1]; }
                    if (do_relu) { v0 = fmaxf(v0, 0.f); v1 = fmaxf(v1, 0.f); }
                    store_split3(op + q, N, v0, v1);
                }
            } else {
                float* cp = C + (size_t)row * N + n0 + j * 32;
                #pragma unroll
                for (int q = 0; q < 32; q += 4) {
                    float v0 = __uint_as_float(r[q + 0]) * alpha;
                    float v1 = __uint_as_float(r[q + 1]) * alpha;
                    float v2 = __uint_as_float(r[q + 2]) * alpha;
                    float v3 = __uint_as_float(r[q + 3]) * alpha;
                    if (bp) { v0 += bp[q]; v1 += bp[q + 1]; v2 += bp[q + 2]; v3 += bp[q + 3]; }
                    if (do_relu) {
                        v0 = fmaxf(v0, 0.f); v1 = fmaxf(v1, 0.f);
                        v2 = fmaxf(v2, 0.f); v3 = fmaxf(v3, 0.f);
                    }
                    float4 o = {v0, v1, v2, v3};
                    *reinterpret_cast<float4*>(cp + q) = o;
                }
            }
        }
        TCGEN05_FENCE_BEFORE();
    }
    __syncthreads();
    if (tid == 0) { MBARRIER_INVAL(mb[0]); MBARRIER_INVAL(mb[1]); MBARRIER_INVAL(mb[2]); }
    __syncthreads();
    if (wid == 0) TCGEN05_DEALLOC(tmem, 128);
#else
    extern __shared__ uint32_t sm[];
    const uint32_t smb = smem_u32(sm);
    legacy_tile128(A3, B3, bias, C, out3, N, K3, alpha, do_relu,
                   blockIdx.x * GBM, blockIdx.y * GBN, sm, smb);
#endif
}

// ---------------------------------------------------------------------------
// 256x256 bf16-split GEMM (big-N cases: QKV, ff1)
// ---------------------------------------------------------------------------
#define G2K 64
#define G2_SMEM (1024 + 3 * 65536)   // 197632 B

__global__ __launch_bounds__(256, 1) void gemm256_kernel(
    const __nv_bfloat16* __restrict__ A3, const __nv_bfloat16* __restrict__ B3,
    const float* __restrict__ bias, float* __restrict__ C,
    __nv_bfloat16* __restrict__ out3,
    int M, int N, int K3, float alpha, int do_relu)
{
#if TC_PATH
    extern __shared__ char smc[];
    const uint32_t smb = smem_u32(smc);
    const int tid = threadIdx.x;
    const int wid = tid >> 5, lane = tid & 31;
    const int m0 = blockIdx.x * 256;
    const int n0 = blockIdx.y * 256;

    const uint32_t mb[3] = {smb + 8u, smb + 16u, smb + 24u};

    if (wid == 0) TCGEN05_ALLOC(smb, 512);
    if (tid == 0) { MBARRIER_INIT(mb[0], 1); MBARRIER_INIT(mb[1], 1); MBARRIER_INIT(mb[2], 1); }
    __syncthreads();
    uint32_t tmem;
    asm volatile("ld.shared.b32 %0, [%1];" : "=r"(tmem) : "r"(smb));
    if (wid == 0) TCGEN05_RELINQUISH();

    const uint32_t IDESC2 =
        (1u << 4) | (1u << 7) | (1u << 10) | ((256 / 8) << 17) | ((128 / 16) << 24);

    const int NC = K3 / G2K;
    const int r0s = tid >> 3;
    const int c8 = tid & 7;
    const __nv_bfloat16* abase = A3 + (size_t)(m0 + r0s) * K3 + c8 * 8;
    const __nv_bfloat16* bbase = B3 + (size_t)(n0 + r0s) * K3 + c8 * 8;
    uint32_t swoff[8];
    #pragma unroll
    for (int it = 0; it < 8; it++)
        swoff[it] = SMEM_SWIZZLE_128B((uint32_t)((r0s + it * 32) * 128 + c8 * 16));

    auto stage_chunk = [&](int chunk, int buf) {
        const uint32_t sa = smb + 1024u + (uint32_t)buf * 65536u;
        const uint32_t sbo = sa + 32768u;
        #pragma unroll
        for (int it = 0; it < 8; it++) {
            cp16(sa + swoff[it], abase + (size_t)it * 32 * K3 + chunk * G2K);
            cp16(sbo + swoff[it], bbase + (size_t)it * 32 * K3 + chunk * G2K);
        }
        cp_commit();
    };

    int ph[3] = {0, 0, 0};
    stage_chunk(0, 0);
    stage_chunk(1, 1);

    for (int c = 0; c < NC; c++) {
        const int b = c % 3;
        if (c + 2 < NC) {
            const int nb = (c + 2) % 3;
            if (c >= 1) { MBARRIER_WAIT_PARITY(mb[nb], ph[nb]); ph[nb] ^= 1; }
            stage_chunk(c + 2, nb);
            cp_wait<2>();
        } else if (c + 1 < NC) {
            cp_wait<1>();
        } else {
            cp_wait<0>();
        }
        __syncthreads();
        if (wid == 0 && elect_one_pred()) {
            FENCE_PROXY_ASYNC();
            const uint32_t sa = smb + 1024u + (uint32_t)b * 65536u;
            const uint64_t ad = MAKE_SMEM_DESC(sa);
            const uint64_t bd = MAKE_SMEM_DESC(sa + 32768u);
            #pragma unroll
            for (int ks = 0; ks < 4; ks++) {
                const uint32_t en = (c > 0 || ks > 0) ? 1u : 0u;
                mma_bf16_ss(tmem,       ad + ks * 2,        bd + ks * 2, IDESC2, en);
                mma_bf16_ss(tmem + 256, ad + 1024 + ks * 2, bd + ks * 2, IDESC2, en);
            }
            TCGEN05_COMMIT(mb[b]);
        }
    }
    MBARRIER_WAIT_PARITY(mb[(NC - 1) % 3], ph[(NC - 1) % 3]);
    TCGEN05_FENCE_AFTER();

    {
        const int mh = wid >> 2;
        const int w4 = wid & 3;
        const uint32_t lofs = (uint32_t)w4 << 21;
        const int row = m0 + mh * 128 + w4 * 32 + lane;
        #pragma unroll
        for (int j = 0; j < 8; j++) {
            uint32_t r[32];
            TCGEN05_LD_32X32B_X32(r, tmem + mh * 256 + j * 32 + lofs);
            TCGEN05_WAIT_LD();
            const float* bp = bias ? (bias + n0 + j * 32) : nullptr;
            if (out3) {
                __nv_bfloat16* op = out3 + (size_t)row * 3 * N + n0 + j * 32;
                #pragma unroll
                for (int q = 0; q < 32; q += 2) {
                    float v0 = __uint_as_float(r[q + 0]) * alpha;
                    float v1 = __uint_as_float(r[q + 1]) * alpha;
                    if (bp) { v0 += bp[q]; v1 += bp[q + 1]; }
                    if (do_relu) { v0 = fmaxf(v0, 0.f); v1 = fmaxf(v1, 0.f); }
                    store_split3(op + q, N, v0, v1);
                }
            } else {
                float* cp = C + (size_t)row * N + n0 + j * 32;
                #pragma unroll
                for (int q = 0; q < 32; q += 4) {
                    float v0 = __uint_as_float(r[q + 0]) * alpha;
                    float v1 = __uint_as_float(r[q + 1]) * alpha;
                    float v2 = __uint_as_float(r[q + 2]) * alpha;
                    float v3 = __uint_as_float(r[q + 3]) * alpha;
                    if (bp) { v0 += bp[q]; v1 += bp[q + 1]; v2 += bp[q + 2]; v3 += bp[q + 3]; }
                    if (do_relu) {
                        v0 = fmaxf(v0, 0.f); v1 = fmaxf(v1, 0.f);
                        v2 = fmaxf(v2, 0.f); v3 = fmaxf(v3, 0.f);
                    }
                    float4 o = {v0, v1, v2, v3};
                    *reinterpret_cast<float4*>(cp + q) = o;
                }
            }
        }
        TCGEN05_FENCE_BEFORE();
    }
    __syncthreads();
    if (tid == 0) { MBARRIER_INVAL(mb[0]); MBARRIER_INVAL(mb[1]); MBARRIER_INVAL(mb[2]); }
    __syncthreads();
    if (wid == 0) TCGEN05_DEALLOC(tmem, 512);
#else
    extern __shared__ uint32_t sm[];
    const uint32_t smb = smem_u32(sm);
    #pragma unroll
    for (int qm = 0; qm < 2; qm++)
        for (int qn = 0; qn < 2; qn++) {
            legacy_tile128(A3, B3, bias, C, out3, N, K3, alpha, do_relu,
                           blockIdx.x * 256 + qm * 128,
                           blockIdx.y * 256 + qn * 128, sm, smb);
            __syncthreads();
        }
#endif
}

// ---------------------------------------------------------------------------
// 256x256 tf32 GEMM (logits only). A, B are RNA-tf32-rounded fp32.
// ---------------------------------------------------------------------------
__global__ __launch_bounds__(256, 1) void gemm256tf_kernel(
    const float* __restrict__ A, const float* __restrict__ Bm,
    float* __restrict__ C, int M, int N, int K)
{
#if TC_PATH
    extern __shared__ char smc[];
    const uint32_t smb = smem_u32(smc);
    const int tid = threadIdx.x;
    const int wid = tid >> 5, lane = tid & 31;
    const int m0 = blockIdx.x * 256;
    const int n0 = blockIdx.y * 256;

    const uint32_t mb[3] = {smb + 8u, smb + 16u, smb + 24u};

    if (wid == 0) TCGEN05_ALLOC(smb, 512);
    if (tid == 0) { MBARRIER_INIT(mb[0], 1); MBARRIER_INIT(mb[1], 1); MBARRIER_INIT(mb[2], 1); }
    __syncthreads();
    uint32_t tmem;
    asm volatile("ld.shared.b32 %0, [%1];" : "=r"(tmem) : "r"(smb));
    if (wid == 0) TCGEN05_RELINQUISH();

    const uint32_t IDESCT =
        (1u << 4) | (2u << 7) | (2u << 10) | ((256 / 8) << 17) | ((128 / 16) << 24);

    const int NC = K / 32;
    const int r0s = tid >> 3;
    const int c8 = tid & 7;
    const float* abase = A + (size_t)(m0 + r0s) * K + c8 * 4;
    const float* bbase = Bm + (size_t)(n0 + r0s) * K + c8 * 4;
    uint32_t swoff[8];
    #pragma unroll
    for (int it = 0; it < 8; it++)
        swoff[it] = SMEM_SWIZZLE_128B((uint32_t)((r0s + it * 32) * 128 + c8 * 16));

    auto stage_chunk = [&](int chunk, int buf) {
        const uint32_t sa = smb + 1024u + (uint32_t)buf * 65536u;
        const uint32_t sbo = sa + 32768u;
        #pragma unroll
        for (int it = 0; it < 8; it++) {
            cp16(sa + swoff[it], abase + (size_t)it * 32 * K + chunk * 32);
            cp16(sbo + swoff[it], bbase + (size_t)it * 32 * K + chunk * 32);
        }
        cp_commit();
    };

    int ph[3] = {0, 0, 0};
    stage_chunk(0, 0);
    stage_chunk(1, 1);

    for (int c = 0; c < NC; c++) {
        const int b = c % 3;
        if (c + 2 < NC) {
            const int nb = (c + 2) % 3;
            if (c >= 1) { MBARRIER_WAIT_PARITY(mb[nb], ph[nb]); ph[nb] ^= 1; }
            stage_chunk(c + 2, nb);
            cp_wait<2>();
        } else if (c + 1 < NC) {
            cp_wait<1>();
        } else {
            cp_wait<0>();
        }
        __syncthreads();
        if (wid == 0 && elect_one_pred()) {
            FENCE_PROXY_ASYNC();
            const uint32_t sa = smb + 1024u + (uint32_t)b * 65536u;
            const uint64_t ad = MAKE_SMEM_DESC(sa);
            const uint64_t bd = MAKE_SMEM_DESC(sa + 32768u);
            #pragma unroll
            for (int ks = 0; ks < 4; ks++) {
                const uint32_t en = (c > 0 || ks > 0) ? 1u : 0u;
                mma_tf32_ss(tmem,       ad + ks * 2,        bd + ks * 2, IDESCT, en);
                mma_tf32_ss(tmem + 256, ad + 1024 + ks * 2, bd + ks * 2, IDESCT, en);
            }
            TCGEN05_COMMIT(mb[b]);
        }
    }
    MBARRIER_WAIT_PARITY(mb[(NC - 1) % 3], ph[(NC - 1) % 3]);
    TCGEN05_FENCE_AFTER();

    {
        const int mh = wid >> 2;
        const int w4 = wid & 3;
        const uint32_t lofs = (uint32_t)w4 << 21;
        const int row = m0 + mh * 128 + w4 * 32 + lane;
        #pragma unroll
        for (int j = 0; j < 8; j++) {
            uint32_t r[32];
            TCGEN05_LD_32X32B_X32(r, tmem + mh * 256 + j * 32 + lofs);
            TCGEN05_WAIT_LD();
            float* cp = C + (size_t)row * N + n0 + j * 32;
            #pragma unroll
            for (int q = 0; q < 32; q += 4) {
                float4 o;
                o.x = __uint_as_float(r[q + 0]);
                o.y = __uint_as_float(r[q + 1]);
                o.z = __uint_as_float(r[q + 2]);
                o.w = __uint_as_float(r[q + 3]);
                *reinterpret_cast<float4*>(cp + q) = o;
            }
        }
        TCGEN05_FENCE_BEFORE();
    }
    __syncthreads();
    if (tid == 0) { MBARRIER_INVAL(mb[0]); MBARRIER_INVAL(mb[1]); MBARRIER_INVAL(mb[2]); }
    __syncthreads();
    if (wid == 0) TCGEN05_DEALLOC(tmem, 512);
#else
    // correctness-only fallback (never executes on sm_103a; operands pre-rounded)
    const int m0 = blockIdx.x * 256;
    const int n0 = blockIdx.y * 256;
    for (int idx = threadIdx.x; idx < 256 * 256; idx += 256) {
        const int i = idx >> 8, j = idx & 255;
        const float* a = A + (size_t)(m0 + i) * K;
        const float* b = Bm + (size_t)(n0 + j) * K;
        float s = 0.f;
        for (int k = 0; k < K; k++) s += a[k] * b[k];
        C[(size_t)(m0 + i) * N + n0 + j] = s;
    }
#endif
}

// ---------------------------------------------------------------------------
// Tensor-core split-bf16 causal flash attention (fused-QKV input).
// Load-balanced: grid (8, 64); each block handles q-tile pair (x, 15-x),
// giving every block exactly 17 K-tile iterations.
// ---------------------------------------------------------------------------
#define AT_STRIDE 136
#define ATT_SMEM  (3 * 64 * AT_STRIDE * 2)   // 52224 B

__global__ __launch_bounds__(128, 3) void attn_mma_kernel(
    const float* __restrict__ Q, const float* __restrict__ Kg,
    const float* __restrict__ Vg, __nv_bfloat16* __restrict__ conc3)
{
    extern __shared__ __nv_bfloat16 sh[];
    __nv_bfloat16* Qs = sh;
    __nv_bfloat16* Ks = sh + 64 * AT_STRIDE;
    __nv_bfloat16* Vs = sh + 128 * AT_STRIDE;

    const int bh = blockIdx.y;
    const int b = bh >> 4, n = bh & 15;
    const int tid = threadIdx.x;
    const int wid = tid >> 5, lane = tid & 31;
    const int g = lane >> 2, c4 = lane & 3;
    const int row0 = wid * 16 + g;

    for (int half = 0; half < 2; half++) {
        const int qt = (half == 0) ? (int)blockIdx.x : 15 - (int)blockIdx.x;
        __syncthreads();   // prior half done reading Qs/Ks/Vs

        // stage Q for this q-tile
        {
            const int r = tid >> 1;
            const int dbase = (tid & 1) * 32;
            const float* qp = Q + ((size_t)(b * S_ + qt * 64 + r)) * QKVS + n * 64 + dbase;
            #pragma unroll
            for (int i = 0; i < 32; i += 4) {
                float4 f = *reinterpret_cast<const float4*>(qp + i);
                float vals[4] = {f.x, f.y, f.z, f.w};
                #pragma unroll
                for (int e = 0; e < 4; e++) {
                    __nv_bfloat16 hi = __float2bfloat16_rn(vals[e]);
                    Qs[r * AT_STRIDE + dbase + i + e] = hi;
                    Qs[r * AT_STRIDE + 64 + dbase + i + e] =
                        __float2bfloat16_rn(vals[e] - __bfloat162float(hi));
                }
            }
        }

        float m0 = -1e30f, m1 = -1e30f, l0 = 0.f, l1 = 0.f;
        float o[8][4];
        #pragma unroll
        for (int j = 0; j < 8; j++)
            #pragma unroll
            for (int q = 0; q < 4; q++) o[j][q] = 0.f;

        for (int kt = 0; kt <= qt; kt++) {
            __syncthreads();
            {
                const int r = tid >> 1;
                const int dbase = (tid & 1) * 32;
                const float* kp = Kg + ((size_t)(b * S_ + kt * 64 + r)) * QKVS + n * 64 + dbase;
                const float* vp = Vg + ((size_t)(b * S_ + kt * 64 + r)) * QKVS + n * 64 + dbase;
                #pragma unroll
                for (int i = 0; i < 32; i += 4) {
                    float4 fk = *reinterpret_cast<const float4*>(kp + i);
                    float4 fv = *reinterpret_cast<const float4*>(vp + i);
                    float kv[4] = {fk.x, fk.y, fk.z, fk.w};
                    float vv[4] = {fv.x, fv.y, fv.z, fv.w};
                    #pragma unroll
                    for (int e = 0; e < 4; e++) {
                        const int d = dbase + i + e;
                        __nv_bfloat16 kh = __float2bfloat16_rn(kv[e]);
                        Ks[r * AT_STRIDE + d] = kh;
                        Ks[r * AT_STRIDE + 64 + d] =
                            __float2bfloat16_rn(kv[e] - __bfloat162float(kh));
                        __nv_bfloat16 vh = __float2bfloat16_rn(vv[e]);
                        Vs[d * AT_STRIDE + r] = vh;
                        Vs[d * AT_STRIDE + 64 + r] =
                            __float2bfloat16_rn(vv[e] - __bfloat162float(vh));
                    }
                }
            }
            __syncthreads();

            float s[8][4];
            #pragma unroll
            for (int j = 0; j < 8; j++)
                #pragma unroll
                for (int q = 0; q < 4; q++) s[j][q] = 0.f;

            #pragma unroll
            for (int phs = 0; phs < 3; phs++) {
                const int aoff = (phs == 1) ? 64 : 0;
                const int boff = (phs == 2) ? 64 : 0;
                #pragma unroll
                for (int ks = 0; ks < 4; ks++) {
                    uint32_t a[4];
                    const __nv_bfloat16* ap = Qs + row0 * AT_STRIDE + aoff + ks * 16 + c4 * 2;
                    a[0] = *reinterpret_cast<const uint32_t*>(ap);
                    a[1] = *reinterpret_cast<const uint32_t*>(ap + 8 * AT_STRIDE);
                    a[2] = *reinterpret_cast<const uint32_t*>(ap + 8);
                    a[3] = *reinterpret_cast<const uint32_t*>(ap + 8 * AT_STRIDE + 8);
                    #pragma unroll
                    for (int j = 0; j < 8; j++) {
                        uint32_t bf[2];
                        const __nv_bfloat16* bp =
                            Ks + (8 * j + g) * AT_STRIDE + boff + ks * 16 + c4 * 2;
                        bf[0] = *reinterpret_cast<const uint32_t*>(bp);
                        bf[1] = *reinterpret_cast<const uint32_t*>(bp + 8);
                        mma16(s[j], a, bf);
                    }
                }
            }

            if (kt == qt) {
                #pragma unroll
                for (int j = 0; j < 8; j++) {
                    const int colb = 8 * j + 2 * c4;
                    if (colb     > row0)     s[j][0] = -1e30f;
                    if (colb + 1 > row0)     s[j][1] = -1e30f;
                    if (colb     > row0 + 8) s[j][2] = -1e30f;
                    if (colb + 1 > row0 + 8) s[j][3] = -1e30f;
                }
            }

            float rm0 = -1e30f, rm1 = -1e30f;
            #pragma unroll
            for (int j = 0; j < 8; j++) {
                rm0 = fmaxf(rm0, fmaxf(s[j][0], s[j][1]));
                rm1 = fmaxf(rm1, fmaxf(s[j][2], s[j][3]));
            }
            rm0 = fmaxf(rm0, __shfl_xor_sync(0xFFFFFFFFu, rm0, 1));
            rm0 = fmaxf(rm0, __shfl_xor_sync(0xFFFFFFFFu, rm0, 2));
            rm1 = fmaxf(rm1, __shfl_xor_sync(0xFFFFFFFFu, rm1, 1));
            rm1 = fmaxf(rm1, __shfl_xor_sync(0xFFFFFFFFu, rm1, 2));
            const float mn0 = fmaxf(m0, rm0), mn1 = fmaxf(m1, rm1);
            const float cr0 = __expf(m0 - mn0), cr1 = __expf(m1 - mn1);
            m0 = mn0; m1 = mn1;

            float ps0 = 0.f, ps1 = 0.f;
            uint32_t phi[8][2], plo[8][2];
            #pragma unroll
            for (int j = 0; j < 8; j++) {
                float p0 = __expf(s[j][0] - mn0);
                float p1 = __expf(s[j][1] - mn0);
                float p2 = __expf(s[j][2] - mn1);
                float p3 = __expf(s[j][3] - mn1);
                ps0 += p0 + p1; ps1 += p2 + p3;
                __nv_bfloat16 h0 = __float2bfloat16_rn(p0), h1 = __float2bfloat16_rn(p1);
                __nv_bfloat16 h2 = __float2bfloat16_rn(p2), h3 = __float2bfloat16_rn(p3);
                phi[j][0] = pack_raw(h0, h1);
                phi[j][1] = pack_raw(h2, h3);
                plo[j][0] = pack_bf16x2(p0 - __bfloat162float(h0), p1 - __bfloat162float(h1));
                plo[j][1] = pack_bf16x2(p2 - __bfloat162float(h2), p3 - __bfloat162float(h3));
            }
            ps0 += __shfl_xor_sync(0xFFFFFFFFu, ps0, 1);
            ps0 += __shfl_xor_sync(0xFFFFFFFFu, ps0, 2);
            ps1 += __shfl_xor_sync(0xFFFFFFFFu, ps1, 1);
            ps1 += __shfl_xor_sync(0xFFFFFFFFu, ps1, 2);
            l0 = l0 * cr0 + ps0;
            l1 = l1 * cr1 + ps1;
            #pragma unroll
            for (int j = 0; j < 8; j++) {
                o[j][0] *= cr0; o[j][1] *= cr0;
                o[j][2] *= cr1; o[j][3] *= cr1;
            }

            #pragma unroll
            for (int phs = 0; phs < 3; phs++) {
                const int voff = (phs == 2) ? 64 : 0;
                #pragma unroll
                for (int ks = 0; ks < 4; ks++) {
                    uint32_t a[4];
                    if (phs == 1) {
                        a[0] = plo[2 * ks][0]; a[1] = plo[2 * ks][1];
                        a[2] = plo[2 * ks + 1][0]; a[3] = plo[2 * ks + 1][1];
                    } else {
                        a[0] = phi[2 * ks][0]; a[1] = phi[2 * ks][1];
                        a[2] = phi[2 * ks + 1][0]; a[3] = phi[2 * ks + 1][1];
                    }
                    #pragma unroll
                    for (int j = 0; j < 8; j++) {
                        uint32_t bf[2];
                        const __nv_bfloat16* bp =
                            Vs + (8 * j + g) * AT_STRIDE + voff + ks * 16 + c4 * 2;
                        bf[0] = *reinterpret_cast<const uint32_t*>(bp);
                        bf[1] = *reinterpret_cast<const uint32_t*>(bp + 8);
                        mma16(o[j], a, bf);
                    }
                }
            }
        }

        // epilogue for this q-tile
        const float inv0 = 1.f / l0, inv1 = 1.f / l1;
        const size_t r0 = (size_t)(b * S_ + qt * 64 + row0);
        __nv_bfloat16* o0 = conc3 + r0 * 3 * H_;
        __nv_bfloat16* o1 = conc3 + (r0 + 8) * 3 * H_;
        #pragma unroll
        for (int j = 0; j < 8; j++) {
            const int col = n * 64 + 8 * j + 2 * c4;
            store_split3(o0 + col, H_, o[j][0] * inv0, o[j][1] * inv0);
            store_split3(o1 + col, H_, o[j][2] * inv1, o[j][3] * inv1);
        }
    }
}

// ---------------------------------------------------------------------------
// Conversion / elementwise kernels
// ---------------------------------------------------------------------------
__global__ void gather_split_kernel(const int* __restrict__ x,
                                    const float* __restrict__ emb,
                                    __nv_bfloat16* __restrict__ out3)
{
    int idx = blockIdx.x * blockDim.x + threadIdx.x;
    if (idx >= M4 * E_) return;
    int i = idx / E_;
    int e = idx - i * E_;
    float v = emb[(size_t)x[i] * E_ + e];
    __nv_bfloat16 hi = __float2bfloat16_rn(v);
    __nv_bfloat16 lo = __float2bfloat16_rn(v - __bfloat162float(hi));
    size_t base = (size_t)i * 3 * E_;
    out3[base + e] = hi;
    out3[base + E_ + e] = lo;
    out3[base + 2 * E_ + e] = hi;
}

__global__ __launch_bounds__(256) void conv_wT_kernel(
    const float* __restrict__ W, __nv_bfloat16* __restrict__ out,
    int K, int N, float wscale)
{
    __shared__ float tile[32][33];
    const int tx = threadIdx.x & 31;
    const int ty = threadIdx.x >> 5;
    const int n0 = blockIdx.x * 32;
    const int k0 = blockIdx.y * 32;
    #pragma unroll
    for (int i = 0; i < 4; i++)
        tile[ty + i * 8][tx] = W[(size_t)(k0 + ty + i * 8) * N + n0 + tx];
    __syncthreads();
    #pragma unroll
    for (int i = 0; i < 4; i++) {
        const int nn = n0 + ty + i * 8;
        const int k = k0 + tx;
        float x = tile[tx][ty + i * 8] * wscale;
        __nv_bfloat16 hi = __float2bfloat16_rn(x);
        __nv_bfloat16 lo = __float2bfloat16_rn(x - __bfloat162float(hi));
        size_t base = (size_t)nn * 3 * K;
        out[base + k] = hi;
        out[base + K + k] = hi;
        out[base + 2 * K + k] = lo;
    }
}

// transpose + RNA-tf32-round to fp32 (for p_decoder)
__global__ __launch_bounds__(256) void conv_wTf32_kernel(
    const float* __restrict__ W, float* __restrict__ out, int K, int N)
{
    __shared__ float tile[32][33];
    const int tx = threadIdx.x & 31;
    const int ty = threadIdx.x >> 5;
    const int n0 = blockIdx.x * 32;
    const int k0 = blockIdx.y * 32;
    #pragma unroll
    for (int i = 0; i < 4; i++)
        tile[ty + i * 8][tx] = W[(size_t)(k0 + ty + i * 8) * N + n0 + tx];
    __syncthreads();
    #pragma unroll
    for (int i = 0; i < 4; i++) {
        const int nn = n0 + ty + i * 8;
        out[(size_t)nn * K + k0 + tx] = rna_tf32(tile[tx][ty + i * 8]);
    }
}

__global__ void addpos_kernel(const float* __restrict__ xemb,
                              const float* __restrict__ pos11,
                              float* __restrict__ out,
                              __nv_bfloat16* __restrict__ out3)
{
    int idx = blockIdx.x * blockDim.x + threadIdx.x;
    if (idx >= M4 * H_) return;
    int i = idx / H_;
    int h = idx - i * H_;
    int s = i & (S_ - 1);
    float y = xemb[idx] + pos11[(size_t)s * H_ + h];
    out[idx] = y;
    __nv_bfloat16 hi = __float2bfloat16_rn(y);
    __nv_bfloat16 lo = __float2bfloat16_rn(y - __bfloat162float(hi));
    size_t base = (size_t)i * 3 * H_;
    out3[base + h] = hi;
    out3[base + H_ + h] = lo;
    out3[base + 2 * H_ + h] = hi;
}

__global__ __launch_bounds__(256) void ln_res_kernel(
    const float* __restrict__ res, const float* __restrict__ x,
    const float* __restrict__ bias, const float* __restrict__ scale,
    float* __restrict__ out, __nv_bfloat16* __restrict__ out3)
{
    __shared__ float red[256];
    const int row = blockIdx.x;
    const int t = threadIdx.x;
    const float* xr = x + (size_t)row * H_;

    float lsum = 0.f;
    for (int i = t; i < H_; i += 256) lsum += xr[i];
    red[t] = lsum; __syncthreads();
    for (int s = 128; s > 0; s >>= 1) { if (t < s) red[t] += red[t + s]; __syncthreads(); }
    const float mean = red[0] * (1.0f / H_);
    __syncthreads();

    float lvar = 0.f;
    for (int i = t; i < H_; i += 256) { float d = xr[i] - mean; lvar += d * d; }
    red[t] = lvar; __syncthreads();
    for (int s = 128; s > 0; s >>= 1) { if (t < s) red[t] += red[t + s]; __syncthreads(); }
    const float rstd = rsqrtf(red[0] * (1.0f / H_) + 1e-6f);

    for (int i = t; i < H_; i += 256) {
        float y = res[(size_t)row * H_ + i] + (xr[i] - mean) * rstd * scale[i] + bias[i];
        out[(size_t)row * H_ + i] = y;
        if (out3) {
            __nv_bfloat16 hi = __float2bfloat16_rn(y);
            __nv_bfloat16 lo = __float2bfloat16_rn(y - __bfloat162float(hi));
            size_t base = (size_t)row * 3 * H_;
            out3[base + i] = hi;
            out3[base + H_ + i] = lo;
            out3[base + 2 * H_ + i] = hi;
        }
    }
}

// ---------------------------------------------------------------------------
// Fused double-LN (steps 9+10):
//   y1 = xself + LN(ffw2)*s1 + b1        (= x_ffw, kept in smem)
//   decout = rna_tf32(xemb + LN(y1)*s2 + b2)
// ---------------------------------------------------------------------------
__global__ __launch_bounds__(256) void ln2_res_kernel(
    const float* __restrict__ xself, const float* __restrict__ ffw2,
    const float* __restrict__ b1, const float* __restrict__ s1,
    const float* __restrict__ xemb,
    const float* __restrict__ b2, const float* __restrict__ s2,
    float* __restrict__ decout)
{
    __shared__ float red[256];
    __shared__ float y1[H_];
    const int row = blockIdx.x;
    const int t = threadIdx.x;
    const float* xr = ffw2 + (size_t)row * H_;

    // LN1 stats over ffw2 row
    float lsum = 0.f;
    for (int i = t; i < H_; i += 256) lsum += xr[i];
    red[t] = lsum; __syncthreads();
    for (int s = 128; s > 0; s >>= 1) { if (t < s) red[t] += red[t + s]; __syncthreads(); }
    const float mean = red[0] * (1.0f / H_);
    __syncthreads();

    float lvar = 0.f;
    for (int i = t; i < H_; i += 256) { float d = xr[i] - mean; lvar += d * d; }
    red[t] = lvar; __syncthreads();
    for (int s = 128; s > 0; s >>= 1) { if (t < s) red[t] += red[t + s]; __syncthreads(); }
    const float rstd = rsqrtf(red[0] * (1.0f / H_) + 1e-6f);
    __syncthreads();

    // y1 = xself + LN1(ffw2)
    for (int i = t; i < H_; i += 256)
        y1[i] = xself[(size_t)row * H_ + i] + (xr[i] - mean) * rstd * s1[i] + b1[i];
    __syncthreads();

    // LN2 stats over y1
    float lsum2 = 0.f;
    for (int i = t; i < H_; i += 256) lsum2 += y1[i];
    red[t] = lsum2; __syncthreads();
    for (int s = 128; s > 0; s >>= 1) { if (t < s) red[t] += red[t + s]; __syncthreads(); }
    const float mean2 = red[0] * (1.0f / H_);
    __syncthreads();

    float lvar2 = 0.f;
    for (int i = t; i < H_; i += 256) { float d = y1[i] - mean2; lvar2 += d * d; }
    red[t] = lvar2; __syncthreads();
    for (int s = 128; s > 0; s >>= 1) { if (t < s) red[t] += red[t + s]; __syncthreads(); }
    const float rstd2 = rsqrtf(red[0] * (1.0f / H_) + 1e-6f);

    for (int i = t; i < H_; i += 256) {
        float y = xemb[(size_t)row * H_ + i] + (y1[i] - mean2) * rstd2 * s2[i] + b2[i];
        decout[(size_t)row * H_ + i] = rna_tf32(y);
    }
}

// ---------------------------------------------------------------------------
// Launch helpers
// ---------------------------------------------------------------------------
static inline void run_gemm(const __nv_bfloat16* A3, const __nv_bfloat16* B3,
                            const float* bias, float* C, __nv_bfloat16* out3,
                            int M, int N, int K3, float alpha, int relu)
{
    dim3 grid(M / GBM, N / GBN);
    gemm_bf16_kernel<<<grid, 256, GEMM_SMEM_BYTES>>>(A3, B3, bias, C, out3,
                                                     M, N, K3, alpha, relu);
}
static inline void run_gemm256(const __nv_bfloat16* A3, const __nv_bfloat16* B3,
                               const float* bias, float* C, __nv_bfloat16* out3,
                               int M, int N, int K3, float alpha, int relu)
{
    dim3 grid(M / 256, N / 256);
    gemm256_kernel<<<grid, 256, G2_SMEM>>>(A3, B3, bias, C, out3,
                                           M, N, K3, alpha, relu);
}
static inline void run_gemm256tf(const float* A, const float* Bm, float* C,
                                 int M, int N, int K)
{
    dim3 grid(M / 256, N / 256);
    gemm256tf_kernel<<<grid, 256, G2_SMEM>>>(A, Bm, C, M, N, K);
}
static inline void run_conv_wT(const float* W, __nv_bfloat16* out,
                               int K, int N, float wscale)
{
    dim3 grid(N / 32, K / 32);
    conv_wT_kernel<<<grid, 256>>>(W, out, K, N, wscale);
}

extern "C" void kernel_launch(void* const* d_in, const int* in_sizes, int n_in,
                              void* d_out, int out_size)
{
    const int*   x            = (const int*)  d_in[0];
    const float* emb_decode   = (const float*)d_in[1];
    const float* W_dec_lin    = (const float*)d_in[2];
    const float* p_decoder    = (const float*)d_in[3];
    const float* x_emb_pos    = (const float*)d_in[4];
    const float* p_d_q        = (const float*)d_in[5];
    const float* p_d_k        = (const float*)d_in[6];
    const float* p_d_v        = (const float*)d_in[7];
    const float* p_d_c        = (const float*)d_in[8];
    const float* p_d_ff1      = (const float*)d_in[9];
    const float* p_d_ff2      = (const float*)d_in[10];
    const float* b_d_ff1      = (const float*)d_in[11];
    const float* b_d_ff2      = (const float*)d_in[12];
    const float* d_o_bias     = (const float*)d_in[13];
    const float* d_o_scale    = (const float*)d_in[14];
    const float* b_d_bias_1   = (const float*)d_in[15];
    const float* b_d_bias_2   = (const float*)d_in[16];
    const float* b_d_scale_1  = (const float*)d_in[17];
    const float* b_d_scale_2  = (const float*)d_in[18];
    float* out = (float*)d_out;

    const int m = L_ - 1;   // only the last layer's result is observable

    cudaFuncSetAttribute(gemm_bf16_kernel,
                         cudaFuncAttributeMaxDynamicSharedMemorySize, GEMM_SMEM_BYTES);
    cudaFuncSetAttribute(gemm256_kernel,
                         cudaFuncAttributeMaxDynamicSharedMemorySize, G2_SMEM);
    cudaFuncSetAttribute(gemm256tf_kernel,
                         cudaFuncAttributeMaxDynamicSharedMemorySize, G2_SMEM);
    cudaFuncSetAttribute(attn_mma_kernel,
                         cudaFuncAttributeMaxDynamicSharedMemorySize, ATT_SMEM);

    float *xemb, *layerin, *qkv, *xmulti, *xself, *ffw1, *ffw2, *decout, *wtp;
    __nv_bfloat16 *a3_emb, *a3_li, *a3_conc, *a3_self, *a3_ffw1;
    __nv_bfloat16 *w3_dec, *w3_qkv, *w3_c, *w3_ff1, *w3_ff2;
    cudaGetSymbolAddress((void**)&xemb,    g_xemb);
    cudaGetSymbolAddress((void**)&layerin, g_layerin);
    cudaGetSymbolAddress((void**)&qkv,     g_qkv);
    cudaGetSymbolAddress((void**)&xmulti,  g_xmulti);
    cudaGetSymbolAddress((void**)&xself,   g_xself);
    cudaGetSymbolAddress((void**)&ffw1,    g_ffw1);
    cudaGetSymbolAddress((void**)&ffw2,    g_ffw2);
    cudaGetSymbolAddress((void**)&decout,  g_decout);
    cudaGetSymbolAddress((void**)&wtp,     g_wtp);
    cudaGetSymbolAddress((void**)&a3_emb,  g_a3_emb);
    cudaGetSymbolAddress((void**)&a3_li,   g_a3_li);
    cudaGetSymbolAddress((void**)&a3_conc, g_a3_conc);
    cudaGetSymbolAddress((void**)&a3_self, g_a3_self);
    cudaGetSymbolAddress((void**)&a3_ffw1, g_a3_ffw1);
    cudaGetSymbolAddress((void**)&w3_dec,  g_w3_dec);
    cudaGetSymbolAddress((void**)&w3_qkv,  g_w3_qkv);
    cudaGetSymbolAddress((void**)&w3_c,    g_w3_c);
    cudaGetSymbolAddress((void**)&w3_ff1,  g_w3_ff1);
    cudaGetSymbolAddress((void**)&w3_ff2,  g_w3_ff2);

    // weight conversions; Q weights pre-scaled by 1/sqrt(head)
    run_conv_wT(W_dec_lin, w3_dec, E_, H_, 1.f);
    run_conv_wT(p_d_q + (size_t)m * H_ * H_, w3_qkv, H_, H_, 0.125f);
    run_conv_wT(p_d_k + (size_t)m * H_ * H_, w3_qkv + (size_t)1024 * 3 * H_, H_, H_, 1.f);
    run_conv_wT(p_d_v + (size_t)m * H_ * H_, w3_qkv + (size_t)2048 * 3 * H_, H_, H_, 1.f);
    run_conv_wT(p_d_c + (size_t)m * H_ * H_, w3_c, H_, H_, 1.f);
    run_conv_wT(p_d_ff1 + (size_t)m * H_ * FF_, w3_ff1, H_, FF_, 1.f);
    run_conv_wT(p_d_ff2 + (size_t)m * FF_ * H_, w3_ff2, FF_, H_, 1.f);
    {   // p_decoder -> transposed RNA-rounded fp32
        dim3 grid(V_ / 32, H_ / 32);
        conv_wTf32_kernel<<<grid, 256>>>(p_decoder, wtp, H_, V_);
    }

    // 1. gather embeddings + split (fused)
    gather_split_kernel<<<(M4 * E_ + 255) / 256, 256>>>(x, emb_decode, a3_emb);

    // 2. x_dec_embed = A_emb @ W_dec_lin   (128-tile: 256 CTAs, 2/SM)
    run_gemm(a3_emb, w3_dec, nullptr, xemb, nullptr, M4, H_, 3 * E_, 1.f, 0);

    // 3. layer_in = pos[11] + x_dec_embed  (+ fused split)
    addpos_kernel<<<(M4 * H_ + 255) / 256, 256>>>(
        xemb, x_emb_pos + (size_t)m * S_ * H_, layerin, a3_li);

    // 4. fused Q/K/V projection (256-tile: grid 16x12 = 192 CTAs)
    run_gemm256(a3_li, w3_qkv, nullptr, qkv, nullptr, M4, QKVS, 3 * H_, 1.f, 0);

    // 5. load-balanced tensor-core causal attention -> a3_conc
    attn_mma_kernel<<<dim3(S_ / 128, B_ * NH_), 128, ATT_SMEM>>>(
        qkv, qkv + 1024, qkv + 2048, a3_conc);

    // 6. x_multi = conc @ p_d_c  (128-tile)
    run_gemm(a3_conc, w3_c, nullptr, xmulti, nullptr, M4, H_, 3 * H_, 1.f, 0);

    // 7. x_self = layer_in + LN(x_multi)  (+ fused split)
    ln_res_kernel<<<M4, 256>>>(layerin, xmulti,
                               b_d_bias_1 + (size_t)m * H_,
                               b_d_scale_1 + (size_t)m * H_, xself, a3_self);

    // 8. FFN (ff1 on 256-tile: 256 CTAs; ff2 on 128-tile)
    run_gemm256(a3_self, w3_ff1, b_d_ff1 + (size_t)m * FF_, ffw1, a3_ffw1,
                M4, FF_, 3 * H_, 1.f, 1);
    run_gemm(a3_ffw1, w3_ff2, b_d_ff2 + (size_t)m * H_, ffw2, nullptr,
             M4, H_, 3 * FF_, 1.f, 0);

    // 9+10. fused double-LN: decout = xemb + LN(xself + LN(ffw2)) [rounded]
    ln2_res_kernel<<<M4, 256>>>(xself, ffw2,
                                b_d_bias_2 + (size_t)m * H_,
                                b_d_scale_2 + (size_t)m * H_,
                                xemb, d_o_bias, d_o_scale, decout);

    // 11. logits = dec_outputs @ p_decoder  (tf32 tcgen05, grid 16x125)
    run_gemm256tf(decout, wtp, out, M4, V_, H_);
}

// round 13
// speedup vs baseline: 1.2279x; 1.1593x over previous
#include <cuda_runtime.h>
#include <cuda_bf16.h>
#include <cuda_fp16.h>
#include <cstdint>

// Problem constants
#define L_   12
#define NH_  16
#define H_   1024
#define FF_  4096
#define V_   32000
#define S_   1024
#define E_   128
#define B_   4
#define HEAD_ 64
#define M4   (B_ * S_)   // 4096 rows total
#define QKVS 3072        // fused qkv row stride (floats)

// Arch-feature dispatch: tcgen05 only legal in the sm_103a pass.
#if defined(__CUDA_ARCH__) && defined(__CUDA_ARCH_FEAT_SM103_ALL)
#define TC_PATH 1
#else
#define TC_PATH 0
#endif

// ---------------------------------------------------------------------------
// Scratch (device globals — allocation-free per harness rules)
// ---------------------------------------------------------------------------
__device__ float g_xemb   [M4 * H_];
__device__ float g_layerin[M4 * H_];
__device__ float g_qkv    [M4 * QKVS];
__device__ float g_xmulti [M4 * H_];
__device__ float g_xself  [M4 * H_];
__device__ float g_ffw1   [M4 * FF_];
__device__ float g_ffw2   [M4 * H_];
__device__ __align__(128) __half g_decout [M4 * H_];   // fp16 (feeds logits GEMM)

// bf16 split-K3 operand buffers.  A' = [hi | lo | hi] (row-major, 3K cols),
// B' = [hi | hi | lo] as [N, 3K] (k-contiguous, i.e. transposed weight).
__device__ __align__(128) __nv_bfloat16 g_a3_emb [M4 * 3 * E_];
__device__ __align__(128) __nv_bfloat16 g_a3_li  [M4 * 3 * H_];
__device__ __align__(128) __nv_bfloat16 g_a3_conc[M4 * 3 * H_];
__device__ __align__(128) __nv_bfloat16 g_a3_self[M4 * 3 * H_];
__device__ __align__(128) __nv_bfloat16 g_a3_ffw1[(size_t)M4 * 3 * FF_];

__device__ __align__(128) __nv_bfloat16 g_w3_dec [H_ * 3 * E_];
__device__ __align__(128) __nv_bfloat16 g_w3_qkv [(size_t)QKVS * 3 * H_];
__device__ __align__(128) __nv_bfloat16 g_w3_c   [H_ * 3 * H_];
__device__ __align__(128) __nv_bfloat16 g_w3_ff1 [(size_t)FF_ * 3 * H_];
__device__ __align__(128) __nv_bfloat16 g_w3_ff2 [(size_t)H_ * 3 * FF_];
// p_decoder transposed, fp16  [V, H]
__device__ __align__(128) __half g_wth [(size_t)V_ * H_];

// ---------------------------------------------------------------------------
// PTX helpers — baseline-legal
// ---------------------------------------------------------------------------
__device__ __forceinline__ uint32_t smem_u32(const void* p) {
    uint32_t a;
    asm("{ .reg .u64 t; cvta.to.shared.u64 t, %1; cvt.u32.u64 %0, t; }"
        : "=r"(a) : "l"(p));
    return a;
}
__device__ __forceinline__ void cp16(uint32_t dst, const void* src) {
    asm volatile("cp.async.cg.shared.global [%0], [%1], 16;"
                 :: "r"(dst), "l"(src) : "memory");
}
__device__ __forceinline__ void cp_commit() {
    asm volatile("cp.async.commit_group;" ::: "memory");
}
template <int N>
__device__ __forceinline__ void cp_wait() {
    asm volatile("cp.async.wait_group %0;" :: "n"(N) : "memory");
}
__device__ __forceinline__ uint32_t elect_one_pred() {
    uint32_t pred;
    asm volatile(
        "{\n\t.reg .pred p;\n\telect.sync _|p, 0xFFFFFFFF;\n\t"
        "selp.b32 %0, 1, 0, p;\n\t}" : "=r"(pred));
    return pred;
}
// legacy m16n8k16 bf16 MMA, fp32 accumulate (sm_80+)
__device__ __forceinline__ void mma16(float* d, const uint32_t* a, const uint32_t* b) {
    asm volatile(
        "mma.sync.aligned.m16n8k16.row.col.f32.bf16.bf16.f32 "
        "{%0,%1,%2,%3}, {%4,%5,%6,%7}, {%8,%9}, {%0,%1,%2,%3};"
        : "+f"(d[0]), "+f"(d[1]), "+f"(d[2]), "+f"(d[3])
        : "r"(a[0]), "r"(a[1]), "r"(a[2]), "r"(a[3]),
          "r"(b[0]), "r"(b[1]));
}
__device__ __forceinline__ uint32_t pack_bf16x2(float lo_elem, float hi_elem) {
    uint32_t r;
    asm("cvt.rn.bf16x2.f32 %0, %1, %2;" : "=r"(r) : "f"(hi_elem), "f"(lo_elem));
    return r;
}
__device__ __forceinline__ uint32_t pack_raw(__nv_bfloat16 lo, __nv_bfloat16 hi) {
    return (uint32_t)__bfloat16_as_ushort(lo) | ((uint32_t)__bfloat16_as_ushort(hi) << 16);
}

#define SMEM_SWIZZLE_128B(o) ((o) ^ (((o) >> 3) & 0x70))

#if TC_PATH
// ---- tcgen05 helpers (only compiled in the sm_103a pass) ----
#define TCGEN05_ALLOC(smem_addr, nCols) \
    asm volatile("tcgen05.alloc.cta_group::1.sync.aligned.shared::cta.b32 [%0], %1;" \
                 :: "r"((uint32_t)(smem_addr)), "r"((uint32_t)(nCols)) : "memory")
#define TCGEN05_DEALLOC(tmem_addr, nCols) \
    asm volatile("tcgen05.dealloc.cta_group::1.sync.aligned.b32 %0, %1;" \
                 :: "r"(tmem_addr), "r"((uint32_t)(nCols)))
#define TCGEN05_RELINQUISH() \
    asm volatile("tcgen05.relinquish_alloc_permit.cta_group::1.sync.aligned;")
#define TCGEN05_COMMIT(mbar) \
    asm volatile("tcgen05.commit.cta_group::1.mbarrier::arrive::one.shared::cluster.b64 [%0];" \
                 :: "r"((uint32_t)(mbar)) : "memory")
#define TCGEN05_FENCE_AFTER() \
    asm volatile("tcgen05.fence::after_thread_sync;" ::: "memory")
#define TCGEN05_FENCE_BEFORE() \
    asm volatile("tcgen05.fence::before_thread_sync;" ::: "memory")
#define TCGEN05_WAIT_LD() \
    asm volatile("tcgen05.wait::ld.sync.aligned;" ::: "memory")
#define MBARRIER_INIT(mbar, cnt) \
    asm volatile("mbarrier.init.shared.b64 [%0], %1;" \
                 :: "r"((uint32_t)(mbar)), "r"((uint32_t)(cnt)) : "memory")
#define MBARRIER_INVAL(mbar) \
    asm volatile("mbarrier.inval.shared.b64 [%0];" :: "r"((uint32_t)(mbar)) : "memory")
#define FENCE_PROXY_ASYNC() \
    asm volatile("fence.proxy.async.shared::cta;" ::: "memory")

#define MBARRIER_WAIT_PARITY(mbar_smem_addr, phase_parity) do { \
    uint32_t _mbar = (uint32_t)(mbar_smem_addr); \
    uint32_t _parity = (uint32_t)(phase_parity); \
    uint32_t _done; \
    asm volatile("{\n\t.reg .pred p;\n\t" \
        "mbarrier.try_wait.parity.acquire.cta.shared::cta.b64 p, [%1], %2;\n\t" \
        "selp.b32 %0, 1, 0, p;\n\t}" \
        : "=r"(_done) : "r"(_mbar), "r"(_parity) : "memory"); \
    if (!_done) { \
        asm volatile("{\n\t.reg .pred P1;\n\t" \
            "WAIT_LOOP_%=:\n\t" \
            "mbarrier.try_wait.parity.acquire.cta.shared::cta.b64 P1, [%0], %1, 0x989680;\n\t" \
            "@P1 bra.uni WAIT_DONE_%=;\n\t" \
            "bra.uni WAIT_LOOP_%=;\n\t" \
            "WAIT_DONE_%=:\n\t}" \
            :: "r"(_mbar), "r"(_parity) : "memory"); \
    } \
} while(0)

#define TCGEN05_LD_32X32B_X32(r, tmem_addr) \
    asm volatile( \
        "tcgen05.ld.sync.aligned.32x32b.x32.b32 " \
        "{%0, %1, %2, %3, %4, %5, %6, %7, " \
        " %8, %9, %10, %11, %12, %13, %14, %15, " \
        " %16, %17, %18, %19, %20, %21, %22, %23, " \
        " %24, %25, %26, %27, %28, %29, %30, %31}, [%32];" \
        : "=r"((r)[0]),  "=r"((r)[1]),  "=r"((r)[2]),  "=r"((r)[3]), \
          "=r"((r)[4]),  "=r"((r)[5]),  "=r"((r)[6]),  "=r"((r)[7]), \
          "=r"((r)[8]),  "=r"((r)[9]),  "=r"((r)[10]), "=r"((r)[11]), \
          "=r"((r)[12]), "=r"((r)[13]), "=r"((r)[14]), "=r"((r)[15]), \
          "=r"((r)[16]), "=r"((r)[17]), "=r"((r)[18]), "=r"((r)[19]), \
          "=r"((r)[20]), "=r"((r)[21]), "=r"((r)[22]), "=r"((r)[23]), \
          "=r"((r)[24]), "=r"((r)[25]), "=r"((r)[26]), "=r"((r)[27]), \
          "=r"((r)[28]), "=r"((r)[29]), "=r"((r)[30]), "=r"((r)[31]) \
        : "r"(tmem_addr))

static constexpr uint64_t SMEM_DESC_BASE_SW128 =
    (uint64_t(2) << 61) | (uint64_t(1) << 46) | (uint64_t(64) << 32) | (uint64_t(1) << 16);
#define MAKE_SMEM_DESC(addr) (SMEM_DESC_BASE_SW128 | ((uint64_t)((addr) >> 4) & 0x3FFF))

// kind::f16 MMA; idesc selects bf16 vs fp16 operand types
__device__ __forceinline__ void mma_f16_ss(uint32_t d_tmem, uint64_t a_desc,
                                           uint64_t b_desc, uint32_t idesc,
                                           uint32_t enable_d) {
    uint32_t z = 0;
    asm volatile(
        "{\n\t.reg .pred p;\n\tsetp.ne.u32 p, %5, 0;\n\t"
        "tcgen05.mma.cta_group::1.kind::f16 [%0], %1, %2, %3, {%4, %4, %4, %4}, p;\n\t}"
        :: "r"(d_tmem), "l"(a_desc), "l"(b_desc), "r"(idesc), "r"(z), "r"(enable_d)
        : "memory");
}
#define mma_bf16_ss mma_f16_ss
#endif // TC_PATH

// ---------------------------------------------------------------------------
// Shared epilogue value transform
// ---------------------------------------------------------------------------
__device__ __forceinline__ void store_split3(__nv_bfloat16* op, int N,
                                             float v0, float v1) {
    __nv_bfloat16 h0 = __float2bfloat16_rn(v0);
    __nv_bfloat16 h1 = __float2bfloat16_rn(v1);
    uint32_t hp = pack_raw(h0, h1);
    uint32_t lp = pack_bf16x2(v0 - __bfloat162float(h0), v1 - __bfloat162float(h1));
    *reinterpret_cast<uint32_t*>(op) = hp;
    *reinterpret_cast<uint32_t*>(op + N) = lp;
    *reinterpret_cast<uint32_t*>(op + 2 * N) = hp;
}

// ---------------------------------------------------------------------------
// Legacy HMMA 128x128 tile (compute_103 fallback only)
// ---------------------------------------------------------------------------
#define GBM 128
#define GBN 128
#define GBK 64
#define RSTRIDE 36
#define ABUF (128 * RSTRIDE)
#define BBUF (128 * RSTRIDE)
#define GEMM_SMEM_BYTES 99328

#if !TC_PATH
__device__ void legacy_tile128(
    const __nv_bfloat16* __restrict__ A3, const __nv_bfloat16* __restrict__ B3,
    const float* __restrict__ bias, float* __restrict__ C,
    __nv_bfloat16* __restrict__ out3,
    int N, int K3, float alpha, int do_relu,
    int m0, int n0, uint32_t* sm, uint32_t smb)
{
    const int tid = threadIdx.x;
    const int wid = tid >> 5, lane = tid & 31;
    const int g = lane >> 2, c4 = lane & 3;
    const int warp_m = wid >> 2;
    const int warp_n = wid & 3;

    const int srow = tid >> 1, spart = tid & 1;
    const __nv_bfloat16* aptr = A3 + (size_t)(m0 + srow) * K3 + spart * 32;
    const __nv_bfloat16* bptr = B3 + (size_t)(n0 + srow) * K3 + spart * 32;
    const uint32_t as_base = smb + (srow * RSTRIDE + spart * 16) * 4;
    const uint32_t bs_base = smb + (2 * ABUF + srow * RSTRIDE + spart * 16) * 4;

    const int NC = K3 / GBK;

    float acc[4][4][4];
    #pragma unroll
    for (int i = 0; i < 4; i++)
        #pragma unroll
        for (int j = 0; j < 4; j++)
            #pragma unroll
            for (int q = 0; q < 4; q++) acc[i][j][q] = 0.f;

    #pragma unroll
    for (int q = 0; q < 4; q++) cp16(as_base + q * 16, aptr + q * 8);
    #pragma unroll
    for (int q = 0; q < 4; q++) cp16(bs_base + q * 16, bptr + q * 8);
    cp_commit();

    for (int c = 0; c < NC; c++) {
        if (c + 1 < NC) {
            const int nb = (c + 1) & 1;
            const __nv_bfloat16* ap = aptr + (c + 1) * GBK;
            const __nv_bfloat16* bp = bptr + (c + 1) * GBK;
            #pragma unroll
            for (int q = 0; q < 4; q++)
                cp16(as_base + nb * ABUF * 4 + q * 16, ap + q * 8);
            #pragma unroll
            for (int q = 0; q < 4; q++)
                cp16(bs_base + nb * BBUF * 4 + q * 16, bp + q * 8);
            cp_commit();
            cp_wait<1>();
        } else {
            cp_wait<0>();
        }
        __syncthreads();

        const uint32_t* ab = sm + (c & 1) * ABUF;
        const uint32_t* bb = sm + 2 * ABUF + (c & 1) * BBUF;

        #pragma unroll
        for (int ks = 0; ks < 4; ks++) {
            const int kb = ks * 8;
            uint32_t af[4][4], bf[4][2];
            #pragma unroll
            for (int i = 0; i < 4; i++) {
                const uint32_t* p = ab + (warp_m * 64 + i * 16 + g) * RSTRIDE + kb + c4;
                af[i][0] = p[0];
                af[i][1] = p[8 * RSTRIDE];
                af[i][2] = p[4];
                af[i][3] = p[8 * RSTRIDE + 4];
            }
            #pragma unroll
            for (int j = 0; j < 4; j++) {
                const uint32_t* p = bb + (warp_n * 32 + j * 8 + g) * RSTRIDE + kb + c4;
                bf[j][0] = p[0];
                bf[j][1] = p[4];
            }
            #pragma unroll
            for (int i = 0; i < 4; i++)
                #pragma unroll
                for (int j = 0; j < 4; j++)
                    mma16(acc[i][j], af[i], bf[j]);
        }
        __syncthreads();
    }

    #pragma unroll
    for (int i = 0; i < 4; i++) {
        #pragma unroll
        for (int j = 0; j < 4; j++) {
            const int col = n0 + warp_n * 32 + j * 8 + c4 * 2;
            float b0v = 0.f, b1v = 0.f;
            if (bias) { b0v = bias[col]; b1v = bias[col + 1]; }
            float v0 = acc[i][j][0] * alpha + b0v;
            float v1 = acc[i][j][1] * alpha + b1v;
            float v2 = acc[i][j][2] * alpha + b0v;
            float v3 = acc[i][j][3] * alpha + b1v;
            if (do_relu) {
                v0 = fmaxf(v0, 0.f); v1 = fmaxf(v1, 0.f);
                v2 = fmaxf(v2, 0.f); v3 = fmaxf(v3, 0.f);
            }
            const int ra = m0 + warp_m * 64 + i * 16 + g;
            if (out3) {
                store_split3(out3 + (size_t)ra * 3 * N + col, N, v0, v1);
                store_split3(out3 + (size_t)(ra + 8) * 3 * N + col, N, v2, v3);
            } else {
                float2 lo = {v0, v1}, hi = {v2, v3};
                *reinterpret_cast<float2*>(C + (size_t)ra * N + col) = lo;
                *reinterpret_cast<float2*>(C + (size_t)(ra + 8) * N + col) = hi;
            }
        }
    }
}
#endif // !TC_PATH

// ---------------------------------------------------------------------------
// 128x128 bf16-split GEMM (N=1024 cases; 2 CTAs/SM)
// ---------------------------------------------------------------------------
__global__ __launch_bounds__(256, 2) void gemm_bf16_kernel(
    const __nv_bfloat16* __restrict__ A3, const __nv_bfloat16* __restrict__ B3,
    const float* __restrict__ bias, float* __restrict__ C,
    __nv_bfloat16* __restrict__ out3,
    int M, int N, int K3, float alpha, int do_relu)
{
#if TC_PATH
    extern __shared__ char smc[];
    const uint32_t smb = smem_u32(smc);
    const int tid = threadIdx.x;
    const int wid = tid >> 5, lane = tid & 31;
    const int m0 = blockIdx.x * GBM;
    const int n0 = blockIdx.y * GBN;

    const uint32_t sa[3] = {1024u, 1024u + 16384u, 1024u + 32768u};
    const uint32_t sb[3] = {1024u + 49152u, 1024u + 65536u, 1024u + 81920u};
    const uint32_t mb[3] = {smb + 8u, smb + 16u, smb + 24u};

    if (wid == 0) TCGEN05_ALLOC(smb, 128);
    if (tid == 0) { MBARRIER_INIT(mb[0], 1); MBARRIER_INIT(mb[1], 1); MBARRIER_INIT(mb[2], 1); }
    __syncthreads();
    uint32_t tmem;
    asm volatile("ld.shared.b32 %0, [%1];" : "=r"(tmem) : "r"(smb));
    if (wid == 0) TCGEN05_RELINQUISH();

    const uint32_t IDESC =
        (1u << 4) | (1u << 7) | (1u << 10) | ((GBN / 8) << 17) | ((GBM / 16) << 24);

    const int NC = K3 / GBK;
    const int r0s = tid >> 3;
    const int c8 = tid & 7;
    const __nv_bfloat16* abase = A3 + (size_t)(m0 + r0s) * K3 + c8 * 8;
    const __nv_bfloat16* bbase = B3 + (size_t)(n0 + r0s) * K3 + c8 * 8;
    const uint32_t swoff[4] = {
        SMEM_SWIZZLE_128B((uint32_t)((r0s +  0) * 128 + c8 * 16)),
        SMEM_SWIZZLE_128B((uint32_t)((r0s + 32) * 128 + c8 * 16)),
        SMEM_SWIZZLE_128B((uint32_t)((r0s + 64) * 128 + c8 * 16)),
        SMEM_SWIZZLE_128B((uint32_t)((r0s + 96) * 128 + c8 * 16))};

    auto stage_chunk = [&](int chunk, int buf) {
        #pragma unroll
        for (int it = 0; it < 4; it++) {
            cp16(smb + sa[buf] + swoff[it], abase + (size_t)it * 32 * K3 + chunk * GBK);
            cp16(smb + sb[buf] + swoff[it], bbase + (size_t)it * 32 * K3 + chunk * GBK);
        }
        cp_commit();
    };

    int ph[3] = {0, 0, 0};
    stage_chunk(0, 0);
    stage_chunk(1, 1);

    for (int c = 0; c < NC; c++) {
        const int b = c % 3;
        if (c + 2 < NC) {
            const int nb = (c + 2) % 3;
            if (c >= 1) { MBARRIER_WAIT_PARITY(mb[nb], ph[nb]); ph[nb] ^= 1; }
            stage_chunk(c + 2, nb);
            cp_wait<2>();
        } else if (c + 1 < NC) {
            cp_wait<1>();
        } else {
            cp_wait<0>();
        }
        __syncthreads();
        if (wid == 0 && elect_one_pred()) {
            FENCE_PROXY_ASYNC();
            const uint64_t ad = MAKE_SMEM_DESC(smb + sa[b]);
            const uint64_t bd = MAKE_SMEM_DESC(smb + sb[b]);
            #pragma unroll
            for (int ks = 0; ks < 4; ks++)
                mma_bf16_ss(tmem, ad + ks * 2, bd + ks * 2, IDESC,
                            (c > 0 || ks > 0) ? 1u : 0u);
            TCGEN05_COMMIT(mb[b]);
        }
    }
    MBARRIER_WAIT_PARITY(mb[(NC - 1) % 3], ph[(NC - 1) % 3]);
    TCGEN05_FENCE_AFTER();

    if (wid < 4) {
        const uint32_t lofs = (uint32_t)wid << 21;
        const int row = m0 + wid * 32 + lane;
        #pragma unroll
        for (int j = 0; j < 4; j++) {
            uint32_t r[32];
            TCGEN05_LD_32X32B_X32(r, tmem + j * 32 + lofs);
            TCGEN05_WAIT_LD();
            const float* bp = bias ? (bias + n0 + j * 32) : nullptr;
            if (out3) {
                __nv_bfloat16* op = out3 + (size_t)row * 3 * N + n0 + j * 32;
                #pragma unroll
                for (int q = 0; q < 32; q += 2) {
                    float v0 = __uint_as_float(r[q + 0]) * alpha;
                    float v1 = __uint_as_float(r[q + 1]) * alpha;
                    if (bp) { v0 += bp[q]; v1 += bp[q + 1]; }
                    if (do_relu) { v0 = fmaxf(v0, 0.f); v1 = fmaxf(v1, 0.f); }
                    store_split3(op + q, N, v0, v1);
                }
            } else {
                float* cp = C + (size_t)row * N + n0 + j * 32;
                #pragma unroll
                for (int q = 0; q < 32; q += 4) {
                    float v0 = __uint_as_float(r[q + 0]) * alpha;
                    float v1 = __uint_as_float(r[q + 1]) * alpha;
                    float v2 = __uint_as_float(r[q + 2]) * alpha;
                    float v3 = __uint_as_float(r[q + 3]) * alpha;
                    if (bp) { v0 += bp[q]; v1 += bp[q + 1]; v2 += bp[q + 2]; v3 += bp[q + 3]; }
                    if (do_relu) {
                        v0 = fmaxf(v0, 0.f); v1 = fmaxf(v1, 0.f);
                        v2 = fmaxf(v2, 0.f); v3 = fmaxf(v3, 0.f);
                    }
                    float4 o = {v0, v1, v2, v3};
                    *reinterpret_cast<float4*>(cp + q) = o;
                }
            }
        }
        TCGEN05_FENCE_BEFORE();
    }
    __syncthreads();
    if (tid == 0) { MBARRIER_INVAL(mb[0]); MBARRIER_INVAL(mb[1]); MBARRIER_INVAL(mb[2]); }
    __syncthreads();
    if (wid == 0) TCGEN05_DEALLOC(tmem, 128);
#else
    extern __shared__ uint32_t sm[];
    const uint32_t smb = smem_u32(sm);
    legacy_tile128(A3, B3, bias, C, out3, N, K3, alpha, do_relu,
                   blockIdx.x * GBM, blockIdx.y * GBN, sm, smb);
#endif
}

// ---------------------------------------------------------------------------
// 256x256 bf16-split GEMM (big-N cases: QKV, ff1)
// ---------------------------------------------------------------------------
#define G2K 64
#define G2_SMEM (1024 + 3 * 65536)   // 197632 B

__global__ __launch_bounds__(256, 1) void gemm256_kernel(
    const __nv_bfloat16* __restrict__ A3, const __nv_bfloat16* __restrict__ B3,
    const float* __restrict__ bias, float* __restrict__ C,
    __nv_bfloat16* __restrict__ out3,
    int M, int N, int K3, float alpha, int do_relu)
{
#if TC_PATH
    extern __shared__ char smc[];
    const uint32_t smb = smem_u32(smc);
    const int tid = threadIdx.x;
    const int wid = tid >> 5, lane = tid & 31;
    const int m0 = blockIdx.x * 256;
    const int n0 = blockIdx.y * 256;

    const uint32_t mb[3] = {smb + 8u, smb + 16u, smb + 24u};

    if (wid == 0) TCGEN05_ALLOC(smb, 512);
    if (tid == 0) { MBARRIER_INIT(mb[0], 1); MBARRIER_INIT(mb[1], 1); MBARRIER_INIT(mb[2], 1); }
    __syncthreads();
    uint32_t tmem;
    asm volatile("ld.shared.b32 %0, [%1];" : "=r"(tmem) : "r"(smb));
    if (wid == 0) TCGEN05_RELINQUISH();

    const uint32_t IDESC2 =
        (1u << 4) | (1u << 7) | (1u << 10) | ((256 / 8) << 17) | ((128 / 16) << 24);

    const int NC = K3 / G2K;
    const int r0s = tid >> 3;
    const int c8 = tid & 7;
    const __nv_bfloat16* abase = A3 + (size_t)(m0 + r0s) * K3 + c8 * 8;
    const __nv_bfloat16* bbase = B3 + (size_t)(n0 + r0s) * K3 + c8 * 8;
    uint32_t swoff[8];
    #pragma unroll
    for (int it = 0; it < 8; it++)
        swoff[it] = SMEM_SWIZZLE_128B((uint32_t)((r0s + it * 32) * 128 + c8 * 16));

    auto stage_chunk = [&](int chunk, int buf) {
        const uint32_t sa = smb + 1024u + (uint32_t)buf * 65536u;
        const uint32_t sbo = sa + 32768u;
        #pragma unroll
        for (int it = 0; it < 8; it++) {
            cp16(sa + swoff[it], abase + (size_t)it * 32 * K3 + chunk * G2K);
            cp16(sbo + swoff[it], bbase + (size_t)it * 32 * K3 + chunk * G2K);
        }
        cp_commit();
    };

    int ph[3] = {0, 0, 0};
    stage_chunk(0, 0);
    stage_chunk(1, 1);

    for (int c = 0; c < NC; c++) {
        const int b = c % 3;
        if (c + 2 < NC) {
            const int nb = (c + 2) % 3;
            if (c >= 1) { MBARRIER_WAIT_PARITY(mb[nb], ph[nb]); ph[nb] ^= 1; }
            stage_chunk(c + 2, nb);
            cp_wait<2>();
        } else if (c + 1 < NC) {
            cp_wait<1>();
        } else {
            cp_wait<0>();
        }
        __syncthreads();
        if (wid == 0 && elect_one_pred()) {
            FENCE_PROXY_ASYNC();
            const uint32_t sa = smb + 1024u + (uint32_t)b * 65536u;
            const uint64_t ad = MAKE_SMEM_DESC(sa);
            const uint64_t bd = MAKE_SMEM_DESC(sa + 32768u);
            #pragma unroll
            for (int ks = 0; ks < 4; ks++) {
                const uint32_t en = (c > 0 || ks > 0) ? 1u : 0u;
                mma_bf16_ss(tmem,       ad + ks * 2,        bd + ks * 2, IDESC2, en);
                mma_bf16_ss(tmem + 256, ad + 1024 + ks * 2, bd + ks * 2, IDESC2, en);
            }
            TCGEN05_COMMIT(mb[b]);
        }
    }
    MBARRIER_WAIT_PARITY(mb[(NC - 1) % 3], ph[(NC - 1) % 3]);
    TCGEN05_FENCE_AFTER();

    {
        const int mh = wid >> 2;
        const int w4 = wid & 3;
        const uint32_t lofs = (uint32_t)w4 << 21;
        const int row = m0 + mh * 128 + w4 * 32 + lane;
        #pragma unroll
        for (int j = 0; j < 8; j++) {
            uint32_t r[32];
            TCGEN05_LD_32X32B_X32(r, tmem + mh * 256 + j * 32 + lofs);
            TCGEN05_WAIT_LD();
            const float* bp = bias ? (bias + n0 + j * 32) : nullptr;
            if (out3) {
                __nv_bfloat16* op = out3 + (size_t)row * 3 * N + n0 + j * 32;
                #pragma unroll
                for (int q = 0; q < 32; q += 2) {
                    float v0 = __uint_as_float(r[q + 0]) * alpha;
                    float v1 = __uint_as_float(r[q + 1]) * alpha;
                    if (bp) { v0 += bp[q]; v1 += bp[q + 1]; }
                    if (do_relu) { v0 = fmaxf(v0, 0.f); v1 = fmaxf(v1, 0.f); }
                    store_split3(op + q, N, v0, v1);
                }
            } else {
                float* cp = C + (size_t)row * N + n0 + j * 32;
                #pragma unroll
                for (int q = 0; q < 32; q += 4) {
                    float v0 = __uint_as_float(r[q + 0]) * alpha;
                    float v1 = __uint_as_float(r[q + 1]) * alpha;
                    float v2 = __uint_as_float(r[q + 2]) * alpha;
                    float v3 = __uint_as_float(r[q + 3]) * alpha;
                    if (bp) { v0 += bp[q]; v1 += bp[q + 1]; v2 += bp[q + 2]; v3 += bp[q + 3]; }
                    if (do_relu) {
                        v0 = fmaxf(v0, 0.f); v1 = fmaxf(v1, 0.f);
                        v2 = fmaxf(v2, 0.f); v3 = fmaxf(v3, 0.f);
                    }
                    float4 o = {v0, v1, v2, v3};
                    *reinterpret_cast<float4*>(cp + q) = o;
                }
            }
        }
        TCGEN05_FENCE_BEFORE();
    }
    __syncthreads();
    if (tid == 0) { MBARRIER_INVAL(mb[0]); MBARRIER_INVAL(mb[1]); MBARRIER_INVAL(mb[2]); }
    __syncthreads();
    if (wid == 0) TCGEN05_DEALLOC(tmem, 512);
#else
    extern __shared__ uint32_t sm[];
    const uint32_t smb = smem_u32(sm);
    #pragma unroll
    for (int qm = 0; qm < 2; qm++)
        for (int qn = 0; qn < 2; qn++) {
            legacy_tile128(A3, B3, bias, C, out3, N, K3, alpha, do_relu,
                           blockIdx.x * 256 + qm * 128,
                           blockIdx.y * 256 + qn * 128, sm, smb);
            __syncthreads();
        }
#endif
}

// ---------------------------------------------------------------------------
// 256x256 fp16 GEMM (logits only). A [M,K] fp16, B [N,K] fp16, C fp32.
// Same staging geometry as bf16 gemm256: 64-elem (128B) chunks, SW128.
// ---------------------------------------------------------------------------
__global__ __launch_bounds__(256, 1) void gemm256h_kernel(
    const __half* __restrict__ A, const __half* __restrict__ Bm,
    float* __restrict__ C, int M, int N, int K)
{
#if TC_PATH
    extern __shared__ char smc[];
    const uint32_t smb = smem_u32(smc);
    const int tid = threadIdx.x;
    const int wid = tid >> 5, lane = tid & 31;
    const int m0 = blockIdx.x * 256;
    const int n0 = blockIdx.y * 256;

    const uint32_t mb[3] = {smb + 8u, smb + 16u, smb + 24u};

    if (wid == 0) TCGEN05_ALLOC(smb, 512);
    if (tid == 0) { MBARRIER_INIT(mb[0], 1); MBARRIER_INIT(mb[1], 1); MBARRIER_INIT(mb[2], 1); }
    __syncthreads();
    uint32_t tmem;
    asm volatile("ld.shared.b32 %0, [%1];" : "=r"(tmem) : "r"(smb));
    if (wid == 0) TCGEN05_RELINQUISH();

    // kind::f16 idesc with FP16 operands: dtype=F32(1), atype=btype=F16(0)
    const uint32_t IDESCH =
        (1u << 4) | ((256 / 8) << 17) | ((128 / 16) << 24);

    const int NC = K / 64;              // 64 fp16 per 128B row chunk
    const int r0s = tid >> 3;
    const int c8 = tid & 7;
    const __half* abase = A + (size_t)(m0 + r0s) * K + c8 * 8;
    const __half* bbase = Bm + (size_t)(n0 + r0s) * K + c8 * 8;
    uint32_t swoff[8];
    #pragma unroll
    for (int it = 0; it < 8; it++)
        swoff[it] = SMEM_SWIZZLE_128B((uint32_t)((r0s + it * 32) * 128 + c8 * 16));

    auto stage_chunk = [&](int chunk, int buf) {
        const uint32_t sa = smb + 1024u + (uint32_t)buf * 65536u;
        const uint32_t sbo = sa + 32768u;
        #pragma unroll
        for (int it = 0; it < 8; it++) {
            cp16(sa + swoff[it], abase + (size_t)it * 32 * K + chunk * 64);
            cp16(sbo + swoff[it], bbase + (size_t)it * 32 * K + chunk * 64);
        }
        cp_commit();
    };

    int ph[3] = {0, 0, 0};
    stage_chunk(0, 0);
    stage_chunk(1, 1);

    for (int c = 0; c < NC; c++) {
        const int b = c % 3;
        if (c + 2 < NC) {
            const int nb = (c + 2) % 3;
            if (c >= 1) { MBARRIER_WAIT_PARITY(mb[nb], ph[nb]); ph[nb] ^= 1; }
            stage_chunk(c + 2, nb);
            cp_wait<2>();
        } else if (c + 1 < NC) {
            cp_wait<1>();
        } else {
            cp_wait<0>();
        }
        __syncthreads();
        if (wid == 0 && elect_one_pred()) {
            FENCE_PROXY_ASYNC();
            const uint32_t sa = smb + 1024u + (uint32_t)b * 65536u;
            const uint64_t ad = MAKE_SMEM_DESC(sa);
            const uint64_t bd = MAKE_SMEM_DESC(sa + 32768u);
            #pragma unroll
            for (int ks = 0; ks < 4; ks++) {     // 4 x K16 = 64 elems
                const uint32_t en = (c > 0 || ks > 0) ? 1u : 0u;
                mma_f16_ss(tmem,       ad + ks * 2,        bd + ks * 2, IDESCH, en);
                mma_f16_ss(tmem + 256, ad + 1024 + ks * 2, bd + ks * 2, IDESCH, en);
            }
            TCGEN05_COMMIT(mb[b]);
        }
    }
    MBARRIER_WAIT_PARITY(mb[(NC - 1) % 3], ph[(NC - 1) % 3]);
    TCGEN05_FENCE_AFTER();

    {
        const int mh = wid >> 2;
        const int w4 = wid & 3;
        const uint32_t lofs = (uint32_t)w4 << 21;
        const int row = m0 + mh * 128 + w4 * 32 + lane;
        #pragma unroll
        for (int j = 0; j < 8; j++) {
            uint32_t r[32];
            TCGEN05_LD_32X32B_X32(r, tmem + mh * 256 + j * 32 + lofs);
            TCGEN05_WAIT_LD();
            float* cp = C + (size_t)row * N + n0 + j * 32;
            #pragma unroll
            for (int q = 0; q < 32; q += 4) {
                float4 o;
                o.x = __uint_as_float(r[q + 0]);
                o.y = __uint_as_float(r[q + 1]);
                o.z = __uint_as_float(r[q + 2]);
                o.w = __uint_as_float(r[q + 3]);
                *reinterpret_cast<float4*>(cp + q) = o;
            }
        }
        TCGEN05_FENCE_BEFORE();
    }
    __syncthreads();
    if (tid == 0) { MBARRIER_INVAL(mb[0]); MBARRIER_INVAL(mb[1]); MBARRIER_INVAL(mb[2]); }
    __syncthreads();
    if (wid == 0) TCGEN05_DEALLOC(tmem, 512);
#else
    // correctness-only fallback (never executes on sm_103a)
    const int m0 = blockIdx.x * 256;
    const int n0 = blockIdx.y * 256;
    for (int idx = threadIdx.x; idx < 256 * 256; idx += 256) {
        const int i = idx >> 8, j = idx & 255;
        const __half* a = A + (size_t)(m0 + i) * K;
        const __half* b = Bm + (size_t)(n0 + j) * K;
        float s = 0.f;
        for (int k = 0; k < K; k++) s += __half2float(a[k]) * __half2float(b[k]);
        C[(size_t)(m0 + i) * N + n0 + j] = s;
    }
#endif
}

// ---------------------------------------------------------------------------
// Tensor-core split-bf16 causal flash attention (fused-QKV input).
// Load-balanced: grid (8, 64); each block handles q-tile pair (x, 15-x).
// ---------------------------------------------------------------------------
#define AT_STRIDE 136
#define ATT_SMEM  (3 * 64 * AT_STRIDE * 2)   // 52224 B

__global__ __launch_bounds__(128, 3) void attn_mma_kernel(
    const float* __restrict__ Q, const float* __restrict__ Kg,
    const float* __restrict__ Vg, __nv_bfloat16* __restrict__ conc3)
{
    extern __shared__ __nv_bfloat16 sh[];
    __nv_bfloat16* Qs = sh;
    __nv_bfloat16* Ks = sh + 64 * AT_STRIDE;
    __nv_bfloat16* Vs = sh + 128 * AT_STRIDE;

    const int bh = blockIdx.y;
    const int b = bh >> 4, n = bh & 15;
    const int tid = threadIdx.x;
    const int wid = tid >> 5, lane = tid & 31;
    const int g = lane >> 2, c4 = lane & 3;
    const int row0 = wid * 16 + g;

    for (int half = 0; half < 2; half++) {
        const int qt = (half == 0) ? (int)blockIdx.x : 15 - (int)blockIdx.x;
        __syncthreads();

        {
            const int r = tid >> 1;
            const int dbase = (tid & 1) * 32;
            const float* qp = Q + ((size_t)(b * S_ + qt * 64 + r)) * QKVS + n * 64 + dbase;
            #pragma unroll
            for (int i = 0; i < 32; i += 4) {
                float4 f = *reinterpret_cast<const float4*>(qp + i);
                float vals[4] = {f.x, f.y, f.z, f.w};
                #pragma unroll
                for (int e = 0; e < 4; e++) {
                    __nv_bfloat16 hi = __float2bfloat16_rn(vals[e]);
                    Qs[r * AT_STRIDE + dbase + i + e] = hi;
                    Qs[r * AT_STRIDE + 64 + dbase + i + e] =
                        __float2bfloat16_rn(vals[e] - __bfloat162float(hi));
                }
            }
        }

        float m0 = -1e30f, m1 = -1e30f, l0 = 0.f, l1 = 0.f;
        float o[8][4];
        #pragma unroll
        for (int j = 0; j < 8; j++)
            #pragma unroll
            for (int q = 0; q < 4; q++) o[j][q] = 0.f;

        for (int kt = 0; kt <= qt; kt++) {
            __syncthreads();
            {
                const int r = tid >> 1;
                const int dbase = (tid & 1) * 32;
                const float* kp = Kg + ((size_t)(b * S_ + kt * 64 + r)) * QKVS + n * 64 + dbase;
                const float* vp = Vg + ((size_t)(b * S_ + kt * 64 + r)) * QKVS + n * 64 + dbase;
                #pragma unroll
                for (int i = 0; i < 32; i += 4) {
                    float4 fk = *reinterpret_cast<const float4*>(kp + i);
                    float4 fv = *reinterpret_cast<const float4*>(vp + i);
                    float kv[4] = {fk.x, fk.y, fk.z, fk.w};
                    float vv[4] = {fv.x, fv.y, fv.z, fv.w};
                    #pragma unroll
                    for (int e = 0; e < 4; e++) {
                        const int d = dbase + i + e;
                        __nv_bfloat16 kh = __float2bfloat16_rn(kv[e]);
                        Ks[r * AT_STRIDE + d] = kh;
                        Ks[r * AT_STRIDE + 64 + d] =
                            __float2bfloat16_rn(kv[e] - __bfloat162float(kh));
                        __nv_bfloat16 vh = __float2bfloat16_rn(vv[e]);
                        Vs[d * AT_STRIDE + r] = vh;
                        Vs[d * AT_STRIDE + 64 + r] =
                            __float2bfloat16_rn(vv[e] - __bfloat162float(vh));
                    }
                }
            }
            __syncthreads();

            float s[8][4];
            #pragma unroll
            for (int j = 0; j < 8; j++)
                #pragma unroll
                for (int q = 0; q < 4; q++) s[j][q] = 0.f;

            #pragma unroll
            for (int phs = 0; phs < 3; phs++) {
                const int aoff = (phs == 1) ? 64 : 0;
                const int boff = (phs == 2) ? 64 : 0;
                #pragma unroll
                for (int ks = 0; ks < 4; ks++) {
                    uint32_t a[4];
                    const __nv_bfloat16* ap = Qs + row0 * AT_STRIDE + aoff + ks * 16 + c4 * 2;
                    a[0] = *reinterpret_cast<const uint32_t*>(ap);
                    a[1] = *reinterpret_cast<const uint32_t*>(ap + 8 * AT_STRIDE);
                    a[2] = *reinterpret_cast<const uint32_t*>(ap + 8);
                    a[3] = *reinterpret_cast<const uint32_t*>(ap + 8 * AT_STRIDE + 8);
                    #pragma unroll
                    for (int j = 0; j < 8; j++) {
                        uint32_t bf[2];
                        const __nv_bfloat16* bp =
                            Ks + (8 * j + g) * AT_STRIDE + boff + ks * 16 + c4 * 2;
                        bf[0] = *reinterpret_cast<const uint32_t*>(bp);
                        bf[1] = *reinterpret_cast<const uint32_t*>(bp + 8);
                        mma16(s[j], a, bf);
                    }
                }
            }

            if (kt == qt) {
                #pragma unroll
                for (int j = 0; j < 8; j++) {
                    const int colb = 8 * j + 2 * c4;
                    if (colb     > row0)     s[j][0] = -1e30f;
                    if (colb + 1 > row0)     s[j][1] = -1e30f;
                    if (colb     > row0 + 8) s[j][2] = -1e30f;
                    if (colb + 1 > row0 + 8) s[j][3] = -1e30f;
                }
            }

            float rm0 = -1e30f, rm1 = -1e30f;
            #pragma unroll
            for (int j = 0; j < 8; j++) {
                rm0 = fmaxf(rm0, fmaxf(s[j][0], s[j][1]));
                rm1 = fmaxf(rm1, fmaxf(s[j][2], s[j][3]));
            }
            rm0 = fmaxf(rm0, __shfl_xor_sync(0xFFFFFFFFu, rm0, 1));
            rm0 = fmaxf(rm0, __shfl_xor_sync(0xFFFFFFFFu, rm0, 2));
            rm1 = fmaxf(rm1, __shfl_xor_sync(0xFFFFFFFFu, rm1, 1));
            rm1 = fmaxf(rm1, __shfl_xor_sync(0xFFFFFFFFu, rm1, 2));
            const float mn0 = fmaxf(m0, rm0), mn1 = fmaxf(m1, rm1);
            const float cr0 = __expf(m0 - mn0), cr1 = __expf(m1 - mn1);
            m0 = mn0; m1 = mn1;

            float ps0 = 0.f, ps1 = 0.f;
            uint32_t phi[8][2], plo[8][2];
            #pragma unroll
            for (int j = 0; j < 8; j++) {
                float p0 = __expf(s[j][0] - mn0);
                float p1 = __expf(s[j][1] - mn0);
                float p2 = __expf(s[j][2] - mn1);
                float p3 = __expf(s[j][3] - mn1);
                ps0 += p0 + p1; ps1 += p2 + p3;
                __nv_bfloat16 h0 = __float2bfloat16_rn(p0), h1 = __float2bfloat16_rn(p1);
                __nv_bfloat16 h2 = __float2bfloat16_rn(p2), h3 = __float2bfloat16_rn(p3);
                phi[j][0] = pack_raw(h0, h1);
                phi[j][1] = pack_raw(h2, h3);
                plo[j][0] = pack_bf16x2(p0 - __bfloat162float(h0), p1 - __bfloat162float(h1));
                plo[j][1] = pack_bf16x2(p2 - __bfloat162float(h2), p3 - __bfloat162float(h3));
            }
            ps0 += __shfl_xor_sync(0xFFFFFFFFu, ps0, 1);
            ps0 += __shfl_xor_sync(0xFFFFFFFFu, ps0, 2);
            ps1 += __shfl_xor_sync(0xFFFFFFFFu, ps1, 1);
            ps1 += __shfl_xor_sync(0xFFFFFFFFu, ps1, 2);
            l0 = l0 * cr0 + ps0;
            l1 = l1 * cr1 + ps1;
            #pragma unroll
            for (int j = 0; j < 8; j++) {
                o[j][0] *= cr0; o[j][1] *= cr0;
                o[j][2] *= cr1; o[j][3] *= cr1;
            }

            #pragma unroll
            for (int phs = 0; phs < 3; phs++) {
                const int voff = (phs == 2) ? 64 : 0;
                #pragma unroll
                for (int ks = 0; ks < 4; ks++) {
                    uint32_t a[4];
                    if (phs == 1) {
                        a[0] = plo[2 * ks][0]; a[1] = plo[2 * ks][1];
                        a[2] = plo[2 * ks + 1][0]; a[3] = plo[2 * ks + 1][1];
                    } else {
                        a[0] = phi[2 * ks][0]; a[1] = phi[2 * ks][1];
                        a[2] = phi[2 * ks + 1][0]; a[3] = phi[2 * ks + 1][1];
                    }
                    #pragma unroll
                    for (int j = 0; j < 8; j++) {
                        uint32_t bf[2];
                        const __nv_bfloat16* bp =
                            Vs + (8 * j + g) * AT_STRIDE + voff + ks * 16 + c4 * 2;
                        bf[0] = *reinterpret_cast<const uint32_t*>(bp);
                        bf[1] = *reinterpret_cast<const uint32_t*>(bp + 8);
                        mma16(o[j], a, bf);
                    }
                }
            }
        }

        const float inv0 = 1.f / l0, inv1 = 1.f / l1;
        const size_t r0 = (size_t)(b * S_ + qt * 64 + row0);
        __nv_bfloat16* o0 = conc3 + r0 * 3 * H_;
        __nv_bfloat16* o1 = conc3 + (r0 + 8) * 3 * H_;
        #pragma unroll
        for (int j = 0; j < 8; j++) {
            const int col = n * 64 + 8 * j + 2 * c4;
            store_split3(o0 + col, H_, o[j][0] * inv0, o[j][1] * inv0);
            store_split3(o1 + col, H_, o[j][2] * inv1, o[j][3] * inv1);
        }
    }
}

// ---------------------------------------------------------------------------
// Conversion / elementwise kernels
// ---------------------------------------------------------------------------
__global__ void gather_split_kernel(const int* __restrict__ x,
                                    const float* __restrict__ emb,
                                    __nv_bfloat16* __restrict__ out3)
{
    int idx = blockIdx.x * blockDim.x + threadIdx.x;
    if (idx >= M4 * E_) return;
    int i = idx / E_;
    int e = idx - i * E_;
    float v = emb[(size_t)x[i] * E_ + e];
    __nv_bfloat16 hi = __float2bfloat16_rn(v);
    __nv_bfloat16 lo = __float2bfloat16_rn(v - __bfloat162float(hi));
    size_t base = (size_t)i * 3 * E_;
    out3[base + e] = hi;
    out3[base + E_ + e] = lo;
    out3[base + 2 * E_ + e] = hi;
}

__global__ __launch_bounds__(256) void conv_wT_kernel(
    const float* __restrict__ W, __nv_bfloat16* __restrict__ out,
    int K, int N, float wscale)
{
    __shared__ float tile[32][33];
    const int tx = threadIdx.x & 31;
    const int ty = threadIdx.x >> 5;
    const int n0 = blockIdx.x * 32;
    const int k0 = blockIdx.y * 32;
    #pragma unroll
    for (int i = 0; i < 4; i++)
        tile[ty + i * 8][tx] = W[(size_t)(k0 + ty + i * 8) * N + n0 + tx];
    __syncthreads();
    #pragma unroll
    for (int i = 0; i < 4; i++) {
        const int nn = n0 + ty + i * 8;
        const int k = k0 + tx;
        float x = tile[tx][ty + i * 8] * wscale;
        __nv_bfloat16 hi = __float2bfloat16_rn(x);
        __nv_bfloat16 lo = __float2bfloat16_rn(x - __bfloat162float(hi));
        size_t base = (size_t)nn * 3 * K;
        out[base + k] = hi;
        out[base + K + k] = hi;
        out[base + 2 * K + k] = lo;
    }
}

// transpose + round to fp16 (for p_decoder)
__global__ __launch_bounds__(256) void conv_wTh_kernel(
    const float* __restrict__ W, __half* __restrict__ out, int K, int N)
{
    __shared__ float tile[32][33];
    const int tx = threadIdx.x & 31;
    const int ty = threadIdx.x >> 5;
    const int n0 = blockIdx.x * 32;
    const int k0 = blockIdx.y * 32;
    #pragma unroll
    for (int i = 0; i < 4; i++)
        tile[ty + i * 8][tx] = W[(size_t)(k0 + ty + i * 8) * N + n0 + tx];
    __syncthreads();
    #pragma unroll
    for (int i = 0; i < 4; i++) {
        const int nn = n0 + ty + i * 8;
        out[(size_t)nn * K + k0 + tx] = __float2half_rn(tile[tx][ty + i * 8]);
    }
}

__global__ void addpos_kernel(const float* __restrict__ xemb,
                              const float* __restrict__ pos11,
                              float* __restrict__ out,
                              __nv_bfloat16* __restrict__ out3)
{
    int idx = blockIdx.x * blockDim.x + threadIdx.x;
    if (idx >= M4 * H_) return;
    int i = idx / H_;
    int h = idx - i * H_;
    int s = i & (S_ - 1);
    float y = xemb[idx] + pos11[(size_t)s * H_ + h];
    out[idx] = y;
    __nv_bfloat16 hi = __float2bfloat16_rn(y);
    __nv_bfloat16 lo = __float2bfloat16_rn(y - __bfloat162float(hi));
    size_t base = (size_t)i * 3 * H_;
    out3[base + h] = hi;
    out3[base + H_ + h] = lo;
    out3[base + 2 * H_ + h] = hi;
}

__global__ __launch_bounds__(256) void ln_res_kernel(
    const float* __restrict__ res, const float* __restrict__ x,
    const float* __restrict__ bias, const float* __restrict__ scale,
    float* __restrict__ out, __nv_bfloat16* __restrict__ out3)
{
    __shared__ float red[256];
    const int row = blockIdx.x;
    const int t = threadIdx.x;
    const float* xr = x + (size_t)row * H_;

    float lsum = 0.f;
    for (int i = t; i < H_; i += 256) lsum += xr[i];
    red[t] = lsum; __syncthreads();
    for (int s = 128; s > 0; s >>= 1) { if (t < s) red[t] += red[t + s]; __syncthreads(); }
    const float mean = red[0] * (1.0f / H_);
    __syncthreads();

    float lvar = 0.f;
    for (int i = t; i < H_; i += 256) { float d = xr[i] - mean; lvar += d * d; }
    red[t] = lvar; __syncthreads();
    for (int s = 128; s > 0; s >>= 1) { if (t < s) red[t] += red[t + s]; __syncthreads(); }
    const float rstd = rsqrtf(red[0] * (1.0f / H_) + 1e-6f);

    for (int i = t; i < H_; i += 256) {
        float y = res[(size_t)row * H_ + i] + (xr[i] - mean) * rstd * scale[i] + bias[i];
        out[(size_t)row * H_ + i] = y;
        if (out3) {
            __nv_bfloat16 hi = __float2bfloat16_rn(y);
            __nv_bfloat16 lo = __float2bfloat16_rn(y - __bfloat162float(hi));
            size_t base = (size_t)row * 3 * H_;
            out3[base + i] = hi;
            out3[base + H_ + i] = lo;
            out3[base + 2 * H_ + i] = hi;
        }
    }
}

// ---------------------------------------------------------------------------
// Fused double-LN (steps 9+10):
//   y1 = xself + LN(ffw2)*s1 + b1
//   decout = fp16(xemb + LN(y1)*s2 + b2)
// ---------------------------------------------------------------------------
__global__ __launch_bounds__(256) void ln2_res_kernel(
    const float* __restrict__ xself, const float* __restrict__ ffw2,
    const float* __restrict__ b1, const float* __restrict__ s1,
    const float* __restrict__ xemb,
    const float* __restrict__ b2, const float* __restrict__ s2,
    __half* __restrict__ decout)
{
    __shared__ float red[256];
    __shared__ float y1[H_];
    const int row = blockIdx.x;
    const int t = threadIdx.x;
    const float* xr = ffw2 + (size_t)row * H_;

    float lsum = 0.f;
    for (int i = t; i < H_; i += 256) lsum += xr[i];
    red[t] = lsum; __syncthreads();
    for (int s = 128; s > 0; s >>= 1) { if (t < s) red[t] += red[t + s]; __syncthreads(); }
    const float mean = red[0] * (1.0f / H_);
    __syncthreads();

    float lvar = 0.f;
    for (int i = t; i < H_; i += 256) { float d = xr[i] - mean; lvar += d * d; }
    red[t] = lvar; __syncthreads();
    for (int s = 128; s > 0; s >>= 1) { if (t < s) red[t] += red[t + s]; __syncthreads(); }
    const float rstd = rsqrtf(red[0] * (1.0f / H_) + 1e-6f);
    __syncthreads();

    for (int i = t; i < H_; i += 256)
        y1[i] = xself[(size_t)row * H_ + i] + (xr[i] - mean) * rstd * s1[i] + b1[i];
    __syncthreads();

    float lsum2 = 0.f;
    for (int i = t; i < H_; i += 256) lsum2 += y1[i];
    red[t] = lsum2; __syncthreads();
    for (int s = 128; s > 0; s >>= 1) { if (t < s) red[t] += red[t + s]; __syncthreads(); }
    const float mean2 = red[0] * (1.0f / H_);
    __syncthreads();

    float lvar2 = 0.f;
    for (int i = t; i < H_; i += 256) { float d = y1[i] - mean2; lvar2 += d * d; }
    red[t] = lvar2; __syncthreads();
    for (int s = 128; s > 0; s >>= 1) { if (t < s) red[t] += red[t + s]; __syncthreads(); }
    const float rstd2 = rsqrtf(red[0] * (1.0f / H_) + 1e-6f);

    for (int i = t; i < H_; i += 256) {
        float y = xemb[(size_t)row * H_ + i] + (y1[i] - mean2) * rstd2 * s2[i] + b2[i];
        decout[(size_t)row * H_ + i] = __float2half_rn(y);
    }
}

// ---------------------------------------------------------------------------
// Launch helpers
// ---------------------------------------------------------------------------
static inline void run_gemm(const __nv_bfloat16* A3, const __nv_bfloat16* B3,
                            const float* bias, float* C, __nv_bfloat16* out3,
                            int M, int N, int K3, float alpha, int relu)
{
    dim3 grid(M / GBM, N / GBN);
    gemm_bf16_kernel<<<grid, 256, GEMM_SMEM_BYTES>>>(A3, B3, bias, C, out3,
                                                     M, N, K3, alpha, relu);
}
static inline void run_gemm256(const __nv_bfloat16* A3, const __nv_bfloat16* B3,
                               const float* bias, float* C, __nv_bfloat16* out3,
                               int M, int N, int K3, float alpha, int relu)
{
    dim3 grid(M / 256, N / 256);
    gemm256_kernel<<<grid, 256, G2_SMEM>>>(A3, B3, bias, C, out3,
                                           M, N, K3, alpha, relu);
}
static inline void run_gemm256h(const __half* A, const __half* Bm, float* C,
                                int M, int N, int K)
{
    dim3 grid(M / 256, N / 256);
    gemm256h_kernel<<<grid, 256, G2_SMEM>>>(A, Bm, C, M, N, K);
}
static inline void run_conv_wT(const float* W, __nv_bfloat16* out,
                               int K, int N, float wscale)
{
    dim3 grid(N / 32, K / 32);
    conv_wT_kernel<<<grid, 256>>>(W, out, K, N, wscale);
}

extern "C" void kernel_launch(void* const* d_in, const int* in_sizes, int n_in,
                              void* d_out, int out_size)
{
    const int*   x            = (const int*)  d_in[0];
    const float* emb_decode   = (const float*)d_in[1];
    const float* W_dec_lin    = (const float*)d_in[2];
    const float* p_decoder    = (const float*)d_in[3];
    const float* x_emb_pos    = (const float*)d_in[4];
    const float* p_d_q        = (const float*)d_in[5];
    const float* p_d_k        = (const float*)d_in[6];
    const float* p_d_v        = (const float*)d_in[7];
    const float* p_d_c        = (const float*)d_in[8];
    const float* p_d_ff1      = (const float*)d_in[9];
    const float* p_d_ff2      = (const float*)d_in[10];
    const float* b_d_ff1      = (const float*)d_in[11];
    const float* b_d_ff2      = (const float*)d_in[12];
    const float* d_o_bias     = (const float*)d_in[13];
    const float* d_o_scale    = (const float*)d_in[14];
    const float* b_d_bias_1   = (const float*)d_in[15];
    const float* b_d_bias_2   = (const float*)d_in[16];
    const float* b_d_scale_1  = (const float*)d_in[17];
    const float* b_d_scale_2  = (const float*)d_in[18];
    float* out = (float*)d_out;

    const int m = L_ - 1;   // only the last layer's result is observable

    cudaFuncSetAttribute(gemm_bf16_kernel,
                         cudaFuncAttributeMaxDynamicSharedMemorySize, GEMM_SMEM_BYTES);
    cudaFuncSetAttribute(gemm256_kernel,
                         cudaFuncAttributeMaxDynamicSharedMemorySize, G2_SMEM);
    cudaFuncSetAttribute(gemm256h_kernel,
                         cudaFuncAttributeMaxDynamicSharedMemorySize, G2_SMEM);
    cudaFuncSetAttribute(attn_mma_kernel,
                         cudaFuncAttributeMaxDynamicSharedMemorySize, ATT_SMEM);

    float *xemb, *layerin, *qkv, *xmulti, *xself, *ffw1, *ffw2;
    __half *decout, *wth;
    __nv_bfloat16 *a3_emb, *a3_li, *a3_conc, *a3_self, *a3_ffw1;
    __nv_bfloat16 *w3_dec, *w3_qkv, *w3_c, *w3_ff1, *w3_ff2;
    cudaGetSymbolAddress((void**)&xemb,    g_xemb);
    cudaGetSymbolAddress((void**)&layerin, g_layerin);
    cudaGetSymbolAddress((void**)&qkv,     g_qkv);
    cudaGetSymbolAddress((void**)&xmulti,  g_xmulti);
    cudaGetSymbolAddress((void**)&xself,   g_xself);
    cudaGetSymbolAddress((void**)&ffw1,    g_ffw1);
    cudaGetSymbolAddress((void**)&ffw2,    g_ffw2);
    cudaGetSymbolAddress((void**)&decout,  g_decout);
    cudaGetSymbolAddress((void**)&wth,     g_wth);
    cudaGetSymbolAddress((void**)&a3_emb,  g_a3_emb);
    cudaGetSymbolAddress((void**)&a3_li,   g_a3_li);
    cudaGetSymbolAddress((void**)&a3_conc, g_a3_conc);
    cudaGetSymbolAddress((void**)&a3_self, g_a3_self);
    cudaGetSymbolAddress((void**)&a3_ffw1, g_a3_ffw1);
    cudaGetSymbolAddress((void**)&w3_dec,  g_w3_dec);
    cudaGetSymbolAddress((void**)&w3_qkv,  g_w3_qkv);
    cudaGetSymbolAddress((void**)&w3_c,    g_w3_c);
    cudaGetSymbolAddress((void**)&w3_ff1,  g_w3_ff1);
    cudaGetSymbolAddress((void**)&w3_ff2,  g_w3_ff2);

    // weight conversions; Q weights pre-scaled by 1/sqrt(head)
    run_conv_wT(W_dec_lin, w3_dec, E_, H_, 1.f);
    run_conv_wT(p_d_q + (size_t)m * H_ * H_, w3_qkv, H_, H_, 0.125f);
    run_conv_wT(p_d_k + (size_t)m * H_ * H_, w3_qkv + (size_t)1024 * 3 * H_, H_, H_, 1.f);
    run_conv_wT(p_d_v + (size_t)m * H_ * H_, w3_qkv + (size_t)2048 * 3 * H_, H_, H_, 1.f);
    run_conv_wT(p_d_c + (size_t)m * H_ * H_, w3_c, H_, H_, 1.f);
    run_conv_wT(p_d_ff1 + (size_t)m * H_ * FF_, w3_ff1, H_, FF_, 1.f);
    run_conv_wT(p_d_ff2 + (size_t)m * FF_ * H_, w3_ff2, FF_, H_, 1.f);
    {   // p_decoder -> transposed fp16
        dim3 grid(V_ / 32, H_ / 32);
        conv_wTh_kernel<<<grid, 256>>>(p_decoder, wth, H_, V_);
    }

    // 1. gather embeddings + split (fused)
    gather_split_kernel<<<(M4 * E_ + 255) / 256, 256>>>(x, emb_decode, a3_emb);

    // 2. x_dec_embed = A_emb @ W_dec_lin   (128-tile: 256 CTAs, 2/SM)
    run_gemm(a3_emb, w3_dec, nullptr, xemb, nullptr, M4, H_, 3 * E_, 1.f, 0);

    // 3. layer_in = pos[11] + x_dec_embed  (+ fused split)
    addpos_kernel<<<(M4 * H_ + 255) / 256, 256>>>(
        xemb, x_emb_pos + (size_t)m * S_ * H_, layerin, a3_li);

    // 4. fused Q/K/V projection (256-tile: 192 CTAs)
    run_gemm256(a3_li, w3_qkv, nullptr, qkv, nullptr, M4, QKVS, 3 * H_, 1.f, 0);

    // 5. load-balanced tensor-core causal attention -> a3_conc
    attn_mma_kernel<<<dim3(S_ / 128, B_ * NH_), 128, ATT_SMEM>>>(
        qkv, qkv + 1024, qkv + 2048, a3_conc);

    // 6. x_multi = conc @ p_d_c  (128-tile)
    run_gemm(a3_conc, w3_c, nullptr, xmulti, nullptr, M4, H_, 3 * H_, 1.f, 0);

    // 7. x_self = layer_in + LN(x_multi)  (+ fused split)
    ln_res_kernel<<<M4, 256>>>(layerin, xmulti,
                               b_d_bias_1 + (size_t)m * H_,
                               b_d_scale_1 + (size_t)m * H_, xself, a3_self);

    // 8. FFN (ff1 on 256-tile: 256 CTAs; ff2 on 128-tile)
    run_gemm256(a3_self, w3_ff1, b_d_ff1 + (size_t)m * FF_, ffw1, a3_ffw1,
                M4, FF_, 3 * H_, 1.f, 1);
    run_gemm(a3_ffw1, w3_ff2, b_d_ff2 + (size_t)m * H_, ffw2, nullptr,
             M4, H_, 3 * FF_, 1.f, 0);

    // 9+10. fused double-LN -> fp16 decout
    ln2_res_kernel<<<M4, 256>>>(xself, ffw2,
                                b_d_bias_2 + (size_t)m * H_,
                                b_d_scale_2 + (size_t)m * H_,
                                xemb, d_o_bias, d_o_scale, decout);

    // 11. logits = dec_outputs @ p_decoder  (fp16 tcgen05, half the traffic)
    run_gemm256h(decout, wth, out, M4, V_, H_);
}

// round 16
// speedup vs baseline: 1.5741x; 1.2819x over previous
#include <cuda_runtime.h>
#include <cuda_bf16.h>
#include <cuda_fp16.h>
#include <cstdint>

// Problem constants
#define L_   12
#define NH_  16
#define H_   1024
#define FF_  4096
#define V_   32000
#define S_   1024
#define E_   128
#define B_   4
#define HEAD_ 64
#define M4   (B_ * S_)   // 4096 rows total
#define QKVS 3072        // fused qkv row stride (floats)

// Arch-feature dispatch: tcgen05 only legal in the sm_103a pass.
#if defined(__CUDA_ARCH__) && defined(__CUDA_ARCH_FEAT_SM103_ALL)
#define TC_PATH 1
#else
#define TC_PATH 0
#endif

// ---------------------------------------------------------------------------
// Scratch (device globals — allocation-free per harness rules)
// ---------------------------------------------------------------------------
__device__ float g_xemb   [M4 * H_];
__device__ float g_layerin[M4 * H_];
__device__ float g_qkv    [M4 * QKVS];
__device__ float g_xmulti [M4 * H_];
__device__ float g_xself  [M4 * H_];
__device__ float g_ffw2   [M4 * H_];
__device__ __align__(128) __half g_decout [M4 * H_];     // fp16 (feeds logits GEMM)
__device__ __align__(128) __half g_ah_self[M4 * H_];     // fp16 A for ff1
__device__ __align__(128) __half g_ah_ffw1[(size_t)M4 * FF_];  // fp16 ff1 out / ff2 A

// bf16 split-K3 operand buffers.  A' = [hi | lo | hi] (row-major, 3K cols),
// B' = [hi | hi | lo] as [N, 3K] (k-contiguous, i.e. transposed weight).
__device__ __align__(128) __nv_bfloat16 g_a3_emb [M4 * 3 * E_];
__device__ __align__(128) __nv_bfloat16 g_a3_li  [M4 * 3 * H_];
__device__ __align__(128) __nv_bfloat16 g_a3_conc[M4 * 3 * H_];

__device__ __align__(128) __nv_bfloat16 g_w3_dec [H_ * 3 * E_];
__device__ __align__(128) __nv_bfloat16 g_w3_qkv [(size_t)QKVS * 3 * H_];
__device__ __align__(128) __nv_bfloat16 g_w3_c   [H_ * 3 * H_];
// fp16 weights
__device__ __align__(128) __half g_wh_ff1 [(size_t)FF_ * H_];
__device__ __align__(128) __half g_wh_ff2 [(size_t)H_ * FF_];
__device__ __align__(128) __half g_wth [(size_t)V_ * H_];

// ---------------------------------------------------------------------------
// PTX helpers — baseline-legal
// ---------------------------------------------------------------------------
__device__ __forceinline__ uint32_t smem_u32(const void* p) {
    uint32_t a;
    asm("{ .reg .u64 t; cvta.to.shared.u64 t, %1; cvt.u32.u64 %0, t; }"
        : "=r"(a) : "l"(p));
    return a;
}
__device__ __forceinline__ void cp16(uint32_t dst, const void* src) {
    asm volatile("cp.async.cg.shared.global [%0], [%1], 16;"
                 :: "r"(dst), "l"(src) : "memory");
}
__device__ __forceinline__ void cp_commit() {
    asm volatile("cp.async.commit_group;" ::: "memory");
}
template <int N>
__device__ __forceinline__ void cp_wait() {
    asm volatile("cp.async.wait_group %0;" :: "n"(N) : "memory");
}
__device__ __forceinline__ uint32_t elect_one_pred() {
    uint32_t pred;
    asm volatile(
        "{\n\t.reg .pred p;\n\telect.sync _|p, 0xFFFFFFFF;\n\t"
        "selp.b32 %0, 1, 0, p;\n\t}" : "=r"(pred));
    return pred;
}
// legacy m16n8k16 bf16 MMA, fp32 accumulate (sm_80+)
__device__ __forceinline__ void mma16(float* d, const uint32_t* a, const uint32_t* b) {
    asm volatile(
        "mma.sync.aligned.m16n8k16.row.col.f32.bf16.bf16.f32 "
        "{%0,%1,%2,%3}, {%4,%5,%6,%7}, {%8,%9}, {%0,%1,%2,%3};"
        : "+f"(d[0]), "+f"(d[1]), "+f"(d[2]), "+f"(d[3])
        : "r"(a[0]), "r"(a[1]), "r"(a[2]), "r"(a[3]),
          "r"(b[0]), "r"(b[1]));
}
__device__ __forceinline__ uint32_t pack_bf16x2(float lo_elem, float hi_elem) {
    uint32_t r;
    asm("cvt.rn.bf16x2.f32 %0, %1, %2;" : "=r"(r) : "f"(hi_elem), "f"(lo_elem));
    return r;
}
__device__ __forceinline__ uint32_t pack_raw(__nv_bfloat16 lo, __nv_bfloat16 hi) {
    return (uint32_t)__bfloat16_as_ushort(lo) | ((uint32_t)__bfloat16_as_ushort(hi) << 16);
}

#define SMEM_SWIZZLE_128B(o) ((o) ^ (((o) >> 3) & 0x70))

#if TC_PATH
// ---- tcgen05 helpers (only compiled in the sm_103a pass) ----
#define TCGEN05_ALLOC(smem_addr, nCols) \
    asm volatile("tcgen05.alloc.cta_group::1.sync.aligned.shared::cta.b32 [%0], %1;" \
                 :: "r"((uint32_t)(smem_addr)), "r"((uint32_t)(nCols)) : "memory")
#define TCGEN05_DEALLOC(tmem_addr, nCols) \
    asm volatile("tcgen05.dealloc.cta_group::1.sync.aligned.b32 %0, %1;" \
                 :: "r"(tmem_addr), "r"((uint32_t)(nCols)))
#define TCGEN05_RELINQUISH() \
    asm volatile("tcgen05.relinquish_alloc_permit.cta_group::1.sync.aligned;")
#define TCGEN05_COMMIT(mbar) \
    asm volatile("tcgen05.commit.cta_group::1.mbarrier::arrive::one.shared::cluster.b64 [%0];" \
                 :: "r"((uint32_t)(mbar)) : "memory")
#define TCGEN05_FENCE_AFTER() \
    asm volatile("tcgen05.fence::after_thread_sync;" ::: "memory")
#define TCGEN05_FENCE_BEFORE() \
    asm volatile("tcgen05.fence::before_thread_sync;" ::: "memory")
#define TCGEN05_WAIT_LD() \
    asm volatile("tcgen05.wait::ld.sync.aligned;" ::: "memory")
#define MBARRIER_INIT(mbar, cnt) \
    asm volatile("mbarrier.init.shared.b64 [%0], %1;" \
                 :: "r"((uint32_t)(mbar)), "r"((uint32_t)(cnt)) : "memory")
#define MBARRIER_INVAL(mbar) \
    asm volatile("mbarrier.inval.shared.b64 [%0];" :: "r"((uint32_t)(mbar)) : "memory")
#define FENCE_PROXY_ASYNC() \
    asm volatile("fence.proxy.async.shared::cta;" ::: "memory")

#define MBARRIER_WAIT_PARITY(mbar_smem_addr, phase_parity) do { \
    uint32_t _mbar = (uint32_t)(mbar_smem_addr); \
    uint32_t _parity = (uint32_t)(phase_parity); \
    uint32_t _done; \
    asm volatile("{\n\t.reg .pred p;\n\t" \
        "mbarrier.try_wait.parity.acquire.cta.shared::cta.b64 p, [%1], %2;\n\t" \
        "selp.b32 %0, 1, 0, p;\n\t}" \
        : "=r"(_done) : "r"(_mbar), "r"(_parity) : "memory"); \
    if (!_done) { \
        asm volatile("{\n\t.reg .pred P1;\n\t" \
            "WAIT_LOOP_%=:\n\t" \
            "mbarrier.try_wait.parity.acquire.cta.shared::cta.b64 P1, [%0], %1, 0x989680;\n\t" \
            "@P1 bra.uni WAIT_DONE_%=;\n\t" \
            "bra.uni WAIT_LOOP_%=;\n\t" \
            "WAIT_DONE_%=:\n\t}" \
            :: "r"(_mbar), "r"(_parity) : "memory"); \
    } \
} while(0)

#define TCGEN05_LD_32X32B_X32(r, tmem_addr) \
    asm volatile( \
        "tcgen05.ld.sync.aligned.32x32b.x32.b32 " \
        "{%0, %1, %2, %3, %4, %5, %6, %7, " \
        " %8, %9, %10, %11, %12, %13, %14, %15, " \
        " %16, %17, %18, %19, %20, %21, %22, %23, " \
        " %24, %25, %26, %27, %28, %29, %30, %31}, [%32];" \
        : "=r"((r)[0]),  "=r"((r)[1]),  "=r"((r)[2]),  "=r"((r)[3]), \
          "=r"((r)[4]),  "=r"((r)[5]),  "=r"((r)[6]),  "=r"((r)[7]), \
          "=r"((r)[8]),  "=r"((r)[9]),  "=r"((r)[10]), "=r"((r)[11]), \
          "=r"((r)[12]), "=r"((r)[13]), "=r"((r)[14]), "=r"((r)[15]), \
          "=r"((r)[16]), "=r"((r)[17]), "=r"((r)[18]), "=r"((r)[19]), \
          "=r"((r)[20]), "=r"((r)[21]), "=r"((r)[22]), "=r"((r)[23]), \
          "=r"((r)[24]), "=r"((r)[25]), "=r"((r)[26]), "=r"((r)[27]), \
          "=r"((r)[28]), "=r"((r)[29]), "=r"((r)[30]), "=r"((r)[31]) \
        : "r"(tmem_addr))

static constexpr uint64_t SMEM_DESC_BASE_SW128 =
    (uint64_t(2) << 61) | (uint64_t(1) << 46) | (uint64_t(64) << 32) | (uint64_t(1) << 16);
#define MAKE_SMEM_DESC(addr) (SMEM_DESC_BASE_SW128 | ((uint64_t)((addr) >> 4) & 0x3FFF))

// kind::f16 MMA; idesc selects bf16 vs fp16 operand types
__device__ __forceinline__ void mma_f16_ss(uint32_t d_tmem, uint64_t a_desc,
                                           uint64_t b_desc, uint32_t idesc,
                                           uint32_t enable_d) {
    uint32_t z = 0;
    asm volatile(
        "{\n\t.reg .pred p;\n\tsetp.ne.u32 p, %5, 0;\n\t"
        "tcgen05.mma.cta_group::1.kind::f16 [%0], %1, %2, %3, {%4, %4, %4, %4}, p;\n\t}"
        :: "r"(d_tmem), "l"(a_desc), "l"(b_desc), "r"(idesc), "r"(z), "r"(enable_d)
        : "memory");
}
#define mma_bf16_ss mma_f16_ss
#endif // TC_PATH

// ---------------------------------------------------------------------------
// Shared epilogue value transform
// ---------------------------------------------------------------------------
__device__ __forceinline__ void store_split3(__nv_bfloat16* op, int N,
                                             float v0, float v1) {
    __nv_bfloat16 h0 = __float2bfloat16_rn(v0);
    __nv_bfloat16 h1 = __float2bfloat16_rn(v1);
    uint32_t hp = pack_raw(h0, h1);
    uint32_t lp = pack_bf16x2(v0 - __bfloat162float(h0), v1 - __bfloat162float(h1));
    *reinterpret_cast<uint32_t*>(op) = hp;
    *reinterpret_cast<uint32_t*>(op + N) = lp;
    *reinterpret_cast<uint32_t*>(op + 2 * N) = hp;
}

// ---------------------------------------------------------------------------
// Legacy HMMA 128x128 tile (compute_103 fallback only)
// ---------------------------------------------------------------------------
#define GBM 128
#define GBN 128
#define GBK 64
#define RSTRIDE 36
#define ABUF (128 * RSTRIDE)
#define BBUF (128 * RSTRIDE)
#define GEMM_SMEM_BYTES 99328

#if !TC_PATH
__device__ void legacy_tile128(
    const __nv_bfloat16* __restrict__ A3, const __nv_bfloat16* __restrict__ B3,
    const float* __restrict__ bias, float* __restrict__ C,
    __nv_bfloat16* __restrict__ out3,
    int N, int K3, float alpha, int do_relu,
    int m0, int n0, uint32_t* sm, uint32_t smb)
{
    const int tid = threadIdx.x;
    const int wid = tid >> 5, lane = tid & 31;
    const int g = lane >> 2, c4 = lane & 3;
    const int warp_m = wid >> 2;
    const int warp_n = wid & 3;

    const int srow = tid >> 1, spart = tid & 1;
    const __nv_bfloat16* aptr = A3 + (size_t)(m0 + srow) * K3 + spart * 32;
    const __nv_bfloat16* bptr = B3 + (size_t)(n0 + srow) * K3 + spart * 32;
    const uint32_t as_base = smb + (srow * RSTRIDE + spart * 16) * 4;
    const uint32_t bs_base = smb + (2 * ABUF + srow * RSTRIDE + spart * 16) * 4;

    const int NC = K3 / GBK;

    float acc[4][4][4];
    #pragma unroll
    for (int i = 0; i < 4; i++)
        #pragma unroll
        for (int j = 0; j < 4; j++)
            #pragma unroll
            for (int q = 0; q < 4; q++) acc[i][j][q] = 0.f;

    #pragma unroll
    for (int q = 0; q < 4; q++) cp16(as_base + q * 16, aptr + q * 8);
    #pragma unroll
    for (int q = 0; q < 4; q++) cp16(bs_base + q * 16, bptr + q * 8);
    cp_commit();

    for (int c = 0; c < NC; c++) {
        if (c + 1 < NC) {
            const int nb = (c + 1) & 1;
            const __nv_bfloat16* ap = aptr + (c + 1) * GBK;
            const __nv_bfloat16* bp = bptr + (c + 1) * GBK;
            #pragma unroll
            for (int q = 0; q < 4; q++)
                cp16(as_base + nb * ABUF * 4 + q * 16, ap + q * 8);
            #pragma unroll
            for (int q = 0; q < 4; q++)
                cp16(bs_base + nb * BBUF * 4 + q * 16, bp + q * 8);
            cp_commit();
            cp_wait<1>();
        } else {
            cp_wait<0>();
        }
        __syncthreads();

        const uint32_t* ab = sm + (c & 1) * ABUF;
        const uint32_t* bb = sm + 2 * ABUF + (c & 1) * BBUF;

        #pragma unroll
        for (int ks = 0; ks < 4; ks++) {
            const int kb = ks * 8;
            uint32_t af[4][4], bf[4][2];
            #pragma unroll
            for (int i = 0; i < 4; i++) {
                const uint32_t* p = ab + (warp_m * 64 + i * 16 + g) * RSTRIDE + kb + c4;
                af[i][0] = p[0];
                af[i][1] = p[8 * RSTRIDE];
                af[i][2] = p[4];
                af[i][3] = p[8 * RSTRIDE + 4];
            }
            #pragma unroll
            for (int j = 0; j < 4; j++) {
                const uint32_t* p = bb + (warp_n * 32 + j * 8 + g) * RSTRIDE + kb + c4;
                bf[j][0] = p[0];
                bf[j][1] = p[4];
            }
            #pragma unroll
            for (int i = 0; i < 4; i++)
                #pragma unroll
                for (int j = 0; j < 4; j++)
                    mma16(acc[i][j], af[i], bf[j]);
        }
        __syncthreads();
    }

    #pragma unroll
    for (int i = 0; i < 4; i++) {
        #pragma unroll
        for (int j = 0; j < 4; j++) {
            const int col = n0 + warp_n * 32 + j * 8 + c4 * 2;
            float b0v = 0.f, b1v = 0.f;
            if (bias) { b0v = bias[col]; b1v = bias[col + 1]; }
            float v0 = acc[i][j][0] * alpha + b0v;
            float v1 = acc[i][j][1] * alpha + b1v;
            float v2 = acc[i][j][2] * alpha + b0v;
            float v3 = acc[i][j][3] * alpha + b1v;
            if (do_relu) {
                v0 = fmaxf(v0, 0.f); v1 = fmaxf(v1, 0.f);
                v2 = fmaxf(v2, 0.f); v3 = fmaxf(v3, 0.f);
            }
            const int ra = m0 + warp_m * 64 + i * 16 + g;
            if (out3) {
                store_split3(out3 + (size_t)ra * 3 * N + col, N, v0, v1);
                store_split3(out3 + (size_t)(ra + 8) * 3 * N + col, N, v2, v3);
            } else {
                float2 lo = {v0, v1}, hi = {v2, v3};
                *reinterpret_cast<float2*>(C + (size_t)ra * N + col) = lo;
                *reinterpret_cast<float2*>(C + (size_t)(ra + 8) * N + col) = hi;
            }
        }
    }
}
#endif // !TC_PATH

// ---------------------------------------------------------------------------
// 128x128 bf16-split GEMM (N=1024 cases; 2 CTAs/SM)
// ---------------------------------------------------------------------------
__global__ __launch_bounds__(256, 2) void gemm_bf16_kernel(
    const __nv_bfloat16* __restrict__ A3, const __nv_bfloat16* __restrict__ B3,
    const float* __restrict__ bias, float* __restrict__ C,
    __nv_bfloat16* __restrict__ out3,
    int M, int N, int K3, float alpha, int do_relu)
{
#if TC_PATH
    extern __shared__ char smc[];
    const uint32_t smb = smem_u32(smc);
    const int tid = threadIdx.x;
    const int wid = tid >> 5, lane = tid & 31;
    const int m0 = blockIdx.x * GBM;
    const int n0 = blockIdx.y * GBN;

    const uint32_t sa[3] = {1024u, 1024u + 16384u, 1024u + 32768u};
    const uint32_t sb[3] = {1024u + 49152u, 1024u + 65536u, 1024u + 81920u};
    const uint32_t mb[3] = {smb + 8u, smb + 16u, smb + 24u};

    if (wid == 0) TCGEN05_ALLOC(smb, 128);
    if (tid == 0) { MBARRIER_INIT(mb[0], 1); MBARRIER_INIT(mb[1], 1); MBARRIER_INIT(mb[2], 1); }
    __syncthreads();
    uint32_t tmem;
    asm volatile("ld.shared.b32 %0, [%1];" : "=r"(tmem) : "r"(smb));
    if (wid == 0) TCGEN05_RELINQUISH();

    const uint32_t IDESC =
        (1u << 4) | (1u << 7) | (1u << 10) | ((GBN / 8) << 17) | ((GBM / 16) << 24);

    const int NC = K3 / GBK;
    const int r0s = tid >> 3;
    const int c8 = tid & 7;
    const __nv_bfloat16* abase = A3 + (size_t)(m0 + r0s) * K3 + c8 * 8;
    const __nv_bfloat16* bbase = B3 + (size_t)(n0 + r0s) * K3 + c8 * 8;
    const uint32_t swoff[4] = {
        SMEM_SWIZZLE_128B((uint32_t)((r0s +  0) * 128 + c8 * 16)),
        SMEM_SWIZZLE_128B((uint32_t)((r0s + 32) * 128 + c8 * 16)),
        SMEM_SWIZZLE_128B((uint32_t)((r0s + 64) * 128 + c8 * 16)),
        SMEM_SWIZZLE_128B((uint32_t)((r0s + 96) * 128 + c8 * 16))};

    auto stage_chunk = [&](int chunk, int buf) {
        #pragma unroll
        for (int it = 0; it < 4; it++) {
            cp16(smb + sa[buf] + swoff[it], abase + (size_t)it * 32 * K3 + chunk * GBK);
            cp16(smb + sb[buf] + swoff[it], bbase + (size_t)it * 32 * K3 + chunk * GBK);
        }
        cp_commit();
    };

    int ph[3] = {0, 0, 0};
    stage_chunk(0, 0);
    stage_chunk(1, 1);

    for (int c = 0; c < NC; c++) {
        const int b = c % 3;
        if (c + 2 < NC) {
            const int nb = (c + 2) % 3;
            if (c >= 1) { MBARRIER_WAIT_PARITY(mb[nb], ph[nb]); ph[nb] ^= 1; }
            stage_chunk(c + 2, nb);
            cp_wait<2>();
        } else if (c + 1 < NC) {
            cp_wait<1>();
        } else {
            cp_wait<0>();
        }
        __syncthreads();
        if (wid == 0 && elect_one_pred()) {
            FENCE_PROXY_ASYNC();
            const uint64_t ad = MAKE_SMEM_DESC(smb + sa[b]);
            const uint64_t bd = MAKE_SMEM_DESC(smb + sb[b]);
            #pragma unroll
            for (int ks = 0; ks < 4; ks++)
                mma_bf16_ss(tmem, ad + ks * 2, bd + ks * 2, IDESC,
                            (c > 0 || ks > 0) ? 1u : 0u);
            TCGEN05_COMMIT(mb[b]);
        }
    }
    MBARRIER_WAIT_PARITY(mb[(NC - 1) % 3], ph[(NC - 1) % 3]);
    TCGEN05_FENCE_AFTER();

    if (wid < 4) {
        const uint32_t lofs = (uint32_t)wid << 21;
        const int row = m0 + wid * 32 + lane;
        #pragma unroll
        for (int j = 0; j < 4; j++) {
            uint32_t r[32];
            TCGEN05_LD_32X32B_X32(r, tmem + j * 32 + lofs);
            TCGEN05_WAIT_LD();
            const float* bp = bias ? (bias + n0 + j * 32) : nullptr;
            if (out3) {
                __nv_bfloat16* op = out3 + (size_t)row * 3 * N + n0 + j * 32;
                #pragma unroll
                for (int q = 0; q < 32; q += 2) {
                    float v0 = __uint_as_float(r[q + 0]) * alpha;
                    float v1 = __uint_as_float(r[q + 1]) * alpha;
                    if (bp) { v0 += bp[q]; v1 += bp[q + 1]; }
                    if (do_relu) { v0 = fmaxf(v0, 0.f); v1 = fmaxf(v1, 0.f); }
                    store_split3(op + q, N, v0, v1);
                }
            } else {
                float* cp = C + (size_t)row * N + n0 + j * 32;
                #pragma unroll
                for (int q = 0; q < 32; q += 4) {
                    float v0 = __uint_as_float(r[q + 0]) * alpha;
                    float v1 = __uint_as_float(r[q + 1]) * alpha;
                    float v2 = __uint_as_float(r[q + 2]) * alpha;
                    float v3 = __uint_as_float(r[q + 3]) * alpha;
                    if (bp) { v0 += bp[q]; v1 += bp[q + 1]; v2 += bp[q + 2]; v3 += bp[q + 3]; }
                    if (do_relu) {
                        v0 = fmaxf(v0, 0.f); v1 = fmaxf(v1, 0.f);
                        v2 = fmaxf(v2, 0.f); v3 = fmaxf(v3, 0.f);
                    }
                    float4 o = {v0, v1, v2, v3};
                    *reinterpret_cast<float4*>(cp + q) = o;
                }
            }
        }
        TCGEN05_FENCE_BEFORE();
    }
    __syncthreads();
    if (tid == 0) { MBARRIER_INVAL(mb[0]); MBARRIER_INVAL(mb[1]); MBARRIER_INVAL(mb[2]); }
    __syncthreads();
    if (wid == 0) TCGEN05_DEALLOC(tmem, 128);
#else
    extern __shared__ uint32_t sm[];
    const uint32_t smb = smem_u32(sm);
    legacy_tile128(A3, B3, bias, C, out3, N, K3, alpha, do_relu,
                   blockIdx.x * GBM, blockIdx.y * GBN, sm, smb);
#endif
}

// ---------------------------------------------------------------------------
// 256x256 bf16-split GEMM (QKV)
// ---------------------------------------------------------------------------
#define G2K 64
#define G2_SMEM (1024 + 3 * 65536)   // 197632 B

__global__ __launch_bounds__(256, 1) void gemm256_kernel(
    const __nv_bfloat16* __restrict__ A3, const __nv_bfloat16* __restrict__ B3,
    const float* __restrict__ bias, float* __restrict__ C,
    __nv_bfloat16* __restrict__ out3,
    int M, int N, int K3, float alpha, int do_relu)
{
#if TC_PATH
    extern __shared__ char smc[];
    const uint32_t smb = smem_u32(smc);
    const int tid = threadIdx.x;
    const int wid = tid >> 5, lane = tid & 31;
    const int m0 = blockIdx.x * 256;
    const int n0 = blockIdx.y * 256;

    const uint32_t mb[3] = {smb + 8u, smb + 16u, smb + 24u};

    if (wid == 0) TCGEN05_ALLOC(smb, 512);
    if (tid == 0) { MBARRIER_INIT(mb[0], 1); MBARRIER_INIT(mb[1], 1); MBARRIER_INIT(mb[2], 1); }
    __syncthreads();
    uint32_t tmem;
    asm volatile("ld.shared.b32 %0, [%1];" : "=r"(tmem) : "r"(smb));
    if (wid == 0) TCGEN05_RELINQUISH();

    const uint32_t IDESC2 =
        (1u << 4) | (1u << 7) | (1u << 10) | ((256 / 8) << 17) | ((128 / 16) << 24);

    const int NC = K3 / G2K;
    const int r0s = tid >> 3;
    const int c8 = tid & 7;
    const __nv_bfloat16* abase = A3 + (size_t)(m0 + r0s) * K3 + c8 * 8;
    const __nv_bfloat16* bbase = B3 + (size_t)(n0 + r0s) * K3 + c8 * 8;
    uint32_t swoff[8];
    #pragma unroll
    for (int it = 0; it < 8; it++)
        swoff[it] = SMEM_SWIZZLE_128B((uint32_t)((r0s + it * 32) * 128 + c8 * 16));

    auto stage_chunk = [&](int chunk, int buf) {
        const uint32_t sa = smb + 1024u + (uint32_t)buf * 65536u;
        const uint32_t sbo = sa + 32768u;
        #pragma unroll
        for (int it = 0; it < 8; it++) {
            cp16(sa + swoff[it], abase + (size_t)it * 32 * K3 + chunk * G2K);
            cp16(sbo + swoff[it], bbase + (size_t)it * 32 * K3 + chunk * G2K);
        }
        cp_commit();
    };

    int ph[3] = {0, 0, 0};
    stage_chunk(0, 0);
    stage_chunk(1, 1);

    for (int c = 0; c < NC; c++) {
        const int b = c % 3;
        if (c + 2 < NC) {
            const int nb = (c + 2) % 3;
            if (c >= 1) { MBARRIER_WAIT_PARITY(mb[nb], ph[nb]); ph[nb] ^= 1; }
            stage_chunk(c + 2, nb);
            cp_wait<2>();
        } else if (c + 1 < NC) {
            cp_wait<1>();
        } else {
            cp_wait<0>();
        }
        __syncthreads();
        if (wid == 0 && elect_one_pred()) {
            FENCE_PROXY_ASYNC();
            const uint32_t sa = smb + 1024u + (uint32_t)b * 65536u;
            const uint64_t ad = MAKE_SMEM_DESC(sa);
            const uint64_t bd = MAKE_SMEM_DESC(sa + 32768u);
            #pragma unroll
            for (int ks = 0; ks < 4; ks++) {
                const uint32_t en = (c > 0 || ks > 0) ? 1u : 0u;
                mma_bf16_ss(tmem,       ad + ks * 2,        bd + ks * 2, IDESC2, en);
                mma_bf16_ss(tmem + 256, ad + 1024 + ks * 2, bd + ks * 2, IDESC2, en);
            }
            TCGEN05_COMMIT(mb[b]);
        }
    }
    MBARRIER_WAIT_PARITY(mb[(NC - 1) % 3], ph[(NC - 1) % 3]);
    TCGEN05_FENCE_AFTER();

    {
        const int mh = wid >> 2;
        const int w4 = wid & 3;
        const uint32_t lofs = (uint32_t)w4 << 21;
        const int row = m0 + mh * 128 + w4 * 32 + lane;
        #pragma unroll
        for (int j = 0; j < 8; j++) {
            uint32_t r[32];
            TCGEN05_LD_32X32B_X32(r, tmem + mh * 256 + j * 32 + lofs);
            TCGEN05_WAIT_LD();
            const float* bp = bias ? (bias + n0 + j * 32) : nullptr;
            if (out3) {
                __nv_bfloat16* op = out3 + (size_t)row * 3 * N + n0 + j * 32;
                #pragma unroll
                for (int q = 0; q < 32; q += 2) {
                    float v0 = __uint_as_float(r[q + 0]) * alpha;
                    float v1 = __uint_as_float(r[q + 1]) * alpha;
                    if (bp) { v0 += bp[q]; v1 += bp[q + 1]; }
                    if (do_relu) { v0 = fmaxf(v0, 0.f); v1 = fmaxf(v1, 0.f); }
                    store_split3(op + q, N, v0, v1);
                }
            } else {
                float* cp = C + (size_t)row * N + n0 + j * 32;
                #pragma unroll
                for (int q = 0; q < 32; q += 4) {
                    float v0 = __uint_as_float(r[q + 0]) * alpha;
                    float v1 = __uint_as_float(r[q + 1]) * alpha;
                    float v2 = __uint_as_float(r[q + 2]) * alpha;
                    float v3 = __uint_as_float(r[q + 3]) * alpha;
                    if (bp) { v0 += bp[q]; v1 += bp[q + 1]; v2 += bp[q + 2]; v3 += bp[q + 3]; }
                    if (do_relu) {
                        v0 = fmaxf(v0, 0.f); v1 = fmaxf(v1, 0.f);
                        v2 = fmaxf(v2, 0.f); v3 = fmaxf(v3, 0.f);
                    }
                    float4 o = {v0, v1, v2, v3};
                    *reinterpret_cast<float4*>(cp + q) = o;
                }
            }
        }
        TCGEN05_FENCE_BEFORE();
    }
    __syncthreads();
    if (tid == 0) { MBARRIER_INVAL(mb[0]); MBARRIER_INVAL(mb[1]); MBARRIER_INVAL(mb[2]); }
    __syncthreads();
    if (wid == 0) TCGEN05_DEALLOC(tmem, 512);
#else
    extern __shared__ uint32_t sm[];
    const uint32_t smb = smem_u32(sm);
    #pragma unroll
    for (int qm = 0; qm < 2; qm++)
        for (int qn = 0; qn < 2; qn++) {
            legacy_tile128(A3, B3, bias, C, out3, N, K3, alpha, do_relu,
                           blockIdx.x * 256 + qm * 128,
                           blockIdx.y * 256 + qn * 128, sm, smb);
            __syncthreads();
        }
#endif
}

// ---------------------------------------------------------------------------
// 256x256 fp16 GEMM (logits, ff1, ff2). A [M,K] fp16, B [N,K] fp16.
// Output: fp32 C, or fp16 outh (with bias/relu applied).
// ---------------------------------------------------------------------------
__global__ __launch_bounds__(256, 1) void gemm256h_kernel(
    const __half* __restrict__ A, const __half* __restrict__ Bm,
    const float* __restrict__ bias, float* __restrict__ C,
    __half* __restrict__ outh, int M, int N, int K, int do_relu)
{
#if TC_PATH
    extern __shared__ char smc[];
    const uint32_t smb = smem_u32(smc);
    const int tid = threadIdx.x;
    const int wid = tid >> 5, lane = tid & 31;
    const int m0 = blockIdx.x * 256;
    const int n0 = blockIdx.y * 256;

    const uint32_t mb[3] = {smb + 8u, smb + 16u, smb + 24u};

    if (wid == 0) TCGEN05_ALLOC(smb, 512);
    if (tid == 0) { MBARRIER_INIT(mb[0], 1); MBARRIER_INIT(mb[1], 1); MBARRIER_INIT(mb[2], 1); }
    __syncthreads();
    uint32_t tmem;
    asm volatile("ld.shared.b32 %0, [%1];" : "=r"(tmem) : "r"(smb));
    if (wid == 0) TCGEN05_RELINQUISH();

    // kind::f16 idesc with FP16 operands: dtype=F32(1), atype=btype=F16(0)
    const uint32_t IDESCH =
        (1u << 4) | ((256 / 8) << 17) | ((128 / 16) << 24);

    const int NC = K / 64;              // 64 fp16 per 128B row chunk
    const int r0s = tid >> 3;
    const int c8 = tid & 7;
    const __half* abase = A + (size_t)(m0 + r0s) * K + c8 * 8;
    const __half* bbase = Bm + (size_t)(n0 + r0s) * K + c8 * 8;
    uint32_t swoff[8];
    #pragma unroll
    for (int it = 0; it < 8; it++)
        swoff[it] = SMEM_SWIZZLE_128B((uint32_t)((r0s + it * 32) * 128 + c8 * 16));

    auto stage_chunk = [&](int chunk, int buf) {
        const uint32_t sa = smb + 1024u + (uint32_t)buf * 65536u;
        const uint32_t sbo = sa + 32768u;
        #pragma unroll
        for (int it = 0; it < 8; it++) {
            cp16(sa + swoff[it], abase + (size_t)it * 32 * K + chunk * 64);
            cp16(sbo + swoff[it], bbase + (size_t)it * 32 * K + chunk * 64);
        }
        cp_commit();
    };

    int ph[3] = {0, 0, 0};
    stage_chunk(0, 0);
    stage_chunk(1, 1);

    for (int c = 0; c < NC; c++) {
        const int b = c % 3;
        if (c + 2 < NC) {
            const int nb = (c + 2) % 3;
            if (c >= 1) { MBARRIER_WAIT_PARITY(mb[nb], ph[nb]); ph[nb] ^= 1; }
            stage_chunk(c + 2, nb);
            cp_wait<2>();
        } else if (c + 1 < NC) {
            cp_wait<1>();
        } else {
            cp_wait<0>();
        }
        __syncthreads();
        if (wid == 0 && elect_one_pred()) {
            FENCE_PROXY_ASYNC();
            const uint32_t sa = smb + 1024u + (uint32_t)b * 65536u;
            const uint64_t ad = MAKE_SMEM_DESC(sa);
            const uint64_t bd = MAKE_SMEM_DESC(sa + 32768u);
            #pragma unroll
            for (int ks = 0; ks < 4; ks++) {     // 4 x K16 = 64 elems
                const uint32_t en = (c > 0 || ks > 0) ? 1u : 0u;
                mma_f16_ss(tmem,       ad + ks * 2,        bd + ks * 2, IDESCH, en);
                mma_f16_ss(tmem + 256, ad + 1024 + ks * 2, bd + ks * 2, IDESCH, en);
            }
            TCGEN05_COMMIT(mb[b]);
        }
    }
    MBARRIER_WAIT_PARITY(mb[(NC - 1) % 3], ph[(NC - 1) % 3]);
    TCGEN05_FENCE_AFTER();

    {
        const int mh = wid >> 2;
        const int w4 = wid & 3;
        const uint32_t lofs = (uint32_t)w4 << 21;
        const int row = m0 + mh * 128 + w4 * 32 + lane;
        #pragma unroll
        for (int j = 0; j < 8; j++) {
            uint32_t r[32];
            TCGEN05_LD_32X32B_X32(r, tmem + mh * 256 + j * 32 + lofs);
            TCGEN05_WAIT_LD();
            const float* bp = bias ? (bias + n0 + j * 32) : nullptr;
            if (outh) {
                __half* op = outh + (size_t)row * N + n0 + j * 32;
                #pragma unroll
                for (int q = 0; q < 32; q += 2) {
                    float v0 = __uint_as_float(r[q + 0]);
                    float v1 = __uint_as_float(r[q + 1]);
                    if (bp) { v0 += bp[q]; v1 += bp[q + 1]; }
                    if (do_relu) { v0 = fmaxf(v0, 0.f); v1 = fmaxf(v1, 0.f); }
                    __half2 h2 = __floats2half2_rn(v0, v1);
                    *reinterpret_cast<__half2*>(op + q) = h2;
                }
            } else {
                float* cp = C + (size_t)row * N + n0 + j * 32;
                #pragma unroll
                for (int q = 0; q < 32; q += 4) {
                    float v0 = __uint_as_float(r[q + 0]);
                    float v1 = __uint_as_float(r[q + 1]);
                    float v2 = __uint_as_float(r[q + 2]);
                    float v3 = __uint_as_float(r[q + 3]);
                    if (bp) { v0 += bp[q]; v1 += bp[q + 1]; v2 += bp[q + 2]; v3 += bp[q + 3]; }
                    if (do_relu) {
                        v0 = fmaxf(v0, 0.f); v1 = fmaxf(v1, 0.f);
                        v2 = fmaxf(v2, 0.f); v3 = fmaxf(v3, 0.f);
                    }
                    float4 o = {v0, v1, v2, v3};
                    *reinterpret_cast<float4*>(cp + q) = o;
                }
            }
        }
        TCGEN05_FENCE_BEFORE();
    }
    __syncthreads();
    if (tid == 0) { MBARRIER_INVAL(mb[0]); MBARRIER_INVAL(mb[1]); MBARRIER_INVAL(mb[2]); }
    __syncthreads();
    if (wid == 0) TCGEN05_DEALLOC(tmem, 512);
#else
    // correctness-only fallback (never executes on sm_103a)
    const int m0 = blockIdx.x * 256;
    const int n0 = blockIdx.y * 256;
    for (int idx = threadIdx.x; idx < 256 * 256; idx += 256) {
        const int i = idx >> 8, j = idx & 255;
        const __half* a = A + (size_t)(m0 + i) * K;
        const __half* b = Bm + (size_t)(n0 + j) * K;
        float s = 0.f;
        for (int k = 0; k < K; k++) s += __half2float(a[k]) * __half2float(b[k]);
        if (bias) s += bias[n0 + j];
        if (do_relu) s = fmaxf(s, 0.f);
        if (outh) outh[(size_t)(m0 + i) * N + n0 + j] = __float2half_rn(s);
        else      C[(size_t)(m0 + i) * N + n0 + j] = s;
    }
#endif
}

// ---------------------------------------------------------------------------
// Tensor-core split-bf16 causal flash attention (fused-QKV input).
// Load-balanced: grid (8, 64); each block handles q-tile pair (x, 15-x).
// ---------------------------------------------------------------------------
#define AT_STRIDE 136
#define ATT_SMEM  (3 * 64 * AT_STRIDE * 2)   // 52224 B

__global__ __launch_bounds__(128, 3) void attn_mma_kernel(
    const float* __restrict__ Q, const float* __restrict__ Kg,
    const float* __restrict__ Vg, __nv_bfloat16* __restrict__ conc3)
{
    extern __shared__ __nv_bfloat16 sh[];
    __nv_bfloat16* Qs = sh;
    __nv_bfloat16* Ks = sh + 64 * AT_STRIDE;
    __nv_bfloat16* Vs = sh + 128 * AT_STRIDE;

    const int bh = blockIdx.y;
    const int b = bh >> 4, n = bh & 15;
    const int tid = threadIdx.x;
    const int wid = tid >> 5, lane = tid & 31;
    const int g = lane >> 2, c4 = lane & 3;
    const int row0 = wid * 16 + g;

    for (int half = 0; half < 2; half++) {
        const int qt = (half == 0) ? (int)blockIdx.x : 15 - (int)blockIdx.x;
        __syncthreads();

        {
            const int r = tid >> 1;
            const int dbase = (tid & 1) * 32;
            const float* qp = Q + ((size_t)(b * S_ + qt * 64 + r)) * QKVS + n * 64 + dbase;
            #pragma unroll
            for (int i = 0; i < 32; i += 4) {
                float4 f = *reinterpret_cast<const float4*>(qp + i);
                float vals[4] = {f.x, f.y, f.z, f.w};
                #pragma unroll
                for (int e = 0; e < 4; e++) {
                    __nv_bfloat16 hi = __float2bfloat16_rn(vals[e]);
                    Qs[r * AT_STRIDE + dbase + i + e] = hi;
                    Qs[r * AT_STRIDE + 64 + dbase + i + e] =
                        __float2bfloat16_rn(vals[e] - __bfloat162float(hi));
                }
            }
        }

        float m0 = -1e30f, m1 = -1e30f, l0 = 0.f, l1 = 0.f;
        float o[8][4];
        #pragma unroll
        for (int j = 0; j < 8; j++)
            #pragma unroll
            for (int q = 0; q < 4; q++) o[j][q] = 0.f;

        for (int kt = 0; kt <= qt; kt++) {
            __syncthreads();
            {
                const int r = tid >> 1;
                const int dbase = (tid & 1) * 32;
                const float* kp = Kg + ((size_t)(b * S_ + kt * 64 + r)) * QKVS + n * 64 + dbase;
                const float* vp = Vg + ((size_t)(b * S_ + kt * 64 + r)) * QKVS + n * 64 + dbase;
                #pragma unroll
                for (int i = 0; i < 32; i += 4) {
                    float4 fk = *reinterpret_cast<const float4*>(kp + i);
                    float4 fv = *reinterpret_cast<const float4*>(vp + i);
                    float kv[4] = {fk.x, fk.y, fk.z, fk.w};
                    float vv[4] = {fv.x, fv.y, fv.z, fv.w};
                    #pragma unroll
                    for (int e = 0; e < 4; e++) {
                        const int d = dbase + i + e;
                        __nv_bfloat16 kh = __float2bfloat16_rn(kv[e]);
                        Ks[r * AT_STRIDE + d] = kh;
                        Ks[r * AT_STRIDE + 64 + d] =
                            __float2bfloat16_rn(kv[e] - __bfloat162float(kh));
                        __nv_bfloat16 vh = __float2bfloat16_rn(vv[e]);
                        Vs[d * AT_STRIDE + r] = vh;
                        Vs[d * AT_STRIDE + 64 + r] =
                            __float2bfloat16_rn(vv[e] - __bfloat162float(vh));
                    }
                }
            }
            __syncthreads();

            float s[8][4];
            #pragma unroll
            for (int j = 0; j < 8; j++)
                #pragma unroll
                for (int q = 0; q < 4; q++) s[j][q] = 0.f;

            #pragma unroll
            for (int phs = 0; phs < 3; phs++) {
                const int aoff = (phs == 1) ? 64 : 0;
                const int boff = (phs == 2) ? 64 : 0;
                #pragma unroll
                for (int ks = 0; ks < 4; ks++) {
                    uint32_t a[4];
                    const __nv_bfloat16* ap = Qs + row0 * AT_STRIDE + aoff + ks * 16 + c4 * 2;
                    a[0] = *reinterpret_cast<const uint32_t*>(ap);
                    a[1] = *reinterpret_cast<const uint32_t*>(ap + 8 * AT_STRIDE);
                    a[2] = *reinterpret_cast<const uint32_t*>(ap + 8);
                    a[3] = *reinterpret_cast<const uint32_t*>(ap + 8 * AT_STRIDE + 8);
                    #pragma unroll
                    for (int j = 0; j < 8; j++) {
                        uint32_t bf[2];
                        const __nv_bfloat16* bp =
                            Ks + (8 * j + g) * AT_STRIDE + boff + ks * 16 + c4 * 2;
                        bf[0] = *reinterpret_cast<const uint32_t*>(bp);
                        bf[1] = *reinterpret_cast<const uint32_t*>(bp + 8);
                        mma16(s[j], a, bf);
                    }
                }
            }

            if (kt == qt) {
                #pragma unroll
                for (int j = 0; j < 8; j++) {
                    const int colb = 8 * j + 2 * c4;
                    if (colb     > row0)     s[j][0] = -1e30f;
                    if (colb + 1 > row0)     s[j][1] = -1e30f;
                    if (colb     > row0 + 8) s[j][2] = -1e30f;
                    if (colb + 1 > row0 + 8) s[j][3] = -1e30f;
                }
            }

            float rm0 = -1e30f, rm1 = -1e30f;
            #pragma unroll
            for (int j = 0; j < 8; j++) {
                rm0 = fmaxf(rm0, fmaxf(s[j][0], s[j][1]));
                rm1 = fmaxf(rm1, fmaxf(s[j][2], s[j][3]));
            }
            rm0 = fmaxf(rm0, __shfl_xor_sync(0xFFFFFFFFu, rm0, 1));
            rm0 = fmaxf(rm0, __shfl_xor_sync(0xFFFFFFFFu, rm0, 2));
            rm1 = fmaxf(rm1, __shfl_xor_sync(0xFFFFFFFFu, rm1, 1));
            rm1 = fmaxf(rm1, __shfl_xor_sync(0xFFFFFFFFu, rm1, 2));
            const float mn0 = fmaxf(m0, rm0), mn1 = fmaxf(m1, rm1);
            const float cr0 = __expf(m0 - mn0), cr1 = __expf(m1 - mn1);
            m0 = mn0; m1 = mn1;

            float ps0 = 0.f, ps1 = 0.f;
            uint32_t phi[8][2], plo[8][2];
            #pragma unroll
            for (int j = 0; j < 8; j++) {
                float p0 = __expf(s[j][0] - mn0);
                float p1 = __expf(s[j][1] - mn0);
                float p2 = __expf(s[j][2] - mn1);
                float p3 = __expf(s[j][3] - mn1);
                ps0 += p0 + p1; ps1 += p2 + p3;
                __nv_bfloat16 h0 = __float2bfloat16_rn(p0), h1 = __float2bfloat16_rn(p1);
                __nv_bfloat16 h2 = __float2bfloat16_rn(p2), h3 = __float2bfloat16_rn(p3);
                phi[j][0] = pack_raw(h0, h1);
                phi[j][1] = pack_raw(h2, h3);
                plo[j][0] = pack_bf16x2(p0 - __bfloat162float(h0), p1 - __bfloat162float(h1));
                plo[j][1] = pack_bf16x2(p2 - __bfloat162float(h2), p3 - __bfloat162float(h3));
            }
            ps0 += __shfl_xor_sync(0xFFFFFFFFu, ps0, 1);
            ps0 += __shfl_xor_sync(0xFFFFFFFFu, ps0, 2);
            ps1 += __shfl_xor_sync(0xFFFFFFFFu, ps1, 1);
            ps1 += __shfl_xor_sync(0xFFFFFFFFu, ps1, 2);
            l0 = l0 * cr0 + ps0;
            l1 = l1 * cr1 + ps1;
            #pragma unroll
            for (int j = 0; j < 8; j++) {
                o[j][0] *= cr0; o[j][1] *= cr0;
                o[j][2] *= cr1; o[j][3] *= cr1;
            }

            #pragma unroll
            for (int phs = 0; phs < 3; phs++) {
                const int voff = (phs == 2) ? 64 : 0;
                #pragma unroll
                for (int ks = 0; ks < 4; ks++) {
                    uint32_t a[4];
                    if (phs == 1) {
                        a[0] = plo[2 * ks][0]; a[1] = plo[2 * ks][1];
                        a[2] = plo[2 * ks + 1][0]; a[3] = plo[2 * ks + 1][1];
                    } else {
                        a[0] = phi[2 * ks][0]; a[1] = phi[2 * ks][1];
                        a[2] = phi[2 * ks + 1][0]; a[3] = phi[2 * ks + 1][1];
                    }
                    #pragma unroll
                    for (int j = 0; j < 8; j++) {
                        uint32_t bf[2];
                        const __nv_bfloat16* bp =
                            Vs + (8 * j + g) * AT_STRIDE + voff + ks * 16 + c4 * 2;
                        bf[0] = *reinterpret_cast<const uint32_t*>(bp);
                        bf[1] = *reinterpret_cast<const uint32_t*>(bp + 8);
                        mma16(o[j], a, bf);
                    }
                }
            }
        }

        const float inv0 = 1.f / l0, inv1 = 1.f / l1;
        const size_t r0 = (size_t)(b * S_ + qt * 64 + row0);
        __nv_bfloat16* o0 = conc3 + r0 * 3 * H_;
        __nv_bfloat16* o1 = conc3 + (r0 + 8) * 3 * H_;
        #pragma unroll
        for (int j = 0; j < 8; j++) {
            const int col = n * 64 + 8 * j + 2 * c4;
            store_split3(o0 + col, H_, o[j][0] * inv0, o[j][1] * inv0);
            store_split3(o1 + col, H_, o[j][2] * inv1, o[j][3] * inv1);
        }
    }
}

// ---------------------------------------------------------------------------
// Conversion / elementwise kernels
// ---------------------------------------------------------------------------
__global__ void gather_split_kernel(const int* __restrict__ x,
                                    const float* __restrict__ emb,
                                    __nv_bfloat16* __restrict__ out3)
{
    int idx = blockIdx.x * blockDim.x + threadIdx.x;
    if (idx >= M4 * E_) return;
    int i = idx / E_;
    int e = idx - i * E_;
    float v = emb[(size_t)x[i] * E_ + e];
    __nv_bfloat16 hi = __float2bfloat16_rn(v);
    __nv_bfloat16 lo = __float2bfloat16_rn(v - __bfloat162float(hi));
    size_t base = (size_t)i * 3 * E_;
    out3[base + e] = hi;
    out3[base + E_ + e] = lo;
    out3[base + 2 * E_ + e] = hi;
}

__global__ __launch_bounds__(256) void conv_wT_kernel(
    const float* __restrict__ W, __nv_bfloat16* __restrict__ out,
    int K, int N, float wscale)
{
    __shared__ float tile[32][33];
    const int tx = threadIdx.x & 31;
    const int ty = threadIdx.x >> 5;
    const int n0 = blockIdx.x * 32;
    const int k0 = blockIdx.y * 32;
    #pragma unroll
    for (int i = 0; i < 4; i++)
        tile[ty + i * 8][tx] = W[(size_t)(k0 + ty + i * 8) * N + n0 + tx];
    __syncthreads();
    #pragma unroll
    for (int i = 0; i < 4; i++) {
        const int nn = n0 + ty + i * 8;
        const int k = k0 + tx;
        float x = tile[tx][ty + i * 8] * wscale;
        __nv_bfloat16 hi = __float2bfloat16_rn(x);
        __nv_bfloat16 lo = __float2bfloat16_rn(x - __bfloat162float(hi));
        size_t base = (size_t)nn * 3 * K;
        out[base + k] = hi;
        out[base + K + k] = hi;
        out[base + 2 * K + k] = lo;
    }
}

// transpose + round to fp16
__global__ __launch_bounds__(256) void conv_wTh_kernel(
    const float* __restrict__ W, __half* __restrict__ out, int K, int N)
{
    __shared__ float tile[32][33];
    const int tx = threadIdx.x & 31;
    const int ty = threadIdx.x >> 5;
    const int n0 = blockIdx.x * 32;
    const int k0 = blockIdx.y * 32;
    #pragma unroll
    for (int i = 0; i < 4; i++)
        tile[ty + i * 8][tx] = W[(size_t)(k0 + ty + i * 8) * N + n0 + tx];
    __syncthreads();
    #pragma unroll
    for (int i = 0; i < 4; i++) {
        const int nn = n0 + ty + i * 8;
        out[(size_t)nn * K + k0 + tx] = __float2half_rn(tile[tx][ty + i * 8]);
    }
}

__global__ void addpos_kernel(const float* __restrict__ xemb,
                              const float* __restrict__ pos11,
                              float* __restrict__ out,
                              __nv_bfloat16* __restrict__ out3)
{
    int idx = blockIdx.x * blockDim.x + threadIdx.x;
    if (idx >= M4 * H_) return;
    int i = idx / H_;
    int h = idx - i * H_;
    int s = i & (S_ - 1);
    float y = xemb[idx] + pos11[(size_t)s * H_ + h];
    out[idx] = y;
    __nv_bfloat16 hi = __float2bfloat16_rn(y);
    __nv_bfloat16 lo = __float2bfloat16_rn(y - __bfloat162float(hi));
    size_t base = (size_t)i * 3 * H_;
    out3[base + h] = hi;
    out3[base + H_ + h] = lo;
    out3[base + 2 * H_ + h] = hi;
}

// LN + residual; fp32 out + fp16 outh
__global__ __launch_bounds__(256) void ln_res_kernel(
    const float* __restrict__ res, const float* __restrict__ x,
    const float* __restrict__ bias, const float* __restrict__ scale,
    float* __restrict__ out, __half* __restrict__ outh)
{
    __shared__ float red[256];
    const int row = blockIdx.x;
    const int t = threadIdx.x;
    const float* xr = x + (size_t)row * H_;

    float lsum = 0.f;
    for (int i = t; i < H_; i += 256) lsum += xr[i];
    red[t] = lsum; __syncthreads();
    for (int s = 128; s > 0; s >>= 1) { if (t < s) red[t] += red[t + s]; __syncthreads(); }
    const float mean = red[0] * (1.0f / H_);
    __syncthreads();

    float lvar = 0.f;
    for (int i = t; i < H_; i += 256) { float d = xr[i] - mean; lvar += d * d; }
    red[t] = lvar; __syncthreads();
    for (int s = 128; s > 0; s >>= 1) { if (t < s) red[t] += red[t + s]; __syncthreads(); }
    const float rstd = rsqrtf(red[0] * (1.0f / H_) + 1e-6f);

    for (int i = t; i < H_; i += 256) {
        float y = res[(size_t)row * H_ + i] + (xr[i] - mean) * rstd * scale[i] + bias[i];
        out[(size_t)row * H_ + i] = y;
        if (outh) outh[(size_t)row * H_ + i] = __float2half_rn(y);
    }
}

// ---------------------------------------------------------------------------
// Fused double-LN (steps 9+10):
//   y1 = xself + LN(ffw2)*s1 + b1
//   decout = fp16(xemb + LN(y1)*s2 + b2)
// ---------------------------------------------------------------------------
__global__ __launch_bounds__(256) void ln2_res_kernel(
    const float* __restrict__ xself, const float* __restrict__ ffw2,
    const float* __restrict__ b1, const float* __restrict__ s1,
    const float* __restrict__ xemb,
    const float* __restrict__ b2, const float* __restrict__ s2,
    __half* __restrict__ decout)
{
    __shared__ float red[256];
    __shared__ float y1[H_];
    const int row = blockIdx.x;
    const int t = threadIdx.x;
    const float* xr = ffw2 + (size_t)row * H_;

    float lsum = 0.f;
    for (int i = t; i < H_; i += 256) lsum += xr[i];
    red[t] = lsum; __syncthreads();
    for (int s = 128; s > 0; s >>= 1) { if (t < s) red[t] += red[t + s]; __syncthreads(); }
    const float mean = red[0] * (1.0f / H_);
    __syncthreads();

    float lvar = 0.f;
    for (int i = t; i < H_; i += 256) { float d = xr[i] - mean; lvar += d * d; }
    red[t] = lvar; __syncthreads();
    for (int s = 128; s > 0; s >>= 1) { if (t < s) red[t] += red[t + s]; __syncthreads(); }
    const float rstd = rsqrtf(red[0] * (1.0f / H_) + 1e-6f);
    __syncthreads();

    for (int i = t; i < H_; i += 256)
        y1[i] = xself[(size_t)row * H_ + i] + (xr[i] - mean) * rstd * s1[i] + b1[i];
    __syncthreads();

    float lsum2 = 0.f;
    for (int i = t; i < H_; i += 256) lsum2 += y1[i];
    red[t] = lsum2; __syncthreads();
    for (int s = 128; s > 0; s >>= 1) { if (t < s) red[t] += red[t + s]; __syncthreads(); }
    const float mean2 = red[0] * (1.0f / H_);
    __syncthreads();

    float lvar2 = 0.f;
    for (int i = t; i < H_; i += 256) { float d = y1[i] - mean2; lvar2 += d * d; }
    red[t] = lvar2; __syncthreads();
    for (int s = 128; s > 0; s >>= 1) { if (t < s) red[t] += red[t + s]; __syncthreads(); }
    const float rstd2 = rsqrtf(red[0] * (1.0f / H_) + 1e-6f);

    for (int i = t; i < H_; i += 256) {
        float y = xemb[(size_t)row * H_ + i] + (y1[i] - mean2) * rstd2 * s2[i] + b2[i];
        decout[(size_t)row * H_ + i] = __float2half_rn(y);
    }
}

// ---------------------------------------------------------------------------
// Launch helpers
// ---------------------------------------------------------------------------
static inline void run_gemm(const __nv_bfloat16* A3, const __nv_bfloat16* B3,
                            const float* bias, float* C, __nv_bfloat16* out3,
                            int M, int N, int K3, float alpha, int relu)
{
    dim3 grid(M / GBM, N / GBN);
    gemm_bf16_kernel<<<grid, 256, GEMM_SMEM_BYTES>>>(A3, B3, bias, C, out3,
                                                     M, N, K3, alpha, relu);
}
static inline void run_gemm256(const __nv_bfloat16* A3, const __nv_bfloat16* B3,
                               const float* bias, float* C, __nv_bfloat16* out3,
                               int M, int N, int K3, float alpha, int relu)
{
    dim3 grid(M / 256, N / 256);
    gemm256_kernel<<<grid, 256, G2_SMEM>>>(A3, B3, bias, C, out3,
                                           M, N, K3, alpha, relu);
}
static inline void run_gemm256h(const __half* A, const __half* Bm,
                                const float* bias, float* C, __half* outh,
                                int M, int N, int K, int relu)
{
    dim3 grid(M / 256, N / 256);
    gemm256h_kernel<<<grid, 256, G2_SMEM>>>(A, Bm, bias, C, outh, M, N, K, relu);
}
static inline void run_conv_wT(const float* W, __nv_bfloat16* out,
                               int K, int N, float wscale)
{
    dim3 grid(N / 32, K / 32);
    conv_wT_kernel<<<grid, 256>>>(W, out, K, N, wscale);
}
static inline void run_conv_wTh(const float* W, __half* out, int K, int N)
{
    dim3 grid(N / 32, K / 32);
    conv_wTh_kernel<<<grid, 256>>>(W, out, K, N);
}

extern "C" void kernel_launch(void* const* d_in, const int* in_sizes, int n_in,
                              void* d_out, int out_size)
{
    const int*   x            = (const int*)  d_in[0];
    const float* emb_decode   = (const float*)d_in[1];
    const float* W_dec_lin    = (const float*)d_in[2];
    const float* p_decoder    = (const float*)d_in[3];
    const float* x_emb_pos    = (const float*)d_in[4];
    const float* p_d_q        = (const float*)d_in[5];
    const float* p_d_k        = (const float*)d_in[6];
    const float* p_d_v        = (const float*)d_in[7];
    const float* p_d_c        = (const float*)d_in[8];
    const float* p_d_ff1      = (const float*)d_in[9];
    const float* p_d_ff2      = (const float*)d_in[10];
    const float* b_d_ff1      = (const float*)d_in[11];
    const float* b_d_ff2      = (const float*)d_in[12];
    const float* d_o_bias     = (const float*)d_in[13];
    const float* d_o_scale    = (const float*)d_in[14];
    const float* b_d_bias_1   = (const float*)d_in[15];
    const float* b_d_bias_2   = (const float*)d_in[16];
    const float* b_d_scale_1  = (const float*)d_in[17];
    const float* b_d_scale_2  = (const float*)d_in[18];
    float* out = (float*)d_out;

    const int m = L_ - 1;   // only the last layer's result is observable

    cudaFuncSetAttribute(gemm_bf16_kernel,
                         cudaFuncAttributeMaxDynamicSharedMemorySize, GEMM_SMEM_BYTES);
    cudaFuncSetAttribute(gemm256_kernel,
                         cudaFuncAttributeMaxDynamicSharedMemorySize, G2_SMEM);
    cudaFuncSetAttribute(gemm256h_kernel,
                         cudaFuncAttributeMaxDynamicSharedMemorySize, G2_SMEM);
    cudaFuncSetAttribute(attn_mma_kernel,
                         cudaFuncAttributeMaxDynamicSharedMemorySize, ATT_SMEM);

    float *xemb, *layerin, *qkv, *xmulti, *xself, *ffw2;
    __half *decout, *ah_self, *ah_ffw1, *wh_ff1, *wh_ff2, *wth;
    __nv_bfloat16 *a3_emb, *a3_li, *a3_conc;
    __nv_bfloat16 *w3_dec, *w3_qkv, *w3_c;
    cudaGetSymbolAddress((void**)&xemb,    g_xemb);
    cudaGetSymbolAddress((void**)&layerin, g_layerin);
    cudaGetSymbolAddress((void**)&qkv,     g_qkv);
    cudaGetSymbolAddress((void**)&xmulti,  g_xmulti);
    cudaGetSymbolAddress((void**)&xself,   g_xself);
    cudaGetSymbolAddress((void**)&ffw2,    g_ffw2);
    cudaGetSymbolAddress((void**)&decout,  g_decout);
    cudaGetSymbolAddress((void**)&ah_self, g_ah_self);
    cudaGetSymbolAddress((void**)&ah_ffw1, g_ah_ffw1);
    cudaGetSymbolAddress((void**)&wh_ff1,  g_wh_ff1);
    cudaGetSymbolAddress((void**)&wh_ff2,  g_wh_ff2);
    cudaGetSymbolAddress((void**)&wth,     g_wth);
    cudaGetSymbolAddress((void**)&a3_emb,  g_a3_emb);
    cudaGetSymbolAddress((void**)&a3_li,   g_a3_li);
    cudaGetSymbolAddress((void**)&a3_conc, g_a3_conc);
    cudaGetSymbolAddress((void**)&w3_dec,  g_w3_dec);
    cudaGetSymbolAddress((void**)&w3_qkv,  g_w3_qkv);
    cudaGetSymbolAddress((void**)&w3_c,    g_w3_c);

    // weight conversions; Q weights pre-scaled by 1/sqrt(head)
    run_conv_wT(W_dec_lin, w3_dec, E_, H_, 1.f);
    run_conv_wT(p_d_q + (size_t)m * H_ * H_, w3_qkv, H_, H_, 0.125f);
    run_conv_wT(p_d_k + (size_t)m * H_ * H_, w3_qkv + (size_t)1024 * 3 * H_, H_, H_, 1.f);
    run_conv_wT(p_d_v + (size_t)m * H_ * H_, w3_qkv + (size_t)2048 * 3 * H_, H_, H_, 1.f);
    run_conv_wT(p_d_c + (size_t)m * H_ * H_, w3_c, H_, H_, 1.f);
    run_conv_wTh(p_d_ff1 + (size_t)m * H_ * FF_, wh_ff1, H_, FF_);
    run_conv_wTh(p_d_ff2 + (size_t)m * FF_ * H_, wh_ff2, FF_, H_);
    run_conv_wTh(p_decoder, wth, H_, V_);

    // 1. gather embeddings + split (fused)
    gather_split_kernel<<<(M4 * E_ + 255) / 256, 256>>>(x, emb_decode, a3_emb);

    // 2. x_dec_embed = A_emb @ W_dec_lin   (128-tile: 256 CTAs, 2/SM)
    run_gemm(a3_emb, w3_dec, nullptr, xemb, nullptr, M4, H_, 3 * E_, 1.f, 0);

    // 3. layer_in = pos[11] + x_dec_embed  (+ fused split)
    addpos_kernel<<<(M4 * H_ + 255) / 256, 256>>>(
        xemb, x_emb_pos + (size_t)m * S_ * H_, layerin, a3_li);

    // 4. fused Q/K/V projection (bf16-split 256-tile: 192 CTAs)
    run_gemm256(a3_li, w3_qkv, nullptr, qkv, nullptr, M4, QKVS, 3 * H_, 1.f, 0);

    // 5. load-balanced tensor-core causal attention -> a3_conc
    attn_mma_kernel<<<dim3(S_ / 128, B_ * NH_), 128, ATT_SMEM>>>(
        qkv, qkv + 1024, qkv + 2048, a3_conc);

    // 6. x_multi = conc @ p_d_c  (bf16-split 128-tile)
    run_gemm(a3_conc, w3_c, nullptr, xmulti, nullptr, M4, H_, 3 * H_, 1.f, 0);

    // 7. x_self = layer_in + LN(x_multi)  -> fp32 xself + fp16 ah_self
    ln_res_kernel<<<M4, 256>>>(layerin, xmulti,
                               b_d_bias_1 + (size_t)m * H_,
                               b_d_scale_1 + (size_t)m * H_, xself, ah_self);

    // 8. FFN — both legs fp16 tcgen05
    run_gemm256h(ah_self, wh_ff1, b_d_ff1 + (size_t)m * FF_,
                 nullptr, ah_ffw1, M4, FF_, H_, 1);
    run_gemm256h(ah_ffw1, wh_ff2, b_d_ff2 + (size_t)m * H_,
                 ffw2, nullptr, M4, H_, FF_, 0);

    // 9+10. fused double-LN -> fp16 decout
    ln2_res_kernel<<<M4, 256>>>(xself, ffw2,
                                b_d_bias_2 + (size_t)m * H_,
                                b_d_scale_2 + (size_t)m * H_,
                                xemb, d_o_bias, d_o_scale, decout);

    // 11. logits = dec_outputs @ p_decoder  (fp16 tcgen05)
    run_gemm256h(decout, wth, nullptr, out, nullptr, M4, V_, H_, 0);
}

// round 17
// speedup vs baseline: 1.6901x; 1.0737x over previous
#include <cuda_runtime.h>
#include <cuda_bf16.h>
#include <cuda_fp16.h>
#include <cstdint>

// Problem constants
#define L_   12
#define NH_  16
#define H_   1024
#define FF_  4096
#define V_   32000
#define S_   1024
#define E_   128
#define B_   4
#define HEAD_ 64
#define M4   (B_ * S_)   // 4096 rows total
#define QKVS 3072        // fused qkv row stride (floats)

// Arch-feature dispatch: tcgen05 only legal in the sm_103a pass.
#if defined(__CUDA_ARCH__) && defined(__CUDA_ARCH_FEAT_SM103_ALL)
#define TC_PATH 1
#else
#define TC_PATH 0
#endif

// ---------------------------------------------------------------------------
// Scratch (device globals — allocation-free per harness rules)
// ---------------------------------------------------------------------------
__device__ float g_xemb   [M4 * H_];
__device__ float g_layerin[M4 * H_];
__device__ float g_qkv    [M4 * QKVS];
__device__ float g_xmulti [M4 * H_];
__device__ float g_xself  [M4 * H_];
__device__ float g_ffw2   [M4 * H_];
__device__ __align__(128) __half g_decout [M4 * H_];
__device__ __align__(128) __half g_ah_emb [M4 * E_];
__device__ __align__(128) __half g_ah_li  [M4 * H_];
__device__ __align__(128) __half g_ah_conc[M4 * H_];
__device__ __align__(128) __half g_ah_self[M4 * H_];
__device__ __align__(128) __half g_ah_ffw1[(size_t)M4 * FF_];

// fp16 transposed weights ([N,K])
__device__ __align__(128) __half g_wh_dec [(size_t)H_ * E_];
__device__ __align__(128) __half g_wh_qkv [(size_t)QKVS * H_];
__device__ __align__(128) __half g_wh_c   [(size_t)H_ * H_];
__device__ __align__(128) __half g_wh_ff1 [(size_t)FF_ * H_];
__device__ __align__(128) __half g_wh_ff2 [(size_t)H_ * FF_];
__device__ __align__(128) __half g_wth    [(size_t)V_ * H_];

// ---------------------------------------------------------------------------
// PTX helpers — baseline-legal
// ---------------------------------------------------------------------------
__device__ __forceinline__ uint32_t smem_u32(const void* p) {
    uint32_t a;
    asm("{ .reg .u64 t; cvta.to.shared.u64 t, %1; cvt.u32.u64 %0, t; }"
        : "=r"(a) : "l"(p));
    return a;
}
__device__ __forceinline__ void cp16(uint32_t dst, const void* src) {
    asm volatile("cp.async.cg.shared.global [%0], [%1], 16;"
                 :: "r"(dst), "l"(src) : "memory");
}
__device__ __forceinline__ void cp_commit() {
    asm volatile("cp.async.commit_group;" ::: "memory");
}
template <int N>
__device__ __forceinline__ void cp_wait() {
    asm volatile("cp.async.wait_group %0;" :: "n"(N) : "memory");
}
__device__ __forceinline__ uint32_t elect_one_pred() {
    uint32_t pred;
    asm volatile(
        "{\n\t.reg .pred p;\n\telect.sync _|p, 0xFFFFFFFF;\n\t"
        "selp.b32 %0, 1, 0, p;\n\t}" : "=r"(pred));
    return pred;
}
// legacy m16n8k16 bf16 MMA, fp32 accumulate (sm_80+)  — used by attention
__device__ __forceinline__ void mma16(float* d, const uint32_t* a, const uint32_t* b) {
    asm volatile(
        "mma.sync.aligned.m16n8k16.row.col.f32.bf16.bf16.f32 "
        "{%0,%1,%2,%3}, {%4,%5,%6,%7}, {%8,%9}, {%0,%1,%2,%3};"
        : "+f"(d[0]), "+f"(d[1]), "+f"(d[2]), "+f"(d[3])
        : "r"(a[0]), "r"(a[1]), "r"(a[2]), "r"(a[3]),
          "r"(b[0]), "r"(b[1]));
}
__device__ __forceinline__ uint32_t pack_bf16x2(float lo_elem, float hi_elem) {
    uint32_t r;
    asm("cvt.rn.bf16x2.f32 %0, %1, %2;" : "=r"(r) : "f"(hi_elem), "f"(lo_elem));
    return r;
}
__device__ __forceinline__ uint32_t pack_raw(__nv_bfloat16 lo, __nv_bfloat16 hi) {
    return (uint32_t)__bfloat16_as_ushort(lo) | ((uint32_t)__bfloat16_as_ushort(hi) << 16);
}

#define SMEM_SWIZZLE_128B(o) ((o) ^ (((o) >> 3) & 0x70))

#if TC_PATH
// ---- tcgen05 helpers (only compiled in the sm_103a pass) ----
#define TCGEN05_ALLOC(smem_addr, nCols) \
    asm volatile("tcgen05.alloc.cta_group::1.sync.aligned.shared::cta.b32 [%0], %1;" \
                 :: "r"((uint32_t)(smem_addr)), "r"((uint32_t)(nCols)) : "memory")
#define TCGEN05_DEALLOC(tmem_addr, nCols) \
    asm volatile("tcgen05.dealloc.cta_group::1.sync.aligned.b32 %0, %1;" \
                 :: "r"(tmem_addr), "r"((uint32_t)(nCols)))
#define TCGEN05_RELINQUISH() \
    asm volatile("tcgen05.relinquish_alloc_permit.cta_group::1.sync.aligned;")
#define TCGEN05_COMMIT(mbar) \
    asm volatile("tcgen05.commit.cta_group::1.mbarrier::arrive::one.shared::cluster.b64 [%0];" \
                 :: "r"((uint32_t)(mbar)) : "memory")
#define TCGEN05_FENCE_AFTER() \
    asm volatile("tcgen05.fence::after_thread_sync;" ::: "memory")
#define TCGEN05_FENCE_BEFORE() \
    asm volatile("tcgen05.fence::before_thread_sync;" ::: "memory")
#define TCGEN05_WAIT_LD() \
    asm volatile("tcgen05.wait::ld.sync.aligned;" ::: "memory")
#define MBARRIER_INIT(mbar, cnt) \
    asm volatile("mbarrier.init.shared.b64 [%0], %1;" \
                 :: "r"((uint32_t)(mbar)), "r"((uint32_t)(cnt)) : "memory")
#define MBARRIER_INVAL(mbar) \
    asm volatile("mbarrier.inval.shared.b64 [%0];" :: "r"((uint32_t)(mbar)) : "memory")
#define FENCE_PROXY_ASYNC() \
    asm volatile("fence.proxy.async.shared::cta;" ::: "memory")

#define MBARRIER_WAIT_PARITY(mbar_smem_addr, phase_parity) do { \
    uint32_t _mbar = (uint32_t)(mbar_smem_addr); \
    uint32_t _parity = (uint32_t)(phase_parity); \
    uint32_t _done; \
    asm volatile("{\n\t.reg .pred p;\n\t" \
        "mbarrier.try_wait.parity.acquire.cta.shared::cta.b64 p, [%1], %2;\n\t" \
        "selp.b32 %0, 1, 0, p;\n\t}" \
        : "=r"(_done) : "r"(_mbar), "r"(_parity) : "memory"); \
    if (!_done) { \
        asm volatile("{\n\t.reg .pred P1;\n\t" \
            "WAIT_LOOP_%=:\n\t" \
            "mbarrier.try_wait.parity.acquire.cta.shared::cta.b64 P1, [%0], %1, 0x989680;\n\t" \
            "@P1 bra.uni WAIT_DONE_%=;\n\t" \
            "bra.uni WAIT_LOOP_%=;\n\t" \
            "WAIT_DONE_%=:\n\t}" \
            :: "r"(_mbar), "r"(_parity) : "memory"); \
    } \
} while(0)

#define TCGEN05_LD_32X32B_X32(r, tmem_addr) \
    asm volatile( \
        "tcgen05.ld.sync.aligned.32x32b.x32.b32 " \
        "{%0, %1, %2, %3, %4, %5, %6, %7, " \
        " %8, %9, %10, %11, %12, %13, %14, %15, " \
        " %16, %17, %18, %19, %20, %21, %22, %23, " \
        " %24, %25, %26, %27, %28, %29, %30, %31}, [%32];" \
        : "=r"((r)[0]),  "=r"((r)[1]),  "=r"((r)[2]),  "=r"((r)[3]), \
          "=r"((r)[4]),  "=r"((r)[5]),  "=r"((r)[6]),  "=r"((r)[7]), \
          "=r"((r)[8]),  "=r"((r)[9]),  "=r"((r)[10]), "=r"((r)[11]), \
          "=r"((r)[12]), "=r"((r)[13]), "=r"((r)[14]), "=r"((r)[15]), \
          "=r"((r)[16]), "=r"((r)[17]), "=r"((r)[18]), "=r"((r)[19]), \
          "=r"((r)[20]), "=r"((r)[21]), "=r"((r)[22]), "=r"((r)[23]), \
          "=r"((r)[24]), "=r"((r)[25]), "=r"((r)[26]), "=r"((r)[27]), \
          "=r"((r)[28]), "=r"((r)[29]), "=r"((r)[30]), "=r"((r)[31]) \
        : "r"(tmem_addr))

static constexpr uint64_t SMEM_DESC_BASE_SW128 =
    (uint64_t(2) << 61) | (uint64_t(1) << 46) | (uint64_t(64) << 32) | (uint64_t(1) << 16);
#define MAKE_SMEM_DESC(addr) (SMEM_DESC_BASE_SW128 | ((uint64_t)((addr) >> 4) & 0x3FFF))

__device__ __forceinline__ void mma_f16_ss(uint32_t d_tmem, uint64_t a_desc,
                                           uint64_t b_desc, uint32_t idesc,
                                           uint32_t enable_d) {
    uint32_t z = 0;
    asm volatile(
        "{\n\t.reg .pred p;\n\tsetp.ne.u32 p, %5, 0;\n\t"
        "tcgen05.mma.cta_group::1.kind::f16 [%0], %1, %2, %3, {%4, %4, %4, %4}, p;\n\t}"
        :: "r"(d_tmem), "l"(a_desc), "l"(b_desc), "r"(idesc), "r"(z), "r"(enable_d)
        : "memory");
}
#endif // TC_PATH

// ---------------------------------------------------------------------------
// 256x256 fp16 GEMM (all GEMMs). A [M,K] fp16, B [N,K] fp16.
// Output: fp32 C, or fp16 outh (bias/relu applied in either case).
// Requires K % 64 == 0, K/64 >= 2, M%256==0, N%256==0.
// ---------------------------------------------------------------------------
#define G2_SMEM (1024 + 3 * 65536)   // 197632 B

__global__ __launch_bounds__(256, 1) void gemm256h_kernel(
    const __half* __restrict__ A, const __half* __restrict__ Bm,
    const float* __restrict__ bias, float* __restrict__ C,
    __half* __restrict__ outh, int M, int N, int K, int do_relu)
{
#if TC_PATH
    extern __shared__ char smc[];
    const uint32_t smb = smem_u32(smc);
    const int tid = threadIdx.x;
    const int wid = tid >> 5, lane = tid & 31;
    const int m0 = blockIdx.x * 256;
    const int n0 = blockIdx.y * 256;

    const uint32_t mb[3] = {smb + 8u, smb + 16u, smb + 24u};

    if (wid == 0) TCGEN05_ALLOC(smb, 512);
    if (tid == 0) { MBARRIER_INIT(mb[0], 1); MBARRIER_INIT(mb[1], 1); MBARRIER_INIT(mb[2], 1); }
    __syncthreads();
    uint32_t tmem;
    asm volatile("ld.shared.b32 %0, [%1];" : "=r"(tmem) : "r"(smb));
    if (wid == 0) TCGEN05_RELINQUISH();

    // kind::f16 idesc with FP16 operands: dtype=F32(1), atype=btype=F16(0)
    const uint32_t IDESCH =
        (1u << 4) | ((256 / 8) << 17) | ((128 / 16) << 24);

    const int NC = K / 64;              // 64 fp16 per 128B row chunk
    const int r0s = tid >> 3;
    const int c8 = tid & 7;
    const __half* abase = A + (size_t)(m0 + r0s) * K + c8 * 8;
    const __half* bbase = Bm + (size_t)(n0 + r0s) * K + c8 * 8;
    uint32_t swoff[8];
    #pragma unroll
    for (int it = 0; it < 8; it++)
        swoff[it] = SMEM_SWIZZLE_128B((uint32_t)((r0s + it * 32) * 128 + c8 * 16));

    auto stage_chunk = [&](int chunk, int buf) {
        const uint32_t sa = smb + 1024u + (uint32_t)buf * 65536u;
        const uint32_t sbo = sa + 32768u;
        #pragma unroll
        for (int it = 0; it < 8; it++) {
            cp16(sa + swoff[it], abase + (size_t)it * 32 * K + chunk * 64);
            cp16(sbo + swoff[it], bbase + (size_t)it * 32 * K + chunk * 64);
        }
        cp_commit();
    };

    int ph[3] = {0, 0, 0};
    stage_chunk(0, 0);
    stage_chunk(1, 1);

    for (int c = 0; c < NC; c++) {
        const int b = c % 3;
        if (c + 2 < NC) {
            const int nb = (c + 2) % 3;
            if (c >= 1) { MBARRIER_WAIT_PARITY(mb[nb], ph[nb]); ph[nb] ^= 1; }
            stage_chunk(c + 2, nb);
            cp_wait<2>();
        } else if (c + 1 < NC) {
            cp_wait<1>();
        } else {
            cp_wait<0>();
        }
        __syncthreads();
        if (wid == 0 && elect_one_pred()) {
            FENCE_PROXY_ASYNC();
            const uint32_t sa = smb + 1024u + (uint32_t)b * 65536u;
            const uint64_t ad = MAKE_SMEM_DESC(sa);
            const uint64_t bd = MAKE_SMEM_DESC(sa + 32768u);
            #pragma unroll
            for (int ks = 0; ks < 4; ks++) {     // 4 x K16 = 64 elems
                const uint32_t en = (c > 0 || ks > 0) ? 1u : 0u;
                mma_f16_ss(tmem,       ad + ks * 2,        bd + ks * 2, IDESCH, en);
                mma_f16_ss(tmem + 256, ad + 1024 + ks * 2, bd + ks * 2, IDESCH, en);
            }
            TCGEN05_COMMIT(mb[b]);
        }
    }
    MBARRIER_WAIT_PARITY(mb[(NC - 1) % 3], ph[(NC - 1) % 3]);
    TCGEN05_FENCE_AFTER();

    {
        const int mh = wid >> 2;
        const int w4 = wid & 3;
        const uint32_t lofs = (uint32_t)w4 << 21;
        const int row = m0 + mh * 128 + w4 * 32 + lane;
        #pragma unroll
        for (int j = 0; j < 8; j++) {
            uint32_t r[32];
            TCGEN05_LD_32X32B_X32(r, tmem + mh * 256 + j * 32 + lofs);
            TCGEN05_WAIT_LD();
            const float* bp = bias ? (bias + n0 + j * 32) : nullptr;
            if (outh) {
                __half* op = outh + (size_t)row * N + n0 + j * 32;
                #pragma unroll
                for (int q = 0; q < 32; q += 2) {
                    float v0 = __uint_as_float(r[q + 0]);
                    float v1 = __uint_as_float(r[q + 1]);
                    if (bp) { v0 += bp[q]; v1 += bp[q + 1]; }
                    if (do_relu) { v0 = fmaxf(v0, 0.f); v1 = fmaxf(v1, 0.f); }
                    __half2 h2 = __floats2half2_rn(v0, v1);
                    *reinterpret_cast<__half2*>(op + q) = h2;
                }
            } else {
                float* cp = C + (size_t)row * N + n0 + j * 32;
                #pragma unroll
                for (int q = 0; q < 32; q += 4) {
                    float v0 = __uint_as_float(r[q + 0]);
                    float v1 = __uint_as_float(r[q + 1]);
                    float v2 = __uint_as_float(r[q + 2]);
                    float v3 = __uint_as_float(r[q + 3]);
                    if (bp) { v0 += bp[q]; v1 += bp[q + 1]; v2 += bp[q + 2]; v3 += bp[q + 3]; }
                    if (do_relu) {
                        v0 = fmaxf(v0, 0.f); v1 = fmaxf(v1, 0.f);
                        v2 = fmaxf(v2, 0.f); v3 = fmaxf(v3, 0.f);
                    }
                    float4 o = {v0, v1, v2, v3};
                    *reinterpret_cast<float4*>(cp + q) = o;
                }
            }
        }
        TCGEN05_FENCE_BEFORE();
    }
    __syncthreads();
    if (tid == 0) { MBARRIER_INVAL(mb[0]); MBARRIER_INVAL(mb[1]); MBARRIER_INVAL(mb[2]); }
    __syncthreads();
    if (wid == 0) TCGEN05_DEALLOC(tmem, 512);
#else
    // correctness-only fallback (never executes on sm_103a)
    const int m0 = blockIdx.x * 256;
    const int n0 = blockIdx.y * 256;
    for (int idx = threadIdx.x; idx < 256 * 256; idx += 256) {
        const int i = idx >> 8, j = idx & 255;
        const __half* a = A + (size_t)(m0 + i) * K;
        const __half* b = Bm + (size_t)(n0 + j) * K;
        float s = 0.f;
        for (int k = 0; k < K; k++) s += __half2float(a[k]) * __half2float(b[k]);
        if (bias) s += bias[n0 + j];
        if (do_relu) s = fmaxf(s, 0.f);
        if (outh) outh[(size_t)(m0 + i) * N + n0 + j] = __float2half_rn(s);
        else      C[(size_t)(m0 + i) * N + n0 + j] = s;
    }
#endif
}

// ---------------------------------------------------------------------------
// Tensor-core split-bf16 causal flash attention (fused-QKV input).
// Load-balanced: grid (8, 64); each block handles q-tile pair (x, 15-x).
// Writes plain fp16 conc [M4, H].
// ---------------------------------------------------------------------------
#define AT_STRIDE 136
#define ATT_SMEM  (3 * 64 * AT_STRIDE * 2)   // 52224 B

__global__ __launch_bounds__(128, 3) void attn_mma_kernel(
    const float* __restrict__ Q, const float* __restrict__ Kg,
    const float* __restrict__ Vg, __half* __restrict__ conc)
{
    extern __shared__ __nv_bfloat16 sh[];
    __nv_bfloat16* Qs = sh;
    __nv_bfloat16* Ks = sh + 64 * AT_STRIDE;
    __nv_bfloat16* Vs = sh + 128 * AT_STRIDE;

    const int bh = blockIdx.y;
    const int b = bh >> 4, n = bh & 15;
    const int tid = threadIdx.x;
    const int wid = tid >> 5, lane = tid & 31;
    const int g = lane >> 2, c4 = lane & 3;
    const int row0 = wid * 16 + g;

    for (int half = 0; half < 2; half++) {
        const int qt = (half == 0) ? (int)blockIdx.x : 15 - (int)blockIdx.x;
        __syncthreads();

        {
            const int r = tid >> 1;
            const int dbase = (tid & 1) * 32;
            const float* qp = Q + ((size_t)(b * S_ + qt * 64 + r)) * QKVS + n * 64 + dbase;
            #pragma unroll
            for (int i = 0; i < 32; i += 4) {
                float4 f = *reinterpret_cast<const float4*>(qp + i);
                float vals[4] = {f.x, f.y, f.z, f.w};
                #pragma unroll
                for (int e = 0; e < 4; e++) {
                    __nv_bfloat16 hi = __float2bfloat16_rn(vals[e]);
                    Qs[r * AT_STRIDE + dbase + i + e] = hi;
                    Qs[r * AT_STRIDE + 64 + dbase + i + e] =
                        __float2bfloat16_rn(vals[e] - __bfloat162float(hi));
                }
            }
        }

        float m0 = -1e30f, m1 = -1e30f, l0 = 0.f, l1 = 0.f;
        float o[8][4];
        #pragma unroll
        for (int j = 0; j < 8; j++)
            #pragma unroll
            for (int q = 0; q < 4; q++) o[j][q] = 0.f;

        for (int kt = 0; kt <= qt; kt++) {
            __syncthreads();
            {
                const int r = tid >> 1;
                const int dbase = (tid & 1) * 32;
                const float* kp = Kg + ((size_t)(b * S_ + kt * 64 + r)) * QKVS + n * 64 + dbase;
                const float* vp = Vg + ((size_t)(b * S_ + kt * 64 + r)) * QKVS + n * 64 + dbase;
                #pragma unroll
                for (int i = 0; i < 32; i += 4) {
                    float4 fk = *reinterpret_cast<const float4*>(kp + i);
                    float4 fv = *reinterpret_cast<const float4*>(vp + i);
                    float kv[4] = {fk.x, fk.y, fk.z, fk.w};
                    float vv[4] = {fv.x, fv.y, fv.z, fv.w};
                    #pragma unroll
                    for (int e = 0; e < 4; e++) {
                        const int d = dbase + i + e;
                        __nv_bfloat16 kh = __float2bfloat16_rn(kv[e]);
                        Ks[r * AT_STRIDE + d] = kh;
                        Ks[r * AT_STRIDE + 64 + d] =
                            __float2bfloat16_rn(kv[e] - __bfloat162float(kh));
                        __nv_bfloat16 vh = __float2bfloat16_rn(vv[e]);
                        Vs[d * AT_STRIDE + r] = vh;
                        Vs[d * AT_STRIDE + 64 + r] =
                            __float2bfloat16_rn(vv[e] - __bfloat162float(vh));
                    }
                }
            }
            __syncthreads();

            float s[8][4];
            #pragma unroll
            for (int j = 0; j < 8; j++)
                #pragma unroll
                for (int q = 0; q < 4; q++) s[j][q] = 0.f;

            #pragma unroll
            for (int phs = 0; phs < 3; phs++) {
                const int aoff = (phs == 1) ? 64 : 0;
                const int boff = (phs == 2) ? 64 : 0;
                #pragma unroll
                for (int ks = 0; ks < 4; ks++) {
                    uint32_t a[4];
                    const __nv_bfloat16* ap = Qs + row0 * AT_STRIDE + aoff + ks * 16 + c4 * 2;
                    a[0] = *reinterpret_cast<const uint32_t*>(ap);
                    a[1] = *reinterpret_cast<const uint32_t*>(ap + 8 * AT_STRIDE);
                    a[2] = *reinterpret_cast<const uint32_t*>(ap + 8);
                    a[3] = *reinterpret_cast<const uint32_t*>(ap + 8 * AT_STRIDE + 8);
                    #pragma unroll
                    for (int j = 0; j < 8; j++) {
                        uint32_t bf[2];
                        const __nv_bfloat16* bp =
                            Ks + (8 * j + g) * AT_STRIDE + boff + ks * 16 + c4 * 2;
                        bf[0] = *reinterpret_cast<const uint32_t*>(bp);
                        bf[1] = *reinterpret_cast<const uint32_t*>(bp + 8);
                        mma16(s[j], a, bf);
                    }
                }
            }

            if (kt == qt) {
                #pragma unroll
                for (int j = 0; j < 8; j++) {
                    const int colb = 8 * j + 2 * c4;
                    if (colb     > row0)     s[j][0] = -1e30f;
                    if (colb + 1 > row0)     s[j][1] = -1e30f;
                    if (colb     > row0 + 8) s[j][2] = -1e30f;
                    if (colb + 1 > row0 + 8) s[j][3] = -1e30f;
                }
            }

            float rm0 = -1e30f, rm1 = -1e30f;
            #pragma unroll
            for (int j = 0; j < 8; j++) {
                rm0 = fmaxf(rm0, fmaxf(s[j][0], s[j][1]));
                rm1 = fmaxf(rm1, fmaxf(s[j][2], s[j][3]));
            }
            rm0 = fmaxf(rm0, __shfl_xor_sync(0xFFFFFFFFu, rm0, 1));
            rm0 = fmaxf(rm0, __shfl_xor_sync(0xFFFFFFFFu, rm0, 2));
            rm1 = fmaxf(rm1, __shfl_xor_sync(0xFFFFFFFFu, rm1, 1));
            rm1 = fmaxf(rm1, __shfl_xor_sync(0xFFFFFFFFu, rm1, 2));
            const float mn0 = fmaxf(m0, rm0), mn1 = fmaxf(m1, rm1);
            const float cr0 = __expf(m0 - mn0), cr1 = __expf(m1 - mn1);
            m0 = mn0; m1 = mn1;

            float ps0 = 0.f, ps1 = 0.f;
            uint32_t phi[8][2], plo[8][2];
            #pragma unroll
            for (int j = 0; j < 8; j++) {
                float p0 = __expf(s[j][0] - mn0);
                float p1 = __expf(s[j][1] - mn0);
                float p2 = __expf(s[j][2] - mn1);
                float p3 = __expf(s[j][3] - mn1);
                ps0 += p0 + p1; ps1 += p2 + p3;
                __nv_bfloat16 h0 = __float2bfloat16_rn(p0), h1 = __float2bfloat16_rn(p1);
                __nv_bfloat16 h2 = __float2bfloat16_rn(p2), h3 = __float2bfloat16_rn(p3);
                phi[j][0] = pack_raw(h0, h1);
                phi[j][1] = pack_raw(h2, h3);
                plo[j][0] = pack_bf16x2(p0 - __bfloat162float(h0), p1 - __bfloat162float(h1));
                plo[j][1] = pack_bf16x2(p2 - __bfloat162float(h2), p3 - __bfloat162float(h3));
            }
            ps0 += __shfl_xor_sync(0xFFFFFFFFu, ps0, 1);
            ps0 += __shfl_xor_sync(0xFFFFFFFFu, ps0, 2);
            ps1 += __shfl_xor_sync(0xFFFFFFFFu, ps1, 1);
            ps1 += __shfl_xor_sync(0xFFFFFFFFu, ps1, 2);
            l0 = l0 * cr0 + ps0;
            l1 = l1 * cr1 + ps1;
            #pragma unroll
            for (int j = 0; j < 8; j++) {
                o[j][0] *= cr0; o[j][1] *= cr0;
                o[j][2] *= cr1; o[j][3] *= cr1;
            }

            #pragma unroll
            for (int phs = 0; phs < 3; phs++) {
                const int voff = (phs == 2) ? 64 : 0;
                #pragma unroll
                for (int ks = 0; ks < 4; ks++) {
                    uint32_t a[4];
                    if (phs == 1) {
                        a[0] = plo[2 * ks][0]; a[1] = plo[2 * ks][1];
                        a[2] = plo[2 * ks + 1][0]; a[3] = plo[2 * ks + 1][1];
                    } else {
                        a[0] = phi[2 * ks][0]; a[1] = phi[2 * ks][1];
                        a[2] = phi[2 * ks + 1][0]; a[3] = phi[2 * ks + 1][1];
                    }
                    #pragma unroll
                    for (int j = 0; j < 8; j++) {
                        uint32_t bf[2];
                        const __nv_bfloat16* bp =
                            Vs + (8 * j + g) * AT_STRIDE + voff + ks * 16 + c4 * 2;
                        bf[0] = *reinterpret_cast<const uint32_t*>(bp);
                        bf[1] = *reinterpret_cast<const uint32_t*>(bp + 8);
                        mma16(o[j], a, bf);
                    }
                }
            }
        }

        // epilogue: normalize + fp16 store
        const float inv0 = 1.f / l0, inv1 = 1.f / l1;
        const size_t r0 = (size_t)(b * S_ + qt * 64 + row0);
        __half* o0 = conc + r0 * H_;
        __half* o1 = conc + (r0 + 8) * H_;
        #pragma unroll
        for (int j = 0; j < 8; j++) {
            const int col = n * 64 + 8 * j + 2 * c4;
            *reinterpret_cast<__half2*>(o0 + col) =
                __floats2half2_rn(o[j][0] * inv0, o[j][1] * inv0);
            *reinterpret_cast<__half2*>(o1 + col) =
                __floats2half2_rn(o[j][2] * inv1, o[j][3] * inv1);
        }
    }
}

// ---------------------------------------------------------------------------
// Conversion / elementwise kernels
// ---------------------------------------------------------------------------
// fused gather -> fp16
__global__ void gather_h_kernel(const int* __restrict__ x,
                                const float* __restrict__ emb,
                                __half* __restrict__ outh)
{
    int idx = blockIdx.x * blockDim.x + threadIdx.x;
    if (idx >= M4 * E_) return;
    int i = idx / E_;
    int e = idx - i * E_;
    outh[idx] = __float2half_rn(emb[(size_t)x[i] * E_ + e]);
}

// transpose + round to fp16, optional scale
__global__ __launch_bounds__(256) void conv_wTh_kernel(
    const float* __restrict__ W, __half* __restrict__ out,
    int K, int N, float wscale)
{
    __shared__ float tile[32][33];
    const int tx = threadIdx.x & 31;
    const int ty = threadIdx.x >> 5;
    const int n0 = blockIdx.x * 32;
    const int k0 = blockIdx.y * 32;
    #pragma unroll
    for (int i = 0; i < 4; i++)
        tile[ty + i * 8][tx] = W[(size_t)(k0 + ty + i * 8) * N + n0 + tx];
    __syncthreads();
    #pragma unroll
    for (int i = 0; i < 4; i++) {
        const int nn = n0 + ty + i * 8;
        out[(size_t)nn * K + k0 + tx] =
            __float2half_rn(tile[tx][ty + i * 8] * wscale);
    }
}

// layer_in = pos + xemb  -> fp32 out + fp16 outh
__global__ void addpos_kernel(const float* __restrict__ xemb,
                              const float* __restrict__ pos11,
                              float* __restrict__ out,
                              __half* __restrict__ outh)
{
    int idx = blockIdx.x * blockDim.x + threadIdx.x;
    if (idx >= M4 * H_) return;
    int i = idx / H_;
    int h = idx - i * H_;
    int s = i & (S_ - 1);
    float y = xemb[idx] + pos11[(size_t)s * H_ + h];
    out[idx] = y;
    outh[idx] = __float2half_rn(y);
}

// LN + residual; fp32 out + fp16 outh
__global__ __launch_bounds__(256) void ln_res_kernel(
    const float* __restrict__ res, const float* __restrict__ x,
    const float* __restrict__ bias, const float* __restrict__ scale,
    float* __restrict__ out, __half* __restrict__ outh)
{
    __shared__ float red[256];
    const int row = blockIdx.x;
    const int t = threadIdx.x;
    const float* xr = x + (size_t)row * H_;

    float lsum = 0.f;
    for (int i = t; i < H_; i += 256) lsum += xr[i];
    red[t] = lsum; __syncthreads();
    for (int s = 128; s > 0; s >>= 1) { if (t < s) red[t] += red[t + s]; __syncthreads(); }
    const float mean = red[0] * (1.0f / H_);
    __syncthreads();

    float lvar = 0.f;
    for (int i = t; i < H_; i += 256) { float d = xr[i] - mean; lvar += d * d; }
    red[t] = lvar; __syncthreads();
    for (int s = 128; s > 0; s >>= 1) { if (t < s) red[t] += red[t + s]; __syncthreads(); }
    const float rstd = rsqrtf(red[0] * (1.0f / H_) + 1e-6f);

    for (int i = t; i < H_; i += 256) {
        float y = res[(size_t)row * H_ + i] + (xr[i] - mean) * rstd * scale[i] + bias[i];
        out[(size_t)row * H_ + i] = y;
        if (outh) outh[(size_t)row * H_ + i] = __float2half_rn(y);
    }
}

// ---------------------------------------------------------------------------
// Fused double-LN (steps 9+10):
//   y1 = xself + LN(ffw2)*s1 + b1
//   decout = fp16(xemb + LN(y1)*s2 + b2)
// ---------------------------------------------------------------------------
__global__ __launch_bounds__(256) void ln2_res_kernel(
    const float* __restrict__ xself, const float* __restrict__ ffw2,
    const float* __restrict__ b1, const float* __restrict__ s1,
    const float* __restrict__ xemb,
    const float* __restrict__ b2, const float* __restrict__ s2,
    __half* __restrict__ decout)
{
    __shared__ float red[256];
    __shared__ float y1[H_];
    const int row = blockIdx.x;
    const int t = threadIdx.x;
    const float* xr = ffw2 + (size_t)row * H_;

    float lsum = 0.f;
    for (int i = t; i < H_; i += 256) lsum += xr[i];
    red[t] = lsum; __syncthreads();
    for (int s = 128; s > 0; s >>= 1) { if (t < s) red[t] += red[t + s]; __syncthreads(); }
    const float mean = red[0] * (1.0f / H_);
    __syncthreads();

    float lvar = 0.f;
    for (int i = t; i < H_; i += 256) { float d = xr[i] - mean; lvar += d * d; }
    red[t] = lvar; __syncthreads();
    for (int s = 128; s > 0; s >>= 1) { if (t < s) red[t] += red[t + s]; __syncthreads(); }
    const float rstd = rsqrtf(red[0] * (1.0f / H_) + 1e-6f);
    __syncthreads();

    for (int i = t; i < H_; i += 256)
        y1[i] = xself[(size_t)row * H_ + i] + (xr[i] - mean) * rstd * s1[i] + b1[i];
    __syncthreads();

    float lsum2 = 0.f;
    for (int i = t; i < H_; i += 256) lsum2 += y1[i];
    red[t] = lsum2; __syncthreads();
    for (int s = 128; s > 0; s >>= 1) { if (t < s) red[t] += red[t + s]; __syncthreads(); }
    const float mean2 = red[0] * (1.0f / H_);
    __syncthreads();

    float lvar2 = 0.f;
    for (int i = t; i < H_; i += 256) { float d = y1[i] - mean2; lvar2 += d * d; }
    red[t] = lvar2; __syncthreads();
    for (int s = 128; s > 0; s >>= 1) { if (t < s) red[t] += red[t + s]; __syncthreads(); }
    const float rstd2 = rsqrtf(red[0] * (1.0f / H_) + 1e-6f);

    for (int i = t; i < H_; i += 256) {
        float y = xemb[(size_t)row * H_ + i] + (y1[i] - mean2) * rstd2 * s2[i] + b2[i];
        decout[(size_t)row * H_ + i] = __float2half_rn(y);
    }
}

// ---------------------------------------------------------------------------
// Launch helpers
// ---------------------------------------------------------------------------
static inline void run_gemm256h(const __half* A, const __half* Bm,
                                const float* bias, float* C, __half* outh,
                                int M, int N, int K, int relu)
{
    dim3 grid(M / 256, N / 256);
    gemm256h_kernel<<<grid, 256, G2_SMEM>>>(A, Bm, bias, C, outh, M, N, K, relu);
}
static inline void run_conv_wTh(const float* W, __half* out, int K, int N,
                                float wscale)
{
    dim3 grid(N / 32, K / 32);
    conv_wTh_kernel<<<grid, 256>>>(W, out, K, N, wscale);
}

extern "C" void kernel_launch(void* const* d_in, const int* in_sizes, int n_in,
                              void* d_out, int out_size)
{
    const int*   x            = (const int*)  d_in[0];
    const float* emb_decode   = (const float*)d_in[1];
    const float* W_dec_lin    = (const float*)d_in[2];
    const float* p_decoder    = (const float*)d_in[3];
    const float* x_emb_pos    = (const float*)d_in[4];
    const float* p_d_q        = (const float*)d_in[5];
    const float* p_d_k        = (const float*)d_in[6];
    const float* p_d_v        = (const float*)d_in[7];
    const float* p_d_c        = (const float*)d_in[8];
    const float* p_d_ff1      = (const float*)d_in[9];
    const float* p_d_ff2      = (const float*)d_in[10];
    const float* b_d_ff1      = (const float*)d_in[11];
    const float* b_d_ff2      = (const float*)d_in[12];
    const float* d_o_bias     = (const float*)d_in[13];
    const float* d_o_scale    = (const float*)d_in[14];
    const float* b_d_bias_1   = (const float*)d_in[15];
    const float* b_d_bias_2   = (const float*)d_in[16];
    const float* b_d_scale_1  = (const float*)d_in[17];
    const float* b_d_scale_2  = (const float*)d_in[18];
    float* out = (float*)d_out;

    const int m = L_ - 1;   // only the last layer's result is observable

    cudaFuncSetAttribute(gemm256h_kernel,
                         cudaFuncAttributeMaxDynamicSharedMemorySize, G2_SMEM);
    cudaFuncSetAttribute(attn_mma_kernel,
                         cudaFuncAttributeMaxDynamicSharedMemorySize, ATT_SMEM);

    float *xemb, *layerin, *qkv, *xmulti, *xself, *ffw2;
    __half *decout, *ah_emb, *ah_li, *ah_conc, *ah_self, *ah_ffw1;
    __half *wh_dec, *wh_qkv, *wh_c, *wh_ff1, *wh_ff2, *wth;
    cudaGetSymbolAddress((void**)&xemb,    g_xemb);
    cudaGetSymbolAddress((void**)&layerin, g_layerin);
    cudaGetSymbolAddress((void**)&qkv,     g_qkv);
    cudaGetSymbolAddress((void**)&xmulti,  g_xmulti);
    cudaGetSymbolAddress((void**)&xself,   g_xself);
    cudaGetSymbolAddress((void**)&ffw2,    g_ffw2);
    cudaGetSymbolAddress((void**)&decout,  g_decout);
    cudaGetSymbolAddress((void**)&ah_emb,  g_ah_emb);
    cudaGetSymbolAddress((void**)&ah_li,   g_ah_li);
    cudaGetSymbolAddress((void**)&ah_conc, g_ah_conc);
    cudaGetSymbolAddress((void**)&ah_self, g_ah_self);
    cudaGetSymbolAddress((void**)&ah_ffw1, g_ah_ffw1);
    cudaGetSymbolAddress((void**)&wh_dec,  g_wh_dec);
    cudaGetSymbolAddress((void**)&wh_qkv,  g_wh_qkv);
    cudaGetSymbolAddress((void**)&wh_c,    g_wh_c);
    cudaGetSymbolAddress((void**)&wh_ff1,  g_wh_ff1);
    cudaGetSymbolAddress((void**)&wh_ff2,  g_wh_ff2);
    cudaGetSymbolAddress((void**)&wth,     g_wth);

    // weight conversions -> fp16 [N,K]; Q weights pre-scaled by 1/sqrt(head)
    run_conv_wTh(W_dec_lin, wh_dec, E_, H_, 1.f);
    run_conv_wTh(p_d_q + (size_t)m * H_ * H_, wh_qkv, H_, H_, 0.125f);
    run_conv_wTh(p_d_k + (size_t)m * H_ * H_, wh_qkv + (size_t)1024 * H_, H_, H_, 1.f);
    run_conv_wTh(p_d_v + (size_t)m * H_ * H_, wh_qkv + (size_t)2048 * H_, H_, H_, 1.f);
    run_conv_wTh(p_d_c + (size_t)m * H_ * H_, wh_c, H_, H_, 1.f);
    run_conv_wTh(p_d_ff1 + (size_t)m * H_ * FF_, wh_ff1, H_, FF_, 1.f);
    run_conv_wTh(p_d_ff2 + (size_t)m * FF_ * H_, wh_ff2, FF_, H_, 1.f);
    run_conv_wTh(p_decoder, wth, H_, V_, 1.f);

    // 1. gather embeddings -> fp16
    gather_h_kernel<<<(M4 * E_ + 255) / 256, 256>>>(x, emb_decode, ah_emb);

    // 2. x_dec_embed = A_emb @ W_dec_lin  (fp16 tcgen05, K=128)
    run_gemm256h(ah_emb, wh_dec, nullptr, xemb, nullptr, M4, H_, E_, 0);

    // 3. layer_in = pos[11] + x_dec_embed  -> fp32 + fp16
    addpos_kernel<<<(M4 * H_ + 255) / 256, 256>>>(
        xemb, x_emb_pos + (size_t)m * S_ * H_, layerin, ah_li);

    // 4. fused Q/K/V projection (fp16 tcgen05, N=3072)
    run_gemm256h(ah_li, wh_qkv, nullptr, qkv, nullptr, M4, QKVS, H_, 0);

    // 5. load-balanced tensor-core causal attention -> fp16 conc
    attn_mma_kernel<<<dim3(S_ / 128, B_ * NH_), 128, ATT_SMEM>>>(
        qkv, qkv + 1024, qkv + 2048, ah_conc);

    // 6. x_multi = conc @ p_d_c  (fp16 tcgen05)
    run_gemm256h(ah_conc, wh_c, nullptr, xmulti, nullptr, M4, H_, H_, 0);

    // 7. x_self = layer_in + LN(x_multi)  -> fp32 xself + fp16 ah_self
    ln_res_kernel<<<M4, 256>>>(layerin, xmulti,
                               b_d_bias_1 + (size_t)m * H_,
                               b_d_scale_1 + (size_t)m * H_, xself, ah_self);

    // 8. FFN — both legs fp16 tcgen05
    run_gemm256h(ah_self, wh_ff1, b_d_ff1 + (size_t)m * FF_,
                 nullptr, ah_ffw1, M4, FF_, H_, 1);
    run_gemm256h(ah_ffw1, wh_ff2, b_d_ff2 + (size_t)m * H_,
                 ffw2, nullptr, M4, H_, FF_, 0);

    // 9+10. fused double-LN -> fp16 decout
    ln2_res_kernel<<<M4, 256>>>(xself, ffw2,
                                b_d_bias_2 + (size_t)m * H_,
                                b_d_scale_2 + (size_t)m * H_,
                                xemb, d_o_bias, d_o_scale, decout);

    // 11. logits = dec_outputs @ p_decoder  (fp16 tcgen05)
    run_gemm256h(decout, wth, nullptr, out, nullptr, M4, V_, H_, 0);
}